// round 8
// baseline (speedup 1.0000x reference)
#include <cuda_runtime.h>
#include <cuda_bf16.h>
#include <cstdint>
#include <math.h>

// ---------------------------------------------------------------------------
// Problem constants
// ---------------------------------------------------------------------------
#define BF      32
#define TOK     256
#define DIMC    1280
#define HEADS   8
#define DH      160
#define CROSS   768
#define ESEQ    77
#define FRAMES  16
#define NROWS   (BF*TOK)          // 8192
#define ENCROWS (BF*ESEQ)         // 2464
#define FF_N    (2*4*DIMC)        // 10240
#define FF_I    (4*DIMC)          // 5120

// ---------------------------------------------------------------------------
// Scratch (device globals; no allocation allowed)
// ---------------------------------------------------------------------------
__device__ float g_nh [NROWS*DIMC];
__device__ float g_q  [NROWS*DIMC];
__device__ float g_k  [NROWS*DIMC];
__device__ float g_v  [NROWS*DIMC];
__device__ float g_ao [NROWS*DIMC];
__device__ float g_ht [NROWS*DIMC];
__device__ float g_ff1[(size_t)NROWS*FF_N];
__device__ float g_gg [(size_t)NROWS*FF_I];
__device__ float g_enck[ENCROWS*DIMC];
__device__ float g_encv[ENCROWS*DIMC];
__device__ float g_encr[ENCROWS*CROSS];
__device__ float g_wt [38010880];   // tf32-rounded weights, original [K,N] layout

// rounded-weight offsets (floats)
#define OFF_A1WQ 0u
#define OFF_A1WK 1638400u
#define OFF_A1WV 3276800u
#define OFF_A1WO 4915200u
#define OFF_A2WQ 6553600u
#define OFF_A2WK 8192000u
#define OFF_A2WV 9175040u
#define OFF_A2WO 10158080u
#define OFF_FFW1 11796480u
#define OFF_FFW2 24903680u
#define OFF_ATWQ 31457280u
#define OFF_ATWK 33095680u
#define OFF_ATWV 34734080u
#define OFF_ATWO 36372480u

// ---------------------------------------------------------------------------
// Helpers
// ---------------------------------------------------------------------------
__device__ __forceinline__ uint32_t f2tf(float f) {
    uint32_t u;
    asm("cvt.rna.tf32.f32 %0, %1;" : "=r"(u) : "f"(f));
    return u;
}
__device__ __forceinline__ float tf32r(float f) { return __uint_as_float(f2tf(f)); }

__device__ __forceinline__ uint32_t smem_u32(const void* p) {
    uint32_t a;
    asm("{ .reg .u64 t; cvta.to.shared.u64 t, %1; cvt.u32.u64 %0, t; }" : "=r"(a) : "l"(p));
    return a;
}

#define CPASYNC16(dst, src, sz) \
    asm volatile("cp.async.cg.shared.global [%0], [%1], 16, %2;" \
        :: "r"((uint32_t)(dst)), "l"(src), "r"((uint32_t)(sz)) : "memory")
#define CP_COMMIT() asm volatile("cp.async.commit_group;" ::: "memory")
#define CP_WAIT(n)  asm volatile("cp.async.wait_group %0;" :: "n"(n) : "memory")

// ---------------------------------------------------------------------------
// tf32 GEMM v2: C[M,N] = A[M,K] @ B[K,N] (+bias[N]) (+res[M,N])
// CTA tile 256x128, 8 warps (4m x 2n), warp tile 64x64, m16n8k8 tf32 mma.
// 3-stage cp.async pipeline; operands must be pre-rounded to tf32 (RNA).
// Requirements: K % 16 == 0, N % 128 == 0; M ragged OK.
// ---------------------------------------------------------------------------
#define STAGES        3
#define A_STG_FLOATS  (256*20)     // 5120 floats (pad 16->20: bank-free frags)
#define B_STG_FLOATS  (16*136)     // 2176 floats (pad 128->136)
#define A_STG_BYTES   (A_STG_FLOATS*4)   // 20480
#define B_STG_BYTES   (B_STG_FLOATS*4)   // 8704
#define GEMM_SMEM     (STAGES*(A_STG_BYTES+B_STG_BYTES))  // 87552

__global__ void __launch_bounds__(256, 1)
gemm_tf32v2(const float* __restrict__ A, const float* __restrict__ B,
            float* __restrict__ C, const float* __restrict__ bias,
            const float* __restrict__ res, int M, int N, int K)
{
    extern __shared__ __align__(16) char smem[];
    uint32_t sbase = smem_u32(smem);
    uint32_t aBase = sbase;
    uint32_t bBase = sbase + STAGES * A_STG_BYTES;
    const uint32_t* asu = (const uint32_t*)smem;
    const uint32_t* bsu = (const uint32_t*)(smem + STAGES * A_STG_BYTES);

    int tid  = threadIdx.x;
    int warp = tid >> 5, lane = tid & 31;
    int wm = warp & 3, wn = warp >> 2;
    int g  = lane >> 2, t4 = lane & 3;

    // tile raster (GM groups along M for L2 reuse of B strips)
    int num_m = (M + 255) >> 8, num_n = N >> 7;
    const int GM = 8;
    int npg = GM * num_n;
    int group = blockIdx.x / npg;
    int first = group * GM;
    int gsz = min(num_m - first, GM);
    int rem = blockIdx.x - group * npg;
    int m0 = (first + rem % gsz) << 8;
    int n0 = (rem / gsz) << 7;

    // gmem load mapping
    //   A: thread tid -> row tid (4x16B chunks, one full 64B k-row)
    //   B: thread -> row tid>>4, cols (tid&15)*8 .. +7 (2x16B chunks)
    bool aval = (m0 + tid) < M;
    const float* aptr = A + (size_t)(m0 + tid) * K;
    const float* bptr = B + (size_t)(tid >> 4) * N + n0 + (tid & 15) * 8;
    uint32_t aDst = aBase + tid * 80;                       // tid*20 floats
    uint32_t bDst = bBase + (tid >> 4) * 544 + (tid & 15) * 32;

    float acc[4][8][4];
#pragma unroll
    for (int mi = 0; mi < 4; mi++)
#pragma unroll
        for (int ni = 0; ni < 8; ni++)
#pragma unroll
            for (int i = 0; i < 4; i++) acc[mi][ni][i] = 0.f;

    int KT = K >> 4;

#define LOAD_STAGE(kt, s)                                                     \
    do {                                                                      \
        const float* _a = aptr + (kt) * 16;                                   \
        uint32_t _ad = aDst + (s) * A_STG_BYTES;                              \
        unsigned _sz = aval ? 16u : 0u;                                       \
        CPASYNC16(_ad,      _a,      _sz);                                    \
        CPASYNC16(_ad + 16, _a + 4,  _sz);                                    \
        CPASYNC16(_ad + 32, _a + 8,  _sz);                                    \
        CPASYNC16(_ad + 48, _a + 12, _sz);                                    \
        const float* _b = bptr + (size_t)(kt) * 16 * N;                       \
        uint32_t _bd = bDst + (s) * B_STG_BYTES;                              \
        CPASYNC16(_bd,      _b,     16u);                                     \
        CPASYNC16(_bd + 16, _b + 4, 16u);                                     \
    } while (0)

#pragma unroll
    for (int s = 0; s < STAGES - 1; s++) {
        if (s < KT) LOAD_STAGE(s, s);
        CP_COMMIT();
    }

    for (int kt = 0; kt < KT; kt++) {
        CP_WAIT(STAGES - 2);
        __syncthreads();

        int nk = kt + STAGES - 1;
        if (nk < KT) LOAD_STAGE(nk, nk % STAGES);
        CP_COMMIT();

        const uint32_t* as = asu + (kt % STAGES) * A_STG_FLOATS;
        const uint32_t* bs = bsu + (kt % STAGES) * B_STG_FLOATS;

#pragma unroll
        for (int ks = 0; ks < 2; ks++) {
            int kk = ks * 8;
            uint32_t af[4][4];
#pragma unroll
            for (int mi = 0; mi < 4; mi++) {
                const uint32_t* ar = as + (wm*64 + mi*16 + g) * 20 + kk + t4;
                af[mi][0] = ar[0];
                af[mi][1] = ar[8*20];
                af[mi][2] = ar[4];
                af[mi][3] = ar[8*20 + 4];
            }
#pragma unroll
            for (int ni = 0; ni < 8; ni++) {
                int c = wn*64 + ni*8 + g;
                uint32_t b0 = bs[(kk + t4)     * 136 + c];
                uint32_t b1 = bs[(kk + t4 + 4) * 136 + c];
#pragma unroll
                for (int mi = 0; mi < 4; mi++)
                    asm volatile(
                        "mma.sync.aligned.m16n8k8.row.col.f32.tf32.tf32.f32 "
                        "{%0,%1,%2,%3}, {%4,%5,%6,%7}, {%8,%9}, {%0,%1,%2,%3};"
                        : "+f"(acc[mi][ni][0]), "+f"(acc[mi][ni][1]),
                          "+f"(acc[mi][ni][2]), "+f"(acc[mi][ni][3])
                        : "r"(af[mi][0]), "r"(af[mi][1]),
                          "r"(af[mi][2]), "r"(af[mi][3]),
                          "r"(b0), "r"(b1));
            }
        }
    }
#undef LOAD_STAGE

    // epilogue: + bias + residual, float2 stores
#pragma unroll
    for (int mi = 0; mi < 4; mi++) {
#pragma unroll
        for (int ni = 0; ni < 8; ni++) {
            int row = m0 + wm*64 + mi*16 + g;
            int col = n0 + wn*64 + ni*8 + t4*2;
            float2 bv = bias ? *(const float2*)(bias + col)
                             : make_float2(0.f, 0.f);
            if (row < M) {
                size_t idx = (size_t)row * N + col;
                float2 rv = res ? *(const float2*)(res + idx)
                                : make_float2(0.f, 0.f);
                float2 o;
                o.x = acc[mi][ni][0] + bv.x + rv.x;
                o.y = acc[mi][ni][1] + bv.y + rv.y;
                *(float2*)(C + idx) = o;
            }
            if (row + 8 < M) {
                size_t idx = (size_t)(row + 8) * N + col;
                float2 rv = res ? *(const float2*)(res + idx)
                                : make_float2(0.f, 0.f);
                float2 o;
                o.x = acc[mi][ni][2] + bv.x + rv.x;
                o.y = acc[mi][ni][3] + bv.y + rv.y;
                *(float2*)(C + idx) = o;
            }
        }
    }
}

// ---------------------------------------------------------------------------
// tf32 RNA rounding copy (weights + enc; keeps [K,N] layout)
// ---------------------------------------------------------------------------
__global__ void round_copy(const float* __restrict__ in, float* __restrict__ out, int n)
{
    int i = blockIdx.x * 256 + threadIdx.x;
    if (i < n) out[i] = tf32r(in[i]);
}

// ---------------------------------------------------------------------------
// LayerNorm (output RNA-rounded to tf32 — it only feeds GEMM A operands)
// ---------------------------------------------------------------------------
__global__ __launch_bounds__(128)
void ln_kernel(const float* __restrict__ x, const float* __restrict__ w,
               const float* __restrict__ b, float* __restrict__ y)
{
    int row = blockIdx.x;
    const float* xr = x + (size_t)row * DIMC;
    float*       yr = y + (size_t)row * DIMC;
    int tid = threadIdx.x;

    float v[10];
    float s = 0.f, ss = 0.f;
#pragma unroll
    for (int i = 0; i < 10; i++) {
        float t = xr[tid + i*128];
        v[i] = t; s += t; ss += t*t;
    }
#pragma unroll
    for (int off = 16; off; off >>= 1) {
        s  += __shfl_xor_sync(0xffffffffu, s,  off);
        ss += __shfl_xor_sync(0xffffffffu, ss, off);
    }
    __shared__ float sh[8];
    int warp = tid >> 5;
    if ((tid & 31) == 0) { sh[warp] = s; sh[4+warp] = ss; }
    __syncthreads();
    s  = sh[0] + sh[1] + sh[2] + sh[3];
    ss = sh[4] + sh[5] + sh[6] + sh[7];
    float mean = s * (1.f/1280.f);
    float var  = ss * (1.f/1280.f) - mean*mean;
    float rstd = rsqrtf(var + 1e-5f);
#pragma unroll
    for (int i = 0; i < 10; i++) {
        int c = tid + i*128;
        yr[c] = tf32r((v[i] - mean) * rstd * w[c] + b[c]);
    }
}

// ---------------------------------------------------------------------------
// Fused attention (fp32, online softmax). Output RNA-rounded (feeds GEMM A).
// ---------------------------------------------------------------------------
__global__ __launch_bounds__(256)
void attn_kernel(const float* __restrict__ Q, const float* __restrict__ K,
                 const float* __restrict__ V, float* __restrict__ O,
                 int Sq, int Sk, long kv_bstride, long q_bstride,
                 int sparse, float scale)
{
    __shared__ float Ks[32][160];
    __shared__ float Vs[32][160];

    int batch = blockIdx.z, head = blockIdx.y;
    int q0  = blockIdx.x * 64;
    int tid = threadIdx.x;
    int r   = tid >> 2, c4 = tid & 3;
    int d0  = c4 * 40;
    bool rowvalid = (q0 + r) < Sq;

    float qv[40];
    {
        int rr = rowvalid ? r : 0;
        const float* qp = Q + (size_t)batch * q_bstride
                            + (size_t)(q0 + rr) * DIMC + head * DH + d0;
#pragma unroll
        for (int i = 0; i < 40; i++) qv[i] = rowvalid ? qp[i] : 0.f;
    }

    float o[40];
#pragma unroll
    for (int i = 0; i < 40; i++) o[i] = 0.f;
    float m = -1e30f, l = 0.f;

    int lr = tid >> 3;
    int lc = (tid & 7) * 20;

    int ntiles = (Sk + 31) >> 5;
    for (int kt = 0; kt < ntiles; kt++) {
        int j = kt * 32 + lr;
        {
            const float* kp = nullptr;
            const float* vp = nullptr;
            if (j < Sk) {
                size_t off;
                if (sparse) {
                    int bb = batch >> 4, f = batch & 15;
                    int srcf = (j < 256) ? 0 : ((f > 0) ? (f - 1) : 0);
                    int jr2  = (j < 256) ? j : (j - 256);
                    off = ((size_t)(bb*16 + srcf) * 256 + jr2) * DIMC
                        + head * DH + lc;
                } else {
                    off = (size_t)batch * kv_bstride + (size_t)j * DIMC
                        + head * DH + lc;
                }
                kp = K + off; vp = V + off;
            }
#pragma unroll
            for (int i = 0; i < 5; i++) {
                float4 kx = kp ? *(const float4*)(kp + i*4)
                               : make_float4(0,0,0,0);
                float4 vx = vp ? *(const float4*)(vp + i*4)
                               : make_float4(0,0,0,0);
                *(float4*)&Ks[lr][lc + i*4] = kx;
                *(float4*)&Vs[lr][lc + i*4] = vx;
            }
        }
        __syncthreads();

#pragma unroll
        for (int jc = 0; jc < 2; jc++) {
            int jb = jc * 16;
            if (kt*32 + jb < Sk) {
                float p[16];
#pragma unroll
                for (int jj = 0; jj < 16; jj++) {
                    const float4* kr = (const float4*)&Ks[jb + jj][d0];
                    float s0 = 0.f, s1 = 0.f, s2 = 0.f, s3 = 0.f;
#pragma unroll
                    for (int i = 0; i < 10; i++) {
                        float4 k4 = kr[i];
                        s0 += qv[i*4+0]*k4.x; s1 += qv[i*4+1]*k4.y;
                        s2 += qv[i*4+2]*k4.z; s3 += qv[i*4+3]*k4.w;
                    }
                    p[jj] = (s0 + s1) + (s2 + s3);
                }
#pragma unroll
                for (int jj = 0; jj < 16; jj++) {
                    p[jj] += __shfl_xor_sync(0xffffffffu, p[jj], 1);
                    p[jj] += __shfl_xor_sync(0xffffffffu, p[jj], 2);
                    int jg = kt*32 + jb + jj;
                    p[jj] = (jg < Sk) ? p[jj] * scale : -1e30f;
                }
                float mt = m;
#pragma unroll
                for (int jj = 0; jj < 16; jj++) mt = fmaxf(mt, p[jj]);
                if (mt > m) {
                    float sc = __expf(m - mt);
                    l *= sc;
#pragma unroll
                    for (int i = 0; i < 40; i++) o[i] *= sc;
                    m = mt;
                }
#pragma unroll
                for (int jj = 0; jj < 16; jj++) {
                    float e = __expf(p[jj] - m);
                    l += e;
                    const float4* vr = (const float4*)&Vs[jb + jj][d0];
#pragma unroll
                    for (int i = 0; i < 10; i++) {
                        float4 v4 = vr[i];
                        o[i*4+0] += e * v4.x; o[i*4+1] += e * v4.y;
                        o[i*4+2] += e * v4.z; o[i*4+3] += e * v4.w;
                    }
                }
            }
        }
        __syncthreads();
    }

    if (rowvalid) {
        float inv = 1.f / l;
        float* op = O + (size_t)batch * q_bstride
                      + (size_t)(q0 + r) * DIMC + head * DH + d0;
#pragma unroll
        for (int i = 0; i < 40; i++) op[i] = tf32r(o[i] * inv);
    }
}

// ---------------------------------------------------------------------------
// GEGLU (output RNA-rounded — feeds ffw2 GEMM A)
// ---------------------------------------------------------------------------
__global__ void geglu_kernel(const float* __restrict__ in, float* __restrict__ out)
{
    size_t idx = (size_t)blockIdx.x * blockDim.x + threadIdx.x;
    if (idx >= (size_t)NROWS * FF_I) return;
    size_t rr = idx / FF_I;
    int    i  = (int)(idx - rr * FF_I);
    const float* row = in + rr * FF_N;
    float p = row[i];
    float g = row[FF_I + i];
    float gel = 0.5f * g * (1.f + erff(g * 0.70710678118654752f));
    out[idx] = tf32r(p * gel);
}

// ---------------------------------------------------------------------------
// Temporal reshape transposes
// ---------------------------------------------------------------------------
__global__ void transpose_fwd(const float* __restrict__ in, float* __restrict__ out)
{
    size_t idx = (size_t)blockIdx.x * blockDim.x + threadIdx.x;
    if (idx >= (size_t)NROWS * DIMC) return;
    int c   = (int)(idx % DIMC);
    int row = (int)(idx / DIMC);
    int f   = row & 15;
    int tok = (row >> 4) & 255;
    int b   = row >> 12;
    out[idx] = in[((size_t)((b*16 + f)*256 + tok)) * DIMC + c];
}

__global__ void transpose_bwd(const float* __restrict__ in, float* __restrict__ out)
{
    size_t idx = (size_t)blockIdx.x * blockDim.x + threadIdx.x;
    if (idx >= (size_t)NROWS * DIMC) return;
    int c   = (int)(idx % DIMC);
    int row = (int)(idx / DIMC);
    int tok = row & 255;
    int f   = (row >> 8) & 15;
    int b   = row >> 12;
    out[idx] = in[((size_t)((b*256 + tok)*16 + f)) * DIMC + c];
}

// ---------------------------------------------------------------------------
// Host launcher
// ---------------------------------------------------------------------------
static void launch_gemm(const float* A, const float* B, float* C,
                        const float* bias, const float* res,
                        int M, int N, int K)
{
    static bool attr_set = false;
    if (!attr_set) {
        cudaFuncSetAttribute(gemm_tf32v2,
            cudaFuncAttributeMaxDynamicSharedMemorySize, GEMM_SMEM);
        attr_set = true;
    }
    int nm = (M + 255) / 256, nn = N / 128;
    gemm_tf32v2<<<nm * nn, 256, GEMM_SMEM>>>(A, B, C, bias, res, M, N, K);
}

static void launch_round(const float* in, float* out, int n)
{
    round_copy<<<(n + 255) / 256, 256>>>(in, out, n);
}

extern "C" void kernel_launch(void* const* d_in, const int* in_sizes, int n_in,
                              void* d_out, int out_size)
{
    const float* hid  = (const float*)d_in[0];
    const float* enc  = (const float*)d_in[1];
    const float* n1w  = (const float*)d_in[2];
    const float* n1b  = (const float*)d_in[3];
    const float* a1wq = (const float*)d_in[4];
    const float* a1wk = (const float*)d_in[5];
    const float* a1wv = (const float*)d_in[6];
    const float* a1wo = (const float*)d_in[7];
    const float* a1bo = (const float*)d_in[8];
    const float* n2w  = (const float*)d_in[9];
    const float* n2b  = (const float*)d_in[10];
    const float* a2wq = (const float*)d_in[11];
    const float* a2wk = (const float*)d_in[12];
    const float* a2wv = (const float*)d_in[13];
    const float* a2wo = (const float*)d_in[14];
    const float* a2bo = (const float*)d_in[15];
    const float* n3w  = (const float*)d_in[16];
    const float* n3b  = (const float*)d_in[17];
    const float* ffw1 = (const float*)d_in[18];
    const float* ffb1 = (const float*)d_in[19];
    const float* ffw2 = (const float*)d_in[20];
    const float* ffb2 = (const float*)d_in[21];
    const float* ntw  = (const float*)d_in[22];
    const float* ntb  = (const float*)d_in[23];
    const float* atwq = (const float*)d_in[24];
    const float* atwk = (const float*)d_in[25];
    const float* atwv = (const float*)d_in[26];
    const float* atwo = (const float*)d_in[27];
    const float* atbo = (const float*)d_in[28];

    float* out = (float*)d_out;

    float *nh, *q, *k, *v, *ao, *ht, *ff1, *gg, *enck, *encv, *encr, *wt;
    cudaGetSymbolAddress((void**)&nh,  g_nh);
    cudaGetSymbolAddress((void**)&q,   g_q);
    cudaGetSymbolAddress((void**)&k,   g_k);
    cudaGetSymbolAddress((void**)&v,   g_v);
    cudaGetSymbolAddress((void**)&ao,  g_ao);
    cudaGetSymbolAddress((void**)&ht,  g_ht);
    cudaGetSymbolAddress((void**)&ff1, g_ff1);
    cudaGetSymbolAddress((void**)&gg,  g_gg);
    cudaGetSymbolAddress((void**)&enck,g_enck);
    cudaGetSymbolAddress((void**)&encv,g_encv);
    cudaGetSymbolAddress((void**)&encr,g_encr);
    cudaGetSymbolAddress((void**)&wt,  g_wt);

    const float scale = 0.07905694150420949f;   // 160^-0.5
    const long QBS = (long)TOK * DIMC;

    // ---- one-time RNA tf32 rounding of B operands (weights + enc) ----
    launch_round(a1wq, wt + OFF_A1WQ, DIMC*DIMC);
    launch_round(a1wk, wt + OFF_A1WK, DIMC*DIMC);
    launch_round(a1wv, wt + OFF_A1WV, DIMC*DIMC);
    launch_round(a1wo, wt + OFF_A1WO, DIMC*DIMC);
    launch_round(a2wq, wt + OFF_A2WQ, DIMC*DIMC);
    launch_round(a2wk, wt + OFF_A2WK, CROSS*DIMC);
    launch_round(a2wv, wt + OFF_A2WV, CROSS*DIMC);
    launch_round(a2wo, wt + OFF_A2WO, DIMC*DIMC);
    launch_round(ffw1, wt + OFF_FFW1, DIMC*FF_N);
    launch_round(ffw2, wt + OFF_FFW2, FF_I*DIMC);
    launch_round(atwq, wt + OFF_ATWQ, DIMC*DIMC);
    launch_round(atwk, wt + OFF_ATWK, DIMC*DIMC);
    launch_round(atwv, wt + OFF_ATWV, DIMC*DIMC);
    launch_round(atwo, wt + OFF_ATWO, DIMC*DIMC);
    launch_round(enc,  encr,          ENCROWS*CROSS);

    // ---- attn1: sparse-causal self-attention ----
    ln_kernel<<<NROWS, 128>>>(hid, n1w, n1b, nh);
    launch_gemm(nh, wt + OFF_A1WQ, q, nullptr, nullptr, NROWS, DIMC, DIMC);
    launch_gemm(nh, wt + OFF_A1WK, k, nullptr, nullptr, NROWS, DIMC, DIMC);
    launch_gemm(nh, wt + OFF_A1WV, v, nullptr, nullptr, NROWS, DIMC, DIMC);
    attn_kernel<<<dim3(4, HEADS, BF), 256>>>(q, k, v, ao,
        TOK, 2*TOK, QBS, QBS, 1, scale);
    launch_gemm(ao, wt + OFF_A1WO, out, a1bo, hid, NROWS, DIMC, DIMC);

    // ---- attn2: cross-attention ----
    ln_kernel<<<NROWS, 128>>>(out, n2w, n2b, nh);
    launch_gemm(nh,   wt + OFF_A2WQ, q,    nullptr, nullptr, NROWS,   DIMC, DIMC);
    launch_gemm(encr, wt + OFF_A2WK, enck, nullptr, nullptr, ENCROWS, DIMC, CROSS);
    launch_gemm(encr, wt + OFF_A2WV, encv, nullptr, nullptr, ENCROWS, DIMC, CROSS);
    attn_kernel<<<dim3(4, HEADS, BF), 256>>>(q, enck, encv, ao,
        TOK, ESEQ, (long)ESEQ * DIMC, QBS, 0, scale);
    launch_gemm(ao, wt + OFF_A2WO, out, a2bo, out, NROWS, DIMC, DIMC);

    // ---- geglu FFN ----
    ln_kernel<<<NROWS, 128>>>(out, n3w, n3b, nh);
    launch_gemm(nh, wt + OFF_FFW1, ff1, ffb1, nullptr, NROWS, FF_N, DIMC);
    {
        size_t tot = (size_t)NROWS * FF_I;
        geglu_kernel<<<(unsigned)((tot + 255) / 256), 256>>>(ff1, gg);
    }
    launch_gemm(gg, wt + OFF_FFW2, out, ffb2, out, NROWS, DIMC, FF_I);

    // ---- temporal self-attention ----
    {
        size_t tot = (size_t)NROWS * DIMC;
        transpose_fwd<<<(unsigned)((tot + 255) / 256), 256>>>(out, ht);
    }
    ln_kernel<<<NROWS, 128>>>(ht, ntw, ntb, nh);
    launch_gemm(nh, wt + OFF_ATWQ, q, nullptr, nullptr, NROWS, DIMC, DIMC);
    launch_gemm(nh, wt + OFF_ATWK, k, nullptr, nullptr, NROWS, DIMC, DIMC);
    launch_gemm(nh, wt + OFF_ATWV, v, nullptr, nullptr, NROWS, DIMC, DIMC);
    attn_kernel<<<dim3(1, HEADS, 2*TOK), 256>>>(q, k, v, ao,
        FRAMES, FRAMES, (long)FRAMES * DIMC, (long)FRAMES * DIMC, 0, scale);
    launch_gemm(ao, wt + OFF_ATWO, ht, atbo, ht, NROWS, DIMC, DIMC);
    {
        size_t tot = (size_t)NROWS * DIMC;
        transpose_bwd<<<(unsigned)((tot + 255) / 256), 256>>>(ht, out);
    }
}

// round 9
// speedup vs baseline: 1.1805x; 1.1805x over previous
#include <cuda_runtime.h>
#include <cuda_bf16.h>
#include <cstdint>
#include <math.h>

// ---------------------------------------------------------------------------
// Problem constants
// ---------------------------------------------------------------------------
#define BF      32
#define TOK     256
#define DIMC    1280
#define HEADS   8
#define DH      160
#define CROSS   768
#define ESEQ    77
#define FRAMES  16
#define NROWS   (BF*TOK)          // 8192
#define ENCROWS (BF*ESEQ)         // 2464
#define FF_N    (2*4*DIMC)        // 10240
#define FF_I    (4*DIMC)          // 5120

// ---------------------------------------------------------------------------
// Scratch (device globals; no allocation allowed)
// ---------------------------------------------------------------------------
__device__ float g_nh [NROWS*DIMC];
__device__ float g_q  [NROWS*DIMC];
__device__ float g_k  [NROWS*DIMC];
__device__ float g_v  [NROWS*DIMC];
__device__ float g_ao [NROWS*DIMC];
__device__ float g_ht [NROWS*DIMC];
__device__ float g_ff1[(size_t)NROWS*FF_N];
__device__ float g_gg [(size_t)NROWS*FF_I];
__device__ float g_enck[ENCROWS*DIMC];
__device__ float g_encv[ENCROWS*DIMC];
__device__ float g_encr[ENCROWS*CROSS];
__device__ float g_wt [38010880];   // tf32-rounded weights, original [K,N] layout

// rounded-weight offsets (floats)
#define OFF_A1WQ 0u
#define OFF_A1WK 1638400u
#define OFF_A1WV 3276800u
#define OFF_A1WO 4915200u
#define OFF_A2WQ 6553600u
#define OFF_A2WK 8192000u
#define OFF_A2WV 9175040u
#define OFF_A2WO 10158080u
#define OFF_FFW1 11796480u
#define OFF_FFW2 24903680u
#define OFF_ATWQ 31457280u
#define OFF_ATWK 33095680u
#define OFF_ATWV 34734080u
#define OFF_ATWO 36372480u

// ---------------------------------------------------------------------------
// Helpers
// ---------------------------------------------------------------------------
__device__ __forceinline__ uint32_t f2tf(float f) {
    uint32_t u;
    asm("cvt.rna.tf32.f32 %0, %1;" : "=r"(u) : "f"(f));
    return u;
}
__device__ __forceinline__ float tf32r(float f) { return __uint_as_float(f2tf(f)); }

__device__ __forceinline__ uint32_t smem_u32(const void* p) {
    uint32_t a;
    asm("{ .reg .u64 t; cvta.to.shared.u64 t, %1; cvt.u32.u64 %0, t; }" : "=r"(a) : "l"(p));
    return a;
}

#define CPASYNC16(dst, src, sz) \
    asm volatile("cp.async.cg.shared.global [%0], [%1], 16, %2;" \
        :: "r"((uint32_t)(dst)), "l"(src), "r"((uint32_t)(sz)) : "memory")
#define CP_COMMIT() asm volatile("cp.async.commit_group;" ::: "memory")
#define CP_WAIT(n)  asm volatile("cp.async.wait_group %0;" :: "n"(n) : "memory")

// ---------------------------------------------------------------------------
// tf32 GEMM v3: C[M,N] = A[M,K] @ B[K,N] (+bias[N]) (+res[M,N])
// CTA tile 128x128x16, 8 warps (4m x 2n), warp tile 32x64, m16n8k8 tf32 mma.
// 3-stage cp.async pipeline; 2 CTAs/SM. Operands pre-rounded to tf32 (RNA).
// Requirements: K % 16 == 0, N % 128 == 0; M ragged OK.
// ---------------------------------------------------------------------------
#define STAGES        3
#define A_STG_FLOATS  (128*20)           // pad 16->20: bank-free frag loads
#define B_STG_FLOATS  (16*136)           // pad 128->136
#define A_STG_BYTES   (A_STG_FLOATS*4)   // 10240
#define B_STG_BYTES   (B_STG_FLOATS*4)   // 8704
#define GEMM_SMEM     (STAGES*(A_STG_BYTES+B_STG_BYTES))  // 56832

__global__ void __launch_bounds__(256, 2)
gemm_tf32v3(const float* __restrict__ A, const float* __restrict__ B,
            float* __restrict__ C, const float* __restrict__ bias,
            const float* __restrict__ res, int M, int N, int K)
{
    extern __shared__ __align__(16) char smem[];
    uint32_t aBase = smem_u32(smem);
    uint32_t bBase = aBase + STAGES * A_STG_BYTES;
    const uint32_t* asu = (const uint32_t*)smem;
    const uint32_t* bsu = (const uint32_t*)(smem + STAGES * A_STG_BYTES);

    int tid  = threadIdx.x;
    int warp = tid >> 5, lane = tid & 31;
    int wm = warp & 3, wn = warp >> 2;
    int g  = lane >> 2, t4 = lane & 3;

    // tile raster (GM groups along M for L2 reuse of B strips)
    int num_m = (M + 127) >> 7, num_n = N >> 7;
    const int GM = 8;
    int npg = GM * num_n;
    int group = blockIdx.x / npg;
    int first = group * GM;
    int gsz = min(num_m - first, GM);
    int rem = blockIdx.x - group * npg;
    int m0 = (first + rem % gsz) << 7;
    int n0 = (rem / gsz) << 7;

    // gmem load mapping:
    //   A: thread -> row tid>>1, cols (tid&1)*8 (2 x 16B)
    //   B: thread -> row tid>>4, cols (tid&15)*8 (2 x 16B)
    int arow = tid >> 1, ac8 = (tid & 1) * 8;
    bool aval = (m0 + arow) < M;
    const float* aptr = A + (size_t)(m0 + arow) * K + ac8;
    const float* bptr = B + (size_t)(tid >> 4) * N + n0 + (tid & 15) * 8;
    uint32_t aDst = aBase + (arow * 20 + ac8) * 4;
    uint32_t bDst = bBase + ((tid >> 4) * 136 + (tid & 15) * 8) * 4;

    float acc[2][8][4];
#pragma unroll
    for (int mi = 0; mi < 2; mi++)
#pragma unroll
        for (int ni = 0; ni < 8; ni++)
#pragma unroll
            for (int i = 0; i < 4; i++) acc[mi][ni][i] = 0.f;

    int KT = K >> 4;

#define LOAD_STAGE(kt, s)                                                     \
    do {                                                                      \
        const float* _a = aptr + (kt) * 16;                                   \
        uint32_t _ad = aDst + (s) * A_STG_BYTES;                              \
        unsigned _sz = aval ? 16u : 0u;                                       \
        CPASYNC16(_ad,      _a,     _sz);                                     \
        CPASYNC16(_ad + 16, _a + 4, _sz);                                     \
        const float* _b = bptr + (size_t)(kt) * 16 * N;                       \
        uint32_t _bd = bDst + (s) * B_STG_BYTES;                              \
        CPASYNC16(_bd,      _b,     16u);                                     \
        CPASYNC16(_bd + 16, _b + 4, 16u);                                     \
    } while (0)

#pragma unroll
    for (int s = 0; s < STAGES - 1; s++) {
        if (s < KT) LOAD_STAGE(s, s);
        CP_COMMIT();
    }

    for (int kt = 0; kt < KT; kt++) {
        CP_WAIT(STAGES - 2);
        __syncthreads();

        int nk = kt + STAGES - 1;
        if (nk < KT) LOAD_STAGE(nk, nk % STAGES);
        CP_COMMIT();

        const uint32_t* as = asu + (kt % STAGES) * A_STG_FLOATS;
        const uint32_t* bs = bsu + (kt % STAGES) * B_STG_FLOATS;

#pragma unroll
        for (int ks = 0; ks < 2; ks++) {
            int kk = ks * 8;
            uint32_t af[2][4];
#pragma unroll
            for (int mi = 0; mi < 2; mi++) {
                const uint32_t* ar = as + (wm*32 + mi*16 + g) * 20 + kk + t4;
                af[mi][0] = ar[0];
                af[mi][1] = ar[8*20];
                af[mi][2] = ar[4];
                af[mi][3] = ar[8*20 + 4];
            }
#pragma unroll
            for (int ni = 0; ni < 8; ni++) {
                int c = wn*64 + ni*8 + g;
                uint32_t b0 = bs[(kk + t4)     * 136 + c];
                uint32_t b1 = bs[(kk + t4 + 4) * 136 + c];
#pragma unroll
                for (int mi = 0; mi < 2; mi++)
                    asm volatile(
                        "mma.sync.aligned.m16n8k8.row.col.f32.tf32.tf32.f32 "
                        "{%0,%1,%2,%3}, {%4,%5,%6,%7}, {%8,%9}, {%0,%1,%2,%3};"
                        : "+f"(acc[mi][ni][0]), "+f"(acc[mi][ni][1]),
                          "+f"(acc[mi][ni][2]), "+f"(acc[mi][ni][3])
                        : "r"(af[mi][0]), "r"(af[mi][1]),
                          "r"(af[mi][2]), "r"(af[mi][3]),
                          "r"(b0), "r"(b1));
            }
        }
    }
#undef LOAD_STAGE

    // epilogue: + bias + residual, float2 stores
#pragma unroll
    for (int mi = 0; mi < 2; mi++) {
#pragma unroll
        for (int ni = 0; ni < 8; ni++) {
            int row = m0 + wm*32 + mi*16 + g;
            int col = n0 + wn*64 + ni*8 + t4*2;
            float2 bv = bias ? *(const float2*)(bias + col)
                             : make_float2(0.f, 0.f);
            if (row < M) {
                size_t idx = (size_t)row * N + col;
                float2 rv = res ? *(const float2*)(res + idx)
                                : make_float2(0.f, 0.f);
                float2 o;
                o.x = acc[mi][ni][0] + bv.x + rv.x;
                o.y = acc[mi][ni][1] + bv.y + rv.y;
                *(float2*)(C + idx) = o;
            }
            if (row + 8 < M) {
                size_t idx = (size_t)(row + 8) * N + col;
                float2 rv = res ? *(const float2*)(res + idx)
                                : make_float2(0.f, 0.f);
                float2 o;
                o.x = acc[mi][ni][2] + bv.x + rv.x;
                o.y = acc[mi][ni][3] + bv.y + rv.y;
                *(float2*)(C + idx) = o;
            }
        }
    }
}

// ---------------------------------------------------------------------------
// tf32 RNA rounding copy (weights + enc; keeps [K,N] layout)
// ---------------------------------------------------------------------------
__global__ void round_copy(const float* __restrict__ in, float* __restrict__ out, int n)
{
    int i = (blockIdx.x * 256 + threadIdx.x) * 4;
    if (i < n) {
        float4 v = *(const float4*)(in + i);
        v.x = tf32r(v.x); v.y = tf32r(v.y); v.z = tf32r(v.z); v.w = tf32r(v.w);
        *(float4*)(out + i) = v;
    }
}

// ---------------------------------------------------------------------------
// LayerNorm (output RNA-rounded to tf32 — it only feeds GEMM A operands)
// ---------------------------------------------------------------------------
__global__ __launch_bounds__(128)
void ln_kernel(const float* __restrict__ x, const float* __restrict__ w,
               const float* __restrict__ b, float* __restrict__ y)
{
    int row = blockIdx.x;
    const float* xr = x + (size_t)row * DIMC;
    float*       yr = y + (size_t)row * DIMC;
    int tid = threadIdx.x;

    float v[10];
    float s = 0.f, ss = 0.f;
#pragma unroll
    for (int i = 0; i < 10; i++) {
        float t = xr[tid + i*128];
        v[i] = t; s += t; ss += t*t;
    }
#pragma unroll
    for (int off = 16; off; off >>= 1) {
        s  += __shfl_xor_sync(0xffffffffu, s,  off);
        ss += __shfl_xor_sync(0xffffffffu, ss, off);
    }
    __shared__ float sh[8];
    int warp = tid >> 5;
    if ((tid & 31) == 0) { sh[warp] = s; sh[4+warp] = ss; }
    __syncthreads();
    s  = sh[0] + sh[1] + sh[2] + sh[3];
    ss = sh[4] + sh[5] + sh[6] + sh[7];
    float mean = s * (1.f/1280.f);
    float var  = ss * (1.f/1280.f) - mean*mean;
    float rstd = rsqrtf(var + 1e-5f);
#pragma unroll
    for (int i = 0; i < 10; i++) {
        int c = tid + i*128;
        yr[c] = tf32r((v[i] - mean) * rstd * w[c] + b[c]);
    }
}

// ---------------------------------------------------------------------------
// Fused attention (fp32, online softmax). Output RNA-rounded (feeds GEMM A).
// ---------------------------------------------------------------------------
__global__ __launch_bounds__(256)
void attn_kernel(const float* __restrict__ Q, const float* __restrict__ K,
                 const float* __restrict__ V, float* __restrict__ O,
                 int Sq, int Sk, long kv_bstride, long q_bstride,
                 int sparse, float scale)
{
    __shared__ float Ks[32][160];
    __shared__ float Vs[32][160];

    int batch = blockIdx.z, head = blockIdx.y;
    int q0  = blockIdx.x * 64;
    int tid = threadIdx.x;
    int r   = tid >> 2, c4 = tid & 3;
    int d0  = c4 * 40;
    bool rowvalid = (q0 + r) < Sq;

    float qv[40];
    {
        int rr = rowvalid ? r : 0;
        const float* qp = Q + (size_t)batch * q_bstride
                            + (size_t)(q0 + rr) * DIMC + head * DH + d0;
#pragma unroll
        for (int i = 0; i < 40; i++) qv[i] = rowvalid ? qp[i] : 0.f;
    }

    float o[40];
#pragma unroll
    for (int i = 0; i < 40; i++) o[i] = 0.f;
    float m = -1e30f, l = 0.f;

    int lr = tid >> 3;
    int lc = (tid & 7) * 20;

    int ntiles = (Sk + 31) >> 5;
    for (int kt = 0; kt < ntiles; kt++) {
        int j = kt * 32 + lr;
        {
            const float* kp = nullptr;
            const float* vp = nullptr;
            if (j < Sk) {
                size_t off;
                if (sparse) {
                    int bb = batch >> 4, f = batch & 15;
                    int srcf = (j < 256) ? 0 : ((f > 0) ? (f - 1) : 0);
                    int jr2  = (j < 256) ? j : (j - 256);
                    off = ((size_t)(bb*16 + srcf) * 256 + jr2) * DIMC
                        + head * DH + lc;
                } else {
                    off = (size_t)batch * kv_bstride + (size_t)j * DIMC
                        + head * DH + lc;
                }
                kp = K + off; vp = V + off;
            }
#pragma unroll
            for (int i = 0; i < 5; i++) {
                float4 kx = kp ? *(const float4*)(kp + i*4)
                               : make_float4(0,0,0,0);
                float4 vx = vp ? *(const float4*)(vp + i*4)
                               : make_float4(0,0,0,0);
                *(float4*)&Ks[lr][lc + i*4] = kx;
                *(float4*)&Vs[lr][lc + i*4] = vx;
            }
        }
        __syncthreads();

#pragma unroll
        for (int jc = 0; jc < 2; jc++) {
            int jb = jc * 16;
            if (kt*32 + jb < Sk) {
                float p[16];
#pragma unroll
                for (int jj = 0; jj < 16; jj++) {
                    const float4* kr = (const float4*)&Ks[jb + jj][d0];
                    float s0 = 0.f, s1 = 0.f, s2 = 0.f, s3 = 0.f;
#pragma unroll
                    for (int i = 0; i < 10; i++) {
                        float4 k4 = kr[i];
                        s0 += qv[i*4+0]*k4.x; s1 += qv[i*4+1]*k4.y;
                        s2 += qv[i*4+2]*k4.z; s3 += qv[i*4+3]*k4.w;
                    }
                    p[jj] = (s0 + s1) + (s2 + s3);
                }
#pragma unroll
                for (int jj = 0; jj < 16; jj++) {
                    p[jj] += __shfl_xor_sync(0xffffffffu, p[jj], 1);
                    p[jj] += __shfl_xor_sync(0xffffffffu, p[jj], 2);
                    int jg = kt*32 + jb + jj;
                    p[jj] = (jg < Sk) ? p[jj] * scale : -1e30f;
                }
                float mt = m;
#pragma unroll
                for (int jj = 0; jj < 16; jj++) mt = fmaxf(mt, p[jj]);
                if (mt > m) {
                    float sc = __expf(m - mt);
                    l *= sc;
#pragma unroll
                    for (int i = 0; i < 40; i++) o[i] *= sc;
                    m = mt;
                }
#pragma unroll
                for (int jj = 0; jj < 16; jj++) {
                    float e = __expf(p[jj] - m);
                    l += e;
                    const float4* vr = (const float4*)&Vs[jb + jj][d0];
#pragma unroll
                    for (int i = 0; i < 10; i++) {
                        float4 v4 = vr[i];
                        o[i*4+0] += e * v4.x; o[i*4+1] += e * v4.y;
                        o[i*4+2] += e * v4.z; o[i*4+3] += e * v4.w;
                    }
                }
            }
        }
        __syncthreads();
    }

    if (rowvalid) {
        float inv = 1.f / l;
        float* op = O + (size_t)batch * q_bstride
                      + (size_t)(q0 + r) * DIMC + head * DH + d0;
#pragma unroll
        for (int i = 0; i < 40; i++) op[i] = tf32r(o[i] * inv);
    }
}

// ---------------------------------------------------------------------------
// GEGLU (output RNA-rounded — feeds ffw2 GEMM A)
// ---------------------------------------------------------------------------
__global__ void geglu_kernel(const float* __restrict__ in, float* __restrict__ out)
{
    size_t idx = (size_t)blockIdx.x * blockDim.x + threadIdx.x;
    if (idx >= (size_t)NROWS * FF_I) return;
    size_t rr = idx / FF_I;
    int    i  = (int)(idx - rr * FF_I);
    const float* row = in + rr * FF_N;
    float p = row[i];
    float g = row[FF_I + i];
    float gel = 0.5f * g * (1.f + erff(g * 0.70710678118654752f));
    out[idx] = tf32r(p * gel);
}

// ---------------------------------------------------------------------------
// Temporal reshape transposes
// ---------------------------------------------------------------------------
__global__ void transpose_fwd(const float* __restrict__ in, float* __restrict__ out)
{
    size_t idx = (size_t)blockIdx.x * blockDim.x + threadIdx.x;
    if (idx >= (size_t)NROWS * DIMC) return;
    int c   = (int)(idx % DIMC);
    int row = (int)(idx / DIMC);
    int f   = row & 15;
    int tok = (row >> 4) & 255;
    int b   = row >> 12;
    out[idx] = in[((size_t)((b*16 + f)*256 + tok)) * DIMC + c];
}

__global__ void transpose_bwd(const float* __restrict__ in, float* __restrict__ out)
{
    size_t idx = (size_t)blockIdx.x * blockDim.x + threadIdx.x;
    if (idx >= (size_t)NROWS * DIMC) return;
    int c   = (int)(idx % DIMC);
    int row = (int)(idx / DIMC);
    int tok = row & 255;
    int f   = (row >> 8) & 15;
    int b   = row >> 12;
    out[idx] = in[((size_t)((b*256 + tok)*16 + f)) * DIMC + c];
}

// ---------------------------------------------------------------------------
// Host launcher
// ---------------------------------------------------------------------------
static void launch_gemm(const float* A, const float* B, float* C,
                        const float* bias, const float* res,
                        int M, int N, int K)
{
    static bool attr_set = false;
    if (!attr_set) {
        cudaFuncSetAttribute(gemm_tf32v3,
            cudaFuncAttributeMaxDynamicSharedMemorySize, GEMM_SMEM);
        attr_set = true;
    }
    int nm = (M + 127) / 128, nn = N / 128;
    gemm_tf32v3<<<nm * nn, 256, GEMM_SMEM>>>(A, B, C, bias, res, M, N, K);
}

static void launch_round(const float* in, float* out, int n)
{
    round_copy<<<(n/4 + 255) / 256, 256>>>(in, out, n);
}

extern "C" void kernel_launch(void* const* d_in, const int* in_sizes, int n_in,
                              void* d_out, int out_size)
{
    const float* hid  = (const float*)d_in[0];
    const float* enc  = (const float*)d_in[1];
    const float* n1w  = (const float*)d_in[2];
    const float* n1b  = (const float*)d_in[3];
    const float* a1wq = (const float*)d_in[4];
    const float* a1wk = (const float*)d_in[5];
    const float* a1wv = (const float*)d_in[6];
    const float* a1wo = (const float*)d_in[7];
    const float* a1bo = (const float*)d_in[8];
    const float* n2w  = (const float*)d_in[9];
    const float* n2b  = (const float*)d_in[10];
    const float* a2wq = (const float*)d_in[11];
    const float* a2wk = (const float*)d_in[12];
    const float* a2wv = (const float*)d_in[13];
    const float* a2wo = (const float*)d_in[14];
    const float* a2bo = (const float*)d_in[15];
    const float* n3w  = (const float*)d_in[16];
    const float* n3b  = (const float*)d_in[17];
    const float* ffw1 = (const float*)d_in[18];
    const float* ffb1 = (const float*)d_in[19];
    const float* ffw2 = (const float*)d_in[20];
    const float* ffb2 = (const float*)d_in[21];
    const float* ntw  = (const float*)d_in[22];
    const float* ntb  = (const float*)d_in[23];
    const float* atwq = (const float*)d_in[24];
    const float* atwk = (const float*)d_in[25];
    const float* atwv = (const float*)d_in[26];
    const float* atwo = (const float*)d_in[27];
    const float* atbo = (const float*)d_in[28];

    float* out = (float*)d_out;

    float *nh, *q, *k, *v, *ao, *ht, *ff1, *gg, *enck, *encv, *encr, *wt;
    cudaGetSymbolAddress((void**)&nh,  g_nh);
    cudaGetSymbolAddress((void**)&q,   g_q);
    cudaGetSymbolAddress((void**)&k,   g_k);
    cudaGetSymbolAddress((void**)&v,   g_v);
    cudaGetSymbolAddress((void**)&ao,  g_ao);
    cudaGetSymbolAddress((void**)&ht,  g_ht);
    cudaGetSymbolAddress((void**)&ff1, g_ff1);
    cudaGetSymbolAddress((void**)&gg,  g_gg);
    cudaGetSymbolAddress((void**)&enck,g_enck);
    cudaGetSymbolAddress((void**)&encv,g_encv);
    cudaGetSymbolAddress((void**)&encr,g_encr);
    cudaGetSymbolAddress((void**)&wt,  g_wt);

    const float scale = 0.07905694150420949f;   // 160^-0.5
    const long QBS = (long)TOK * DIMC;

    // ---- one-time RNA tf32 rounding of B operands (weights + enc) ----
    launch_round(a1wq, wt + OFF_A1WQ, DIMC*DIMC);
    launch_round(a1wk, wt + OFF_A1WK, DIMC*DIMC);
    launch_round(a1wv, wt + OFF_A1WV, DIMC*DIMC);
    launch_round(a1wo, wt + OFF_A1WO, DIMC*DIMC);
    launch_round(a2wq, wt + OFF_A2WQ, DIMC*DIMC);
    launch_round(a2wk, wt + OFF_A2WK, CROSS*DIMC);
    launch_round(a2wv, wt + OFF_A2WV, CROSS*DIMC);
    launch_round(a2wo, wt + OFF_A2WO, DIMC*DIMC);
    launch_round(ffw1, wt + OFF_FFW1, DIMC*FF_N);
    launch_round(ffw2, wt + OFF_FFW2, FF_I*DIMC);
    launch_round(atwq, wt + OFF_ATWQ, DIMC*DIMC);
    launch_round(atwk, wt + OFF_ATWK, DIMC*DIMC);
    launch_round(atwv, wt + OFF_ATWV, DIMC*DIMC);
    launch_round(atwo, wt + OFF_ATWO, DIMC*DIMC);
    launch_round(enc,  encr,          ENCROWS*CROSS);

    // ---- attn1: sparse-causal self-attention ----
    ln_kernel<<<NROWS, 128>>>(hid, n1w, n1b, nh);
    launch_gemm(nh, wt + OFF_A1WQ, q, nullptr, nullptr, NROWS, DIMC, DIMC);
    launch_gemm(nh, wt + OFF_A1WK, k, nullptr, nullptr, NROWS, DIMC, DIMC);
    launch_gemm(nh, wt + OFF_A1WV, v, nullptr, nullptr, NROWS, DIMC, DIMC);
    attn_kernel<<<dim3(4, HEADS, BF), 256>>>(q, k, v, ao,
        TOK, 2*TOK, QBS, QBS, 1, scale);
    launch_gemm(ao, wt + OFF_A1WO, out, a1bo, hid, NROWS, DIMC, DIMC);

    // ---- attn2: cross-attention ----
    ln_kernel<<<NROWS, 128>>>(out, n2w, n2b, nh);
    launch_gemm(nh,   wt + OFF_A2WQ, q,    nullptr, nullptr, NROWS,   DIMC, DIMC);
    launch_gemm(encr, wt + OFF_A2WK, enck, nullptr, nullptr, ENCROWS, DIMC, CROSS);
    launch_gemm(encr, wt + OFF_A2WV, encv, nullptr, nullptr, ENCROWS, DIMC, CROSS);
    attn_kernel<<<dim3(4, HEADS, BF), 256>>>(q, enck, encv, ao,
        TOK, ESEQ, (long)ESEQ * DIMC, QBS, 0, scale);
    launch_gemm(ao, wt + OFF_A2WO, out, a2bo, out, NROWS, DIMC, DIMC);

    // ---- geglu FFN ----
    ln_kernel<<<NROWS, 128>>>(out, n3w, n3b, nh);
    launch_gemm(nh, wt + OFF_FFW1, ff1, ffb1, nullptr, NROWS, FF_N, DIMC);
    {
        size_t tot = (size_t)NROWS * FF_I;
        geglu_kernel<<<(unsigned)((tot + 255) / 256), 256>>>(ff1, gg);
    }
    launch_gemm(gg, wt + OFF_FFW2, out, ffb2, out, NROWS, DIMC, FF_I);

    // ---- temporal self-attention ----
    {
        size_t tot = (size_t)NROWS * DIMC;
        transpose_fwd<<<(unsigned)((tot + 255) / 256), 256>>>(out, ht);
    }
    ln_kernel<<<NROWS, 128>>>(ht, ntw, ntb, nh);
    launch_gemm(nh, wt + OFF_ATWQ, q, nullptr, nullptr, NROWS, DIMC, DIMC);
    launch_gemm(nh, wt + OFF_ATWK, k, nullptr, nullptr, NROWS, DIMC, DIMC);
    launch_gemm(nh, wt + OFF_ATWV, v, nullptr, nullptr, NROWS, DIMC, DIMC);
    attn_kernel<<<dim3(1, HEADS, 2*TOK), 256>>>(q, k, v, ao,
        FRAMES, FRAMES, (long)FRAMES * DIMC, (long)FRAMES * DIMC, 0, scale);
    launch_gemm(ao, wt + OFF_ATWO, ht, atbo, ht, NROWS, DIMC, DIMC);
    {
        size_t tot = (size_t)NROWS * DIMC;
        transpose_bwd<<<(unsigned)((tot + 255) / 256), 256>>>(ht, out);
    }
}

// round 10
// speedup vs baseline: 1.2355x; 1.0465x over previous
#include <cuda_runtime.h>
#include <cuda_bf16.h>
#include <cstdint>
#include <math.h>

// ---------------------------------------------------------------------------
// Problem constants
// ---------------------------------------------------------------------------
#define BF      32
#define TOK     256
#define DIMC    1280
#define HEADS   8
#define DH      160
#define CROSS   768
#define ESEQ    77
#define FRAMES  16
#define NROWS   (BF*TOK)          // 8192
#define ENCROWS (BF*ESEQ)         // 2464
#define FF_N    (2*4*DIMC)        // 10240
#define FF_I    (4*DIMC)          // 5120

// ---------------------------------------------------------------------------
// Scratch (device globals; no allocation allowed)
// ---------------------------------------------------------------------------
__device__ float g_nh [NROWS*DIMC];
__device__ float g_q  [NROWS*DIMC];
__device__ float g_ao [NROWS*DIMC];
__device__ float g_ht [NROWS*DIMC];
__device__ float g_ff1[(size_t)NROWS*FF_N];   // also QKV buffer [8192, 3840]
__device__ float g_gg [(size_t)NROWS*FF_I];   // also enc-KV buffer [2464, 2560]
__device__ float g_encr[ENCROWS*CROSS];
__device__ float g_wt [38010880];             // tf32-rounded (packed) weights

// packed-weight offsets (floats), all [K, N] row-major
#define OFF_W1QKV 0u          // [1280, 3840]
#define OFF_A1WO  4915200u    // [1280, 1280]
#define OFF_A2WQ  6553600u    // [1280, 1280]
#define OFF_W2KV  8192000u    // [768,  2560]
#define OFF_A2WO  10158080u   // [1280, 1280]
#define OFF_FFW1  11796480u   // [1280, 10240]
#define OFF_FFW2  24903680u   // [5120, 1280]
#define OFF_WTQKV 31457280u   // [1280, 3840]
#define OFF_ATWO  36372480u   // [1280, 1280]

// ---------------------------------------------------------------------------
// Helpers
// ---------------------------------------------------------------------------
__device__ __forceinline__ uint32_t f2tf(float f) {
    uint32_t u;
    asm("cvt.rna.tf32.f32 %0, %1;" : "=r"(u) : "f"(f));
    return u;
}
__device__ __forceinline__ float tf32r(float f) { return __uint_as_float(f2tf(f)); }

__device__ __forceinline__ uint32_t smem_u32(const void* p) {
    uint32_t a;
    asm("{ .reg .u64 t; cvta.to.shared.u64 t, %1; cvt.u32.u64 %0, t; }" : "=r"(a) : "l"(p));
    return a;
}

#define CPASYNC16(dst, src, sz) \
    asm volatile("cp.async.cg.shared.global [%0], [%1], 16, %2;" \
        :: "r"((uint32_t)(dst)), "l"(src), "r"((uint32_t)(sz)) : "memory")
#define CP_COMMIT() asm volatile("cp.async.commit_group;" ::: "memory")
#define CP_WAIT(n)  asm volatile("cp.async.wait_group %0;" :: "n"(n) : "memory")

// ---------------------------------------------------------------------------
// tf32 GEMM v4: C[M,N] = A[M,K] @ B[K,N] (+bias[N]) (+res[M,N])
// CTA tile 128x128x16, 8 warps (4m x 2n), warp tile 32x64, m16n8k8 tf32 mma.
// 3-stage cp.async pipeline; 2 CTAs/SM; ldmatrix.x4 A-fragment loads.
// Operands must be pre-rounded to tf32 (RNA).
// Requirements: K % 16 == 0, N % 128 == 0; M ragged OK.
// ---------------------------------------------------------------------------
#define STAGES        3
#define A_STG_FLOATS  (128*20)           // pad 16->20: bank-free frag loads
#define B_STG_FLOATS  (16*136)           // pad 128->136
#define A_STG_BYTES   (A_STG_FLOATS*4)   // 10240
#define B_STG_BYTES   (B_STG_FLOATS*4)   // 8704
#define GEMM_SMEM     (STAGES*(A_STG_BYTES+B_STG_BYTES))  // 56832

__global__ void __launch_bounds__(256, 2)
gemm_tf32v4(const float* __restrict__ A, const float* __restrict__ B,
            float* __restrict__ C, const float* __restrict__ bias,
            const float* __restrict__ res, int M, int N, int K)
{
    extern __shared__ __align__(16) char smem[];
    uint32_t aBase = smem_u32(smem);
    uint32_t bBase = aBase + STAGES * A_STG_BYTES;
    const uint32_t* bsu = (const uint32_t*)(smem + STAGES * A_STG_BYTES);

    int tid  = threadIdx.x;
    int warp = tid >> 5, lane = tid & 31;
    int wm = warp & 3, wn = warp >> 2;
    int g  = lane >> 2, t4 = lane & 3;

    // tile raster (GM groups along M for L2 reuse of B strips)
    int num_m = (M + 127) >> 7, num_n = N >> 7;
    const int GM = 8;
    int npg = GM * num_n;
    int group = blockIdx.x / npg;
    int first = group * GM;
    int gsz = min(num_m - first, GM);
    int rem = blockIdx.x - group * npg;
    int m0 = (first + rem % gsz) << 7;
    int n0 = (rem / gsz) << 7;

    // gmem load mapping
    int arow = tid >> 1, ac8 = (tid & 1) * 8;
    bool aval = (m0 + arow) < M;
    const float* aptr = A + (size_t)(m0 + arow) * K + ac8;
    const float* bptr = B + (size_t)(tid >> 4) * N + n0 + (tid & 15) * 8;
    uint32_t aDst = aBase + (arow * 20 + ac8) * 4;
    uint32_t bDst = bBase + ((tid >> 4) * 136 + (tid & 15) * 8) * 4;

    // ldmatrix per-lane address component:
    // lanes 0-7: mat0 rows 0-7 col+0 | 8-15: mat1 rows 8-15 col+0
    // 16-23: mat2 rows 0-7 col+4     | 24-31: mat3 rows 8-15 col+4
    uint32_t aFragOff = (((wm * 32 + (lane & 15)) * 20) + ((lane >> 4) << 2)) * 4;

    float acc[2][8][4];
#pragma unroll
    for (int mi = 0; mi < 2; mi++)
#pragma unroll
        for (int ni = 0; ni < 8; ni++)
#pragma unroll
            for (int i = 0; i < 4; i++) acc[mi][ni][i] = 0.f;

    int KT = K >> 4;

#define LOAD_STAGE(kt, s)                                                     \
    do {                                                                      \
        const float* _a = aptr + (kt) * 16;                                   \
        uint32_t _ad = aDst + (s) * A_STG_BYTES;                              \
        unsigned _sz = aval ? 16u : 0u;                                       \
        CPASYNC16(_ad,      _a,     _sz);                                     \
        CPASYNC16(_ad + 16, _a + 4, _sz);                                     \
        const float* _b = bptr + (size_t)(kt) * 16 * N;                       \
        uint32_t _bd = bDst + (s) * B_STG_BYTES;                              \
        CPASYNC16(_bd,      _b,     16u);                                     \
        CPASYNC16(_bd + 16, _b + 4, 16u);                                     \
    } while (0)

#pragma unroll
    for (int s = 0; s < STAGES - 1; s++) {
        if (s < KT) LOAD_STAGE(s, s);
        CP_COMMIT();
    }

    for (int kt = 0; kt < KT; kt++) {
        CP_WAIT(STAGES - 2);
        __syncthreads();

        int nk = kt + STAGES - 1;
        if (nk < KT) LOAD_STAGE(nk, nk % STAGES);
        CP_COMMIT();

        uint32_t astage = aBase + (kt % STAGES) * A_STG_BYTES + aFragOff;
        const uint32_t* bs = bsu + (kt % STAGES) * B_STG_FLOATS;

#pragma unroll
        for (int ks = 0; ks < 2; ks++) {
            int kk = ks * 8;
            uint32_t af[2][4];
#pragma unroll
            for (int mi = 0; mi < 2; mi++) {
                uint32_t addr = astage + (mi * 16 * 20 + kk) * 4;
                asm volatile(
                    "ldmatrix.sync.aligned.m8n8.x4.shared.b16 {%0,%1,%2,%3}, [%4];"
                    : "=r"(af[mi][0]), "=r"(af[mi][1]),
                      "=r"(af[mi][2]), "=r"(af[mi][3])
                    : "r"(addr));
            }
#pragma unroll
            for (int ni = 0; ni < 8; ni++) {
                int c = wn*64 + ni*8 + g;
                uint32_t b0 = bs[(kk + t4)     * 136 + c];
                uint32_t b1 = bs[(kk + t4 + 4) * 136 + c];
#pragma unroll
                for (int mi = 0; mi < 2; mi++)
                    asm volatile(
                        "mma.sync.aligned.m16n8k8.row.col.f32.tf32.tf32.f32 "
                        "{%0,%1,%2,%3}, {%4,%5,%6,%7}, {%8,%9}, {%0,%1,%2,%3};"
                        : "+f"(acc[mi][ni][0]), "+f"(acc[mi][ni][1]),
                          "+f"(acc[mi][ni][2]), "+f"(acc[mi][ni][3])
                        : "r"(af[mi][0]), "r"(af[mi][1]),
                          "r"(af[mi][2]), "r"(af[mi][3]),
                          "r"(b0), "r"(b1));
            }
        }
    }
#undef LOAD_STAGE

    // epilogue: + bias + residual, float2 stores
#pragma unroll
    for (int mi = 0; mi < 2; mi++) {
#pragma unroll
        for (int ni = 0; ni < 8; ni++) {
            int row = m0 + wm*32 + mi*16 + g;
            int col = n0 + wn*64 + ni*8 + t4*2;
            float2 bv = bias ? *(const float2*)(bias + col)
                             : make_float2(0.f, 0.f);
            if (row < M) {
                size_t idx = (size_t)row * N + col;
                float2 rv = res ? *(const float2*)(res + idx)
                                : make_float2(0.f, 0.f);
                float2 o;
                o.x = acc[mi][ni][0] + bv.x + rv.x;
                o.y = acc[mi][ni][1] + bv.y + rv.y;
                *(float2*)(C + idx) = o;
            }
            if (row + 8 < M) {
                size_t idx = (size_t)(row + 8) * N + col;
                float2 rv = res ? *(const float2*)(res + idx)
                                : make_float2(0.f, 0.f);
                float2 o;
                o.x = acc[mi][ni][2] + bv.x + rv.x;
                o.y = acc[mi][ni][3] + bv.y + rv.y;
                *(float2*)(C + idx) = o;
            }
        }
    }
}

// ---------------------------------------------------------------------------
// Weight packing kernels (RNA tf32 rounding)
// ---------------------------------------------------------------------------
__global__ void pack3(const float* __restrict__ s0, const float* __restrict__ s1,
                      const float* __restrict__ s2, float* __restrict__ dst,
                      int K, int N)
{
    int idx = (blockIdx.x * 256 + threadIdx.x) * 4;
    if (idx >= K * N) return;
    int k = idx / N, n = idx - k * N;
    size_t dbase = (size_t)k * 3 * N + n;
    float4 v;
    v = *(const float4*)(s0 + idx);
    v.x = tf32r(v.x); v.y = tf32r(v.y); v.z = tf32r(v.z); v.w = tf32r(v.w);
    *(float4*)(dst + dbase) = v;
    v = *(const float4*)(s1 + idx);
    v.x = tf32r(v.x); v.y = tf32r(v.y); v.z = tf32r(v.z); v.w = tf32r(v.w);
    *(float4*)(dst + dbase + N) = v;
    v = *(const float4*)(s2 + idx);
    v.x = tf32r(v.x); v.y = tf32r(v.y); v.z = tf32r(v.z); v.w = tf32r(v.w);
    *(float4*)(dst + dbase + 2 * N) = v;
}

__global__ void pack2(const float* __restrict__ s0, const float* __restrict__ s1,
                      float* __restrict__ dst, int K, int N)
{
    int idx = (blockIdx.x * 256 + threadIdx.x) * 4;
    if (idx >= K * N) return;
    int k = idx / N, n = idx - k * N;
    size_t dbase = (size_t)k * 2 * N + n;
    float4 v;
    v = *(const float4*)(s0 + idx);
    v.x = tf32r(v.x); v.y = tf32r(v.y); v.z = tf32r(v.z); v.w = tf32r(v.w);
    *(float4*)(dst + dbase) = v;
    v = *(const float4*)(s1 + idx);
    v.x = tf32r(v.x); v.y = tf32r(v.y); v.z = tf32r(v.z); v.w = tf32r(v.w);
    *(float4*)(dst + dbase + N) = v;
}

__global__ void round_copy(const float* __restrict__ in, float* __restrict__ out, int n)
{
    int i = (blockIdx.x * 256 + threadIdx.x) * 4;
    if (i < n) {
        float4 v = *(const float4*)(in + i);
        v.x = tf32r(v.x); v.y = tf32r(v.y); v.z = tf32r(v.z); v.w = tf32r(v.w);
        *(float4*)(out + i) = v;
    }
}

// ---------------------------------------------------------------------------
// LayerNorm (output RNA-rounded to tf32 — it only feeds GEMM A operands)
// ---------------------------------------------------------------------------
__global__ __launch_bounds__(128)
void ln_kernel(const float* __restrict__ x, const float* __restrict__ w,
               const float* __restrict__ b, float* __restrict__ y)
{
    int row = blockIdx.x;
    const float* xr = x + (size_t)row * DIMC;
    float*       yr = y + (size_t)row * DIMC;
    int tid = threadIdx.x;

    float v[10];
    float s = 0.f, ss = 0.f;
#pragma unroll
    for (int i = 0; i < 10; i++) {
        float t = xr[tid + i*128];
        v[i] = t; s += t; ss += t*t;
    }
#pragma unroll
    for (int off = 16; off; off >>= 1) {
        s  += __shfl_xor_sync(0xffffffffu, s,  off);
        ss += __shfl_xor_sync(0xffffffffu, ss, off);
    }
    __shared__ float sh[8];
    int warp = tid >> 5;
    if ((tid & 31) == 0) { sh[warp] = s; sh[4+warp] = ss; }
    __syncthreads();
    s  = sh[0] + sh[1] + sh[2] + sh[3];
    ss = sh[4] + sh[5] + sh[6] + sh[7];
    float mean = s * (1.f/1280.f);
    float var  = ss * (1.f/1280.f) - mean*mean;
    float rstd = rsqrtf(var + 1e-5f);
#pragma unroll
    for (int i = 0; i < 10; i++) {
        int c = tid + i*128;
        yr[c] = tf32r((v[i] - mean) * rstd * w[c] + b[c]);
    }
}

// ---------------------------------------------------------------------------
// Fused attention (fp32, online softmax) with explicit row strides.
// Output RNA-rounded (feeds GEMM A).
// ---------------------------------------------------------------------------
__global__ __launch_bounds__(256)
void attn_kernel(const float* __restrict__ Q, const float* __restrict__ K,
                 const float* __restrict__ V, float* __restrict__ O,
                 int Sq, int Sk, long q_bs, long kv_bs, long o_bs,
                 int ldq, int ldkv, int ldo, int sparse, float scale)
{
    __shared__ float Ks[32][160];
    __shared__ float Vs[32][160];

    int batch = blockIdx.z, head = blockIdx.y;
    int q0  = blockIdx.x * 64;
    int tid = threadIdx.x;
    int r   = tid >> 2, c4 = tid & 3;
    int d0  = c4 * 40;
    bool rowvalid = (q0 + r) < Sq;

    float qv[40];
    {
        int rr = rowvalid ? r : 0;
        const float* qp = Q + (size_t)batch * q_bs
                            + (size_t)(q0 + rr) * ldq + head * DH + d0;
#pragma unroll
        for (int i = 0; i < 40; i++) qv[i] = rowvalid ? qp[i] : 0.f;
    }

    float o[40];
#pragma unroll
    for (int i = 0; i < 40; i++) o[i] = 0.f;
    float m = -1e30f, l = 0.f;

    int lr = tid >> 3;
    int lc = (tid & 7) * 20;

    int ntiles = (Sk + 31) >> 5;
    for (int kt = 0; kt < ntiles; kt++) {
        int j = kt * 32 + lr;
        {
            const float* kp = nullptr;
            const float* vp = nullptr;
            if (j < Sk) {
                size_t off;
                if (sparse) {
                    int bb = batch >> 4, f = batch & 15;
                    int srcf = (j < 256) ? 0 : ((f > 0) ? (f - 1) : 0);
                    int jr2  = (j < 256) ? j : (j - 256);
                    off = (size_t)((bb*16 + srcf) * 256 + jr2) * ldkv
                        + head * DH + lc;
                } else {
                    off = (size_t)batch * kv_bs + (size_t)j * ldkv
                        + head * DH + lc;
                }
                kp = K + off; vp = V + off;
            }
#pragma unroll
            for (int i = 0; i < 5; i++) {
                float4 kx = kp ? *(const float4*)(kp + i*4)
                               : make_float4(0,0,0,0);
                float4 vx = vp ? *(const float4*)(vp + i*4)
                               : make_float4(0,0,0,0);
                *(float4*)&Ks[lr][lc + i*4] = kx;
                *(float4*)&Vs[lr][lc + i*4] = vx;
            }
        }
        __syncthreads();

#pragma unroll
        for (int jc = 0; jc < 2; jc++) {
            int jb = jc * 16;
            if (kt*32 + jb < Sk) {
                float p[16];
#pragma unroll
                for (int jj = 0; jj < 16; jj++) {
                    const float4* kr = (const float4*)&Ks[jb + jj][d0];
                    float s0 = 0.f, s1 = 0.f, s2 = 0.f, s3 = 0.f;
#pragma unroll
                    for (int i = 0; i < 10; i++) {
                        float4 k4 = kr[i];
                        s0 += qv[i*4+0]*k4.x; s1 += qv[i*4+1]*k4.y;
                        s2 += qv[i*4+2]*k4.z; s3 += qv[i*4+3]*k4.w;
                    }
                    p[jj] = (s0 + s1) + (s2 + s3);
                }
#pragma unroll
                for (int jj = 0; jj < 16; jj++) {
                    p[jj] += __shfl_xor_sync(0xffffffffu, p[jj], 1);
                    p[jj] += __shfl_xor_sync(0xffffffffu, p[jj], 2);
                    int jg = kt*32 + jb + jj;
                    p[jj] = (jg < Sk) ? p[jj] * scale : -1e30f;
                }
                float mt = m;
#pragma unroll
                for (int jj = 0; jj < 16; jj++) mt = fmaxf(mt, p[jj]);
                if (mt > m) {
                    float sc = __expf(m - mt);
                    l *= sc;
#pragma unroll
                    for (int i = 0; i < 40; i++) o[i] *= sc;
                    m = mt;
                }
#pragma unroll
                for (int jj = 0; jj < 16; jj++) {
                    float e = __expf(p[jj] - m);
                    l += e;
                    const float4* vr = (const float4*)&Vs[jb + jj][d0];
#pragma unroll
                    for (int i = 0; i < 10; i++) {
                        float4 v4 = vr[i];
                        o[i*4+0] += e * v4.x; o[i*4+1] += e * v4.y;
                        o[i*4+2] += e * v4.z; o[i*4+3] += e * v4.w;
                    }
                }
            }
        }
        __syncthreads();
    }

    if (rowvalid) {
        float inv = 1.f / l;
        float* op = O + (size_t)batch * o_bs
                      + (size_t)(q0 + r) * ldo + head * DH + d0;
#pragma unroll
        for (int i = 0; i < 40; i++) op[i] = tf32r(o[i] * inv);
    }
}

// ---------------------------------------------------------------------------
// GEGLU (output RNA-rounded — feeds ffw2 GEMM A)
// ---------------------------------------------------------------------------
__global__ void geglu_kernel(const float* __restrict__ in, float* __restrict__ out)
{
    size_t idx = (size_t)blockIdx.x * blockDim.x + threadIdx.x;
    if (idx >= (size_t)NROWS * FF_I) return;
    size_t rr = idx / FF_I;
    int    i  = (int)(idx - rr * FF_I);
    const float* row = in + rr * FF_N;
    float p = row[i];
    float g = row[FF_I + i];
    float gel = 0.5f * g * (1.f + erff(g * 0.70710678118654752f));
    out[idx] = tf32r(p * gel);
}

// ---------------------------------------------------------------------------
// Temporal reshape transposes
// ---------------------------------------------------------------------------
__global__ void transpose_fwd(const float* __restrict__ in, float* __restrict__ out)
{
    size_t idx = (size_t)blockIdx.x * blockDim.x + threadIdx.x;
    if (idx >= (size_t)NROWS * DIMC) return;
    int c   = (int)(idx % DIMC);
    int row = (int)(idx / DIMC);
    int f   = row & 15;
    int tok = (row >> 4) & 255;
    int b   = row >> 12;
    out[idx] = in[((size_t)((b*16 + f)*256 + tok)) * DIMC + c];
}

__global__ void transpose_bwd(const float* __restrict__ in, float* __restrict__ out)
{
    size_t idx = (size_t)blockIdx.x * blockDim.x + threadIdx.x;
    if (idx >= (size_t)NROWS * DIMC) return;
    int c   = (int)(idx % DIMC);
    int row = (int)(idx / DIMC);
    int tok = row & 255;
    int f   = (row >> 8) & 15;
    int b   = row >> 12;
    out[idx] = in[((size_t)((b*256 + tok)*16 + f)) * DIMC + c];
}

// ---------------------------------------------------------------------------
// Host launcher
// ---------------------------------------------------------------------------
static void launch_gemm(const float* A, const float* B, float* C,
                        const float* bias, const float* res,
                        int M, int N, int K)
{
    static bool attr_set = false;
    if (!attr_set) {
        cudaFuncSetAttribute(gemm_tf32v4,
            cudaFuncAttributeMaxDynamicSharedMemorySize, GEMM_SMEM);
        attr_set = true;
    }
    int nm = (M + 127) / 128, nn = N / 128;
    gemm_tf32v4<<<nm * nn, 256, GEMM_SMEM>>>(A, B, C, bias, res, M, N, K);
}

static void launch_round(const float* in, float* out, int n)
{
    round_copy<<<(n/4 + 255) / 256, 256>>>(in, out, n);
}

extern "C" void kernel_launch(void* const* d_in, const int* in_sizes, int n_in,
                              void* d_out, int out_size)
{
    const float* hid  = (const float*)d_in[0];
    const float* enc  = (const float*)d_in[1];
    const float* n1w  = (const float*)d_in[2];
    const float* n1b  = (const float*)d_in[3];
    const float* a1wq = (const float*)d_in[4];
    const float* a1wk = (const float*)d_in[5];
    const float* a1wv = (const float*)d_in[6];
    const float* a1wo = (const float*)d_in[7];
    const float* a1bo = (const float*)d_in[8];
    const float* n2w  = (const float*)d_in[9];
    const float* n2b  = (const float*)d_in[10];
    const float* a2wq = (const float*)d_in[11];
    const float* a2wk = (const float*)d_in[12];
    const float* a2wv = (const float*)d_in[13];
    const float* a2wo = (const float*)d_in[14];
    const float* a2bo = (const float*)d_in[15];
    const float* n3w  = (const float*)d_in[16];
    const float* n3b  = (const float*)d_in[17];
    const float* ffw1 = (const float*)d_in[18];
    const float* ffb1 = (const float*)d_in[19];
    const float* ffw2 = (const float*)d_in[20];
    const float* ffb2 = (const float*)d_in[21];
    const float* ntw  = (const float*)d_in[22];
    const float* ntb  = (const float*)d_in[23];
    const float* atwq = (const float*)d_in[24];
    const float* atwk = (const float*)d_in[25];
    const float* atwv = (const float*)d_in[26];
    const float* atwo = (const float*)d_in[27];
    const float* atbo = (const float*)d_in[28];

    float* out = (float*)d_out;

    float *nh, *q, *ao, *ht, *ff1, *gg, *encr, *wt;
    cudaGetSymbolAddress((void**)&nh,  g_nh);
    cudaGetSymbolAddress((void**)&q,   g_q);
    cudaGetSymbolAddress((void**)&ao,  g_ao);
    cudaGetSymbolAddress((void**)&ht,  g_ht);
    cudaGetSymbolAddress((void**)&ff1, g_ff1);
    cudaGetSymbolAddress((void**)&gg,  g_gg);
    cudaGetSymbolAddress((void**)&encr,g_encr);
    cudaGetSymbolAddress((void**)&wt,  g_wt);

    const float scale = 0.07905694150420949f;   // 160^-0.5

    // ---- one-time packing/rounding of B operands ----
    {
        int n1 = DIMC * DIMC;     // 1,638,400
        pack3<<<(n1/4 + 255) / 256, 256>>>(a1wq, a1wk, a1wv, wt + OFF_W1QKV, DIMC, DIMC);
        pack3<<<(n1/4 + 255) / 256, 256>>>(atwq, atwk, atwv, wt + OFF_WTQKV, DIMC, DIMC);
        int n2 = CROSS * DIMC;    // 983,040
        pack2<<<(n2/4 + 255) / 256, 256>>>(a2wk, a2wv, wt + OFF_W2KV, CROSS, DIMC);
        launch_round(a1wo, wt + OFF_A1WO, n1);
        launch_round(a2wq, wt + OFF_A2WQ, n1);
        launch_round(a2wo, wt + OFF_A2WO, n1);
        launch_round(ffw1, wt + OFF_FFW1, DIMC*FF_N);
        launch_round(ffw2, wt + OFF_FFW2, FF_I*DIMC);
        launch_round(atwo, wt + OFF_ATWO, n1);
        launch_round(enc,  encr,          ENCROWS*CROSS);
    }

    const int QKV = 3 * DIMC;     // 3840
    const int KV2 = 2 * DIMC;     // 2560

    // ---- attn1: sparse-causal self-attention ----
    ln_kernel<<<NROWS, 128>>>(hid, n1w, n1b, nh);
    launch_gemm(nh, wt + OFF_W1QKV, ff1, nullptr, nullptr, NROWS, QKV, DIMC);
    attn_kernel<<<dim3(4, HEADS, BF), 256>>>(
        ff1, ff1 + DIMC, ff1 + 2*DIMC, ao,
        TOK, 2*TOK, (long)TOK*QKV, 0, (long)TOK*DIMC,
        QKV, QKV, DIMC, 1, scale);
    launch_gemm(ao, wt + OFF_A1WO, out, a1bo, hid, NROWS, DIMC, DIMC);

    // ---- attn2: cross-attention ----
    ln_kernel<<<NROWS, 128>>>(out, n2w, n2b, nh);
    launch_gemm(nh,   wt + OFF_A2WQ, q,  nullptr, nullptr, NROWS,   DIMC, DIMC);
    launch_gemm(encr, wt + OFF_W2KV, gg, nullptr, nullptr, ENCROWS, KV2,  CROSS);
    attn_kernel<<<dim3(4, HEADS, BF), 256>>>(
        q, gg, gg + DIMC, ao,
        TOK, ESEQ, (long)TOK*DIMC, (long)ESEQ*KV2, (long)TOK*DIMC,
        DIMC, KV2, DIMC, 0, scale);
    launch_gemm(ao, wt + OFF_A2WO, out, a2bo, out, NROWS, DIMC, DIMC);

    // ---- geglu FFN ----
    ln_kernel<<<NROWS, 128>>>(out, n3w, n3b, nh);
    launch_gemm(nh, wt + OFF_FFW1, ff1, ffb1, nullptr, NROWS, FF_N, DIMC);
    {
        size_t tot = (size_t)NROWS * FF_I;
        geglu_kernel<<<(unsigned)((tot + 255) / 256), 256>>>(ff1, gg);
    }
    launch_gemm(gg, wt + OFF_FFW2, out, ffb2, out, NROWS, DIMC, FF_I);

    // ---- temporal self-attention ----
    {
        size_t tot = (size_t)NROWS * DIMC;
        transpose_fwd<<<(unsigned)((tot + 255) / 256), 256>>>(out, ht);
    }
    ln_kernel<<<NROWS, 128>>>(ht, ntw, ntb, nh);
    launch_gemm(nh, wt + OFF_WTQKV, ff1, nullptr, nullptr, NROWS, QKV, DIMC);
    attn_kernel<<<dim3(1, HEADS, 2*TOK), 256>>>(
        ff1, ff1 + DIMC, ff1 + 2*DIMC, ao,
        FRAMES, FRAMES, (long)FRAMES*QKV, (long)FRAMES*QKV, (long)FRAMES*DIMC,
        QKV, QKV, DIMC, 0, scale);
    launch_gemm(ao, wt + OFF_ATWO, ht, atbo, ht, NROWS, DIMC, DIMC);
    {
        size_t tot = (size_t)NROWS * DIMC;
        transpose_bwd<<<(unsigned)((tot + 255) / 256), 256>>>(ht, out);
    }
}

// round 11
// speedup vs baseline: 1.3539x; 1.0958x over previous
#include <cuda_runtime.h>
#include <cuda_bf16.h>
#include <cstdint>
#include <math.h>

// ---------------------------------------------------------------------------
// Problem constants
// ---------------------------------------------------------------------------
#define BF      32
#define TOK     256
#define DIMC    1280
#define HEADS   8
#define DH      160
#define CROSS   768
#define ESEQ    77
#define FRAMES  16
#define NROWS   (BF*TOK)          // 8192
#define ENCROWS (BF*ESEQ)         // 2464
#define FF_N    (2*4*DIMC)        // 10240
#define FF_I    (4*DIMC)          // 5120

// ---------------------------------------------------------------------------
// Scratch (device globals; no allocation allowed)
// ---------------------------------------------------------------------------
__device__ float g_nh [NROWS*DIMC];
__device__ float g_q  [NROWS*DIMC];
__device__ float g_ao [NROWS*DIMC];
__device__ float g_ht [NROWS*DIMC];
__device__ float g_ff1[(size_t)NROWS*FF_N];   // also QKV buffer [8192, 3840]
__device__ float g_gg [(size_t)NROWS*FF_I];   // also enc-KV buffer [2464, 2560]
__device__ float g_encr[ENCROWS*CROSS];
__device__ float g_wt [38010880];             // tf32-rounded (packed) weights

// packed-weight offsets (floats), all [K, N] row-major
#define OFF_W1QKV 0u          // [1280, 3840]
#define OFF_A1WO  4915200u    // [1280, 1280]
#define OFF_A2WQ  6553600u    // [1280, 1280]
#define OFF_W2KV  8192000u    // [768,  2560]
#define OFF_A2WO  10158080u   // [1280, 1280]
#define OFF_FFW1  11796480u   // [1280, 10240]
#define OFF_FFW2  24903680u   // [5120, 1280]
#define OFF_WTQKV 31457280u   // [1280, 3840]
#define OFF_ATWO  36372480u   // [1280, 1280]

// ---------------------------------------------------------------------------
// Helpers
// ---------------------------------------------------------------------------
__device__ __forceinline__ uint32_t f2tf(float f) {
    uint32_t u;
    asm("cvt.rna.tf32.f32 %0, %1;" : "=r"(u) : "f"(f));
    return u;
}
__device__ __forceinline__ float tf32r(float f) { return __uint_as_float(f2tf(f)); }

__device__ __forceinline__ uint32_t smem_u32(const void* p) {
    uint32_t a;
    asm("{ .reg .u64 t; cvta.to.shared.u64 t, %1; cvt.u32.u64 %0, t; }" : "=r"(a) : "l"(p));
    return a;
}

#define CPASYNC16(dst, src, sz) \
    asm volatile("cp.async.cg.shared.global [%0], [%1], 16, %2;" \
        :: "r"((uint32_t)(dst)), "l"(src), "r"((uint32_t)(sz)) : "memory")
#define CP_COMMIT() asm volatile("cp.async.commit_group;" ::: "memory")
#define CP_WAIT(n)  asm volatile("cp.async.wait_group %0;" :: "n"(n) : "memory")

// ---------------------------------------------------------------------------
// tf32 GEMM v5: C[M,N] = A[M,K] @ B[K,N] (+bias[N]) (+res[M,N])
// CTA tile 128x128x16, 8 warps (4m x 2n), warp tile 32x64, m16n8k8 tf32 mma.
// 4-stage cp.async pipeline; 2 CTAs/SM; ldmatrix.x4 A frags;
// column-permuted MMA tiles + row-rotated B layout -> LDS.128 B frags.
// Operands must be pre-rounded to tf32 (RNA).
// Requirements: K % 16 == 0, N % 128 == 0; M ragged OK.
// ---------------------------------------------------------------------------
#define STAGES        4
#define A_STG_FLOATS  (128*20)           // pad 16->20: bank-free LDSM
#define B_STG_FLOATS  (16*128)           // stride 128, rows rotated by r(k&3)
#define A_STG_BYTES   (A_STG_FLOATS*4)   // 10240
#define B_STG_BYTES   (B_STG_FLOATS*4)   // 8192
#define GEMM_SMEM     (STAGES*(A_STG_BYTES+B_STG_BYTES))  // 73728

// rotation (in words) for B row k: r = 4*a, a(k) for k&3 = 0,1,2,3 -> 0,1,4,5
__device__ __forceinline__ int brot(int k3) { return (k3 + 2 * (k3 >> 1)) * 4; }

__global__ void __launch_bounds__(256, 2)
gemm_tf32v5(const float* __restrict__ A, const float* __restrict__ B,
            float* __restrict__ C, const float* __restrict__ bias,
            const float* __restrict__ res, int M, int N, int K)
{
    extern __shared__ __align__(16) char smem[];
    uint32_t aBase = smem_u32(smem);
    uint32_t bBase = aBase + STAGES * A_STG_BYTES;

    int tid  = threadIdx.x;
    int warp = tid >> 5, lane = tid & 31;
    int wm = warp & 3, wn = warp >> 2;
    int g  = lane >> 2, t4 = lane & 3;

    // tile raster (GM groups along M for L2 reuse of B strips)
    int num_m = (M + 127) >> 7, num_n = N >> 7;
    const int GM = 8;
    int npg = GM * num_n;
    int group = blockIdx.x / npg;
    int first = group * GM;
    int gsz = min(num_m - first, GM);
    int rem = blockIdx.x - group * npg;
    int m0 = (first + rem % gsz) << 7;
    int n0 = (rem / gsz) << 7;

    // gmem load mapping
    int arow = tid >> 1, ac8 = (tid & 1) * 8;
    bool aval = (m0 + arow) < M;
    const float* aptr = A + (size_t)(m0 + arow) * K + ac8;
    uint32_t aDst = aBase + (arow * 20 + ac8) * 4;

    int bk  = tid >> 4;              // B row 0..15
    int bw0 = (tid & 15) * 8;        // logical word 0,8,...,120
    int brr = brot(bk & 3);
    const float* bptr = B + (size_t)bk * N + n0 + bw0;
    uint32_t bD0 = bBase + (bk * 128 + ((bw0 + brr) & 127)) * 4;
    uint32_t bD1 = bBase + (bk * 128 + ((bw0 + 4 + brr) & 127)) * 4;

    // ldmatrix A per-lane address
    uint32_t aFragOff = (((wm * 32 + (lane & 15)) * 20) + ((lane >> 4) << 2)) * 4;

    // B fragment physical word offsets (per thread, constant across k)
    int rB  = brot(t4);
    int pb0 = (wn * 64 + 8 * g + rB) & 127;
    int pb1 = (wn * 64 + 8 * g + 4 + rB) & 127;

    float acc[2][8][4];
#pragma unroll
    for (int mi = 0; mi < 2; mi++)
#pragma unroll
        for (int ni = 0; ni < 8; ni++)
#pragma unroll
            for (int i = 0; i < 4; i++) acc[mi][ni][i] = 0.f;

    int KT = K >> 4;

#define LOAD_STAGE(kt, s)                                                     \
    do {                                                                      \
        const float* _a = aptr + (kt) * 16;                                   \
        uint32_t _ad = aDst + (s) * A_STG_BYTES;                              \
        unsigned _sz = aval ? 16u : 0u;                                       \
        CPASYNC16(_ad,      _a,     _sz);                                     \
        CPASYNC16(_ad + 16, _a + 4, _sz);                                     \
        const float* _b = bptr + (size_t)(kt) * 16 * N;                       \
        CPASYNC16(bD0 + (s) * B_STG_BYTES, _b,     16u);                      \
        CPASYNC16(bD1 + (s) * B_STG_BYTES, _b + 4, 16u);                      \
    } while (0)

#pragma unroll
    for (int s = 0; s < STAGES - 1; s++) {
        if (s < KT) LOAD_STAGE(s, s);
        CP_COMMIT();
    }

    for (int kt = 0; kt < KT; kt++) {
        CP_WAIT(STAGES - 2);
        __syncthreads();

        int nk = kt + STAGES - 1;
        if (nk < KT) LOAD_STAGE(nk, nk % STAGES);
        CP_COMMIT();

        uint32_t astage = aBase + (kt % STAGES) * A_STG_BYTES + aFragOff;
        uint32_t bstage = bBase + (kt % STAGES) * B_STG_BYTES;

#pragma unroll
        for (int ks = 0; ks < 2; ks++) {
            int kk = ks * 8;
            uint32_t af[2][4];
#pragma unroll
            for (int mi = 0; mi < 2; mi++) {
                uint32_t addr = astage + (mi * 16 * 20 + kk) * 4;
                asm volatile(
                    "ldmatrix.sync.aligned.m8n8.x4.shared.b16 {%0,%1,%2,%3}, [%4];"
                    : "=r"(af[mi][0]), "=r"(af[mi][1]),
                      "=r"(af[mi][2]), "=r"(af[mi][3])
                    : "r"(addr));
            }
            // B fragment rows kk+t4 and kk+t4+4, 8 contiguous logical cols
            float4 x0, x1, y0, y1;
            {
                uint32_t r0 = bstage + ((kk + t4) * 128) * 4;
                uint32_t r1 = bstage + ((kk + t4 + 4) * 128) * 4;
                asm volatile("ld.shared.v4.f32 {%0,%1,%2,%3}, [%4];"
                    : "=f"(x0.x), "=f"(x0.y), "=f"(x0.z), "=f"(x0.w)
                    : "r"(r0 + pb0 * 4));
                asm volatile("ld.shared.v4.f32 {%0,%1,%2,%3}, [%4];"
                    : "=f"(x1.x), "=f"(x1.y), "=f"(x1.z), "=f"(x1.w)
                    : "r"(r0 + pb1 * 4));
                asm volatile("ld.shared.v4.f32 {%0,%1,%2,%3}, [%4];"
                    : "=f"(y0.x), "=f"(y0.y), "=f"(y0.z), "=f"(y0.w)
                    : "r"(r1 + pb0 * 4));
                asm volatile("ld.shared.v4.f32 {%0,%1,%2,%3}, [%4];"
                    : "=f"(y1.x), "=f"(y1.y), "=f"(y1.z), "=f"(y1.w)
                    : "r"(r1 + pb1 * 4));
            }
            float b0a[8] = {x0.x, x0.y, x0.z, x0.w, x1.x, x1.y, x1.z, x1.w};
            float b1a[8] = {y0.x, y0.y, y0.z, y0.w, y1.x, y1.y, y1.z, y1.w};
#pragma unroll
            for (int ni = 0; ni < 8; ni++) {
                uint32_t b0 = __float_as_uint(b0a[ni]);
                uint32_t b1 = __float_as_uint(b1a[ni]);
#pragma unroll
                for (int mi = 0; mi < 2; mi++)
                    asm volatile(
                        "mma.sync.aligned.m16n8k8.row.col.f32.tf32.tf32.f32 "
                        "{%0,%1,%2,%3}, {%4,%5,%6,%7}, {%8,%9}, {%0,%1,%2,%3};"
                        : "+f"(acc[mi][ni][0]), "+f"(acc[mi][ni][1]),
                          "+f"(acc[mi][ni][2]), "+f"(acc[mi][ni][3])
                        : "r"(af[mi][0]), "r"(af[mi][1]),
                          "r"(af[mi][2]), "r"(af[mi][3]),
                        "r"(b0), "r"(b1));
            }
        }
    }
#undef LOAD_STAGE

    // epilogue: thread's cols are the contiguous strip colb..colb+15
    // strip index s: s<8 -> acc[mi][s][0/2]; s>=8 -> acc[mi][s-8][1/3]
    int colb = n0 + wn * 64 + 16 * t4;
    float4 bv[4];
#pragma unroll
    for (int q2 = 0; q2 < 4; q2++)
        bv[q2] = bias ? *(const float4*)(bias + colb + 4 * q2)
                      : make_float4(0.f, 0.f, 0.f, 0.f);

#pragma unroll
    for (int mi = 0; mi < 2; mi++) {
        int row0 = m0 + wm * 32 + mi * 16 + g;
#pragma unroll
        for (int h = 0; h < 2; h++) {
            int row = row0 + h * 8;
            if (row < M) {
                size_t base = (size_t)row * N + colb;
#pragma unroll
                for (int q2 = 0; q2 < 4; q2++) {
                    float4 o;
                    float* s0 = &o.x;
                    // strip values s = 4*q2 .. 4*q2+3
#pragma unroll
                    for (int e = 0; e < 4; e++) {
                        int s = 4 * q2 + e;
                        float v = (s < 8) ? acc[mi][s][h ? 2 : 0]
                                          : acc[mi][s - 8][h ? 3 : 1];
                        s0[e] = v;
                    }
                    float4 rv = res ? *(const float4*)(res + base + 4 * q2)
                                    : make_float4(0.f, 0.f, 0.f, 0.f);
                    const float* bb = &bv[q2].x;
                    o.x += bb[0] + rv.x; o.y += bb[1] + rv.y;
                    o.z += bb[2] + rv.z; o.w += bb[3] + rv.w;
                    *(float4*)(C + base + 4 * q2) = o;
                }
            }
        }
    }
}

// ---------------------------------------------------------------------------
// Weight packing kernels (RNA tf32 rounding)
// ---------------------------------------------------------------------------
__global__ void pack3(const float* __restrict__ s0, const float* __restrict__ s1,
                      const float* __restrict__ s2, float* __restrict__ dst,
                      int K, int N)
{
    int idx = (blockIdx.x * 256 + threadIdx.x) * 4;
    if (idx >= K * N) return;
    int k = idx / N, n = idx - k * N;
    size_t dbase = (size_t)k * 3 * N + n;
    float4 v;
    v = *(const float4*)(s0 + idx);
    v.x = tf32r(v.x); v.y = tf32r(v.y); v.z = tf32r(v.z); v.w = tf32r(v.w);
    *(float4*)(dst + dbase) = v;
    v = *(const float4*)(s1 + idx);
    v.x = tf32r(v.x); v.y = tf32r(v.y); v.z = tf32r(v.z); v.w = tf32r(v.w);
    *(float4*)(dst + dbase + N) = v;
    v = *(const float4*)(s2 + idx);
    v.x = tf32r(v.x); v.y = tf32r(v.y); v.z = tf32r(v.z); v.w = tf32r(v.w);
    *(float4*)(dst + dbase + 2 * N) = v;
}

__global__ void pack2(const float* __restrict__ s0, const float* __restrict__ s1,
                      float* __restrict__ dst, int K, int N)
{
    int idx = (blockIdx.x * 256 + threadIdx.x) * 4;
    if (idx >= K * N) return;
    int k = idx / N, n = idx - k * N;
    size_t dbase = (size_t)k * 2 * N + n;
    float4 v;
    v = *(const float4*)(s0 + idx);
    v.x = tf32r(v.x); v.y = tf32r(v.y); v.z = tf32r(v.z); v.w = tf32r(v.w);
    *(float4*)(dst + dbase) = v;
    v = *(const float4*)(s1 + idx);
    v.x = tf32r(v.x); v.y = tf32r(v.y); v.z = tf32r(v.z); v.w = tf32r(v.w);
    *(float4*)(dst + dbase + N) = v;
}

__global__ void round_copy(const float* __restrict__ in, float* __restrict__ out, int n)
{
    int i = (blockIdx.x * 256 + threadIdx.x) * 4;
    if (i < n) {
        float4 v = *(const float4*)(in + i);
        v.x = tf32r(v.x); v.y = tf32r(v.y); v.z = tf32r(v.z); v.w = tf32r(v.w);
        *(float4*)(out + i) = v;
    }
}

// ---------------------------------------------------------------------------
// LayerNorm (output RNA-rounded to tf32 — it only feeds GEMM A operands)
// ---------------------------------------------------------------------------
__global__ __launch_bounds__(128)
void ln_kernel(const float* __restrict__ x, const float* __restrict__ w,
               const float* __restrict__ b, float* __restrict__ y)
{
    int row = blockIdx.x;
    const float* xr = x + (size_t)row * DIMC;
    float*       yr = y + (size_t)row * DIMC;
    int tid = threadIdx.x;

    float v[10];
    float s = 0.f, ss = 0.f;
#pragma unroll
    for (int i = 0; i < 10; i++) {
        float t = xr[tid + i*128];
        v[i] = t; s += t; ss += t*t;
    }
#pragma unroll
    for (int off = 16; off; off >>= 1) {
        s  += __shfl_xor_sync(0xffffffffu, s,  off);
        ss += __shfl_xor_sync(0xffffffffu, ss, off);
    }
    __shared__ float sh[8];
    int warp = tid >> 5;
    if ((tid & 31) == 0) { sh[warp] = s; sh[4+warp] = ss; }
    __syncthreads();
    s  = sh[0] + sh[1] + sh[2] + sh[3];
    ss = sh[4] + sh[5] + sh[6] + sh[7];
    float mean = s * (1.f/1280.f);
    float var  = ss * (1.f/1280.f) - mean*mean;
    float rstd = rsqrtf(var + 1e-5f);
#pragma unroll
    for (int i = 0; i < 10; i++) {
        int c = tid + i*128;
        yr[c] = tf32r((v[i] - mean) * rstd * w[c] + b[c]);
    }
}

// ---------------------------------------------------------------------------
// Fused attention (fp32, online softmax) with explicit row strides.
// Output RNA-rounded (feeds GEMM A).
// ---------------------------------------------------------------------------
__global__ __launch_bounds__(256)
void attn_kernel(const float* __restrict__ Q, const float* __restrict__ K,
                 const float* __restrict__ V, float* __restrict__ O,
                 int Sq, int Sk, long q_bs, long kv_bs, long o_bs,
                 int ldq, int ldkv, int ldo, int sparse, float scale)
{
    __shared__ float Ks[32][160];
    __shared__ float Vs[32][160];

    int batch = blockIdx.z, head = blockIdx.y;
    int q0  = blockIdx.x * 64;
    int tid = threadIdx.x;
    int r   = tid >> 2, c4 = tid & 3;
    int d0  = c4 * 40;
    bool rowvalid = (q0 + r) < Sq;

    float qv[40];
    {
        int rr = rowvalid ? r : 0;
        const float* qp = Q + (size_t)batch * q_bs
                            + (size_t)(q0 + rr) * ldq + head * DH + d0;
#pragma unroll
        for (int i = 0; i < 40; i++) qv[i] = rowvalid ? qp[i] : 0.f;
    }

    float o[40];
#pragma unroll
    for (int i = 0; i < 40; i++) o[i] = 0.f;
    float m = -1e30f, l = 0.f;

    int lr = tid >> 3;
    int lc = (tid & 7) * 20;

    int ntiles = (Sk + 31) >> 5;
    for (int kt = 0; kt < ntiles; kt++) {
        int j = kt * 32 + lr;
        {
            const float* kp = nullptr;
            const float* vp = nullptr;
            if (j < Sk) {
                size_t off;
                if (sparse) {
                    int bb = batch >> 4, f = batch & 15;
                    int srcf = (j < 256) ? 0 : ((f > 0) ? (f - 1) : 0);
                    int jr2  = (j < 256) ? j : (j - 256);
                    off = (size_t)((bb*16 + srcf) * 256 + jr2) * ldkv
                        + head * DH + lc;
                } else {
                    off = (size_t)batch * kv_bs + (size_t)j * ldkv
                        + head * DH + lc;
                }
                kp = K + off; vp = V + off;
            }
#pragma unroll
            for (int i = 0; i < 5; i++) {
                float4 kx = kp ? *(const float4*)(kp + i*4)
                               : make_float4(0,0,0,0);
                float4 vx = vp ? *(const float4*)(vp + i*4)
                               : make_float4(0,0,0,0);
                *(float4*)&Ks[lr][lc + i*4] = kx;
                *(float4*)&Vs[lr][lc + i*4] = vx;
            }
        }
        __syncthreads();

#pragma unroll
        for (int jc = 0; jc < 2; jc++) {
            int jb = jc * 16;
            if (kt*32 + jb < Sk) {
                float p[16];
#pragma unroll
                for (int jj = 0; jj < 16; jj++) {
                    const float4* kr = (const float4*)&Ks[jb + jj][d0];
                    float s0 = 0.f, s1 = 0.f, s2 = 0.f, s3 = 0.f;
#pragma unroll
                    for (int i = 0; i < 10; i++) {
                        float4 k4 = kr[i];
                        s0 += qv[i*4+0]*k4.x; s1 += qv[i*4+1]*k4.y;
                        s2 += qv[i*4+2]*k4.z; s3 += qv[i*4+3]*k4.w;
                    }
                    p[jj] = (s0 + s1) + (s2 + s3);
                }
#pragma unroll
                for (int jj = 0; jj < 16; jj++) {
                    p[jj] += __shfl_xor_sync(0xffffffffu, p[jj], 1);
                    p[jj] += __shfl_xor_sync(0xffffffffu, p[jj], 2);
                    int jg = kt*32 + jb + jj;
                    p[jj] = (jg < Sk) ? p[jj] * scale : -1e30f;
                }
                float mt = m;
#pragma unroll
                for (int jj = 0; jj < 16; jj++) mt = fmaxf(mt, p[jj]);
                if (mt > m) {
                    float sc = __expf(m - mt);
                    l *= sc;
#pragma unroll
                    for (int i = 0; i < 40; i++) o[i] *= sc;
                    m = mt;
                }
#pragma unroll
                for (int jj = 0; jj < 16; jj++) {
                    float e = __expf(p[jj] - m);
                    l += e;
                    const float4* vr = (const float4*)&Vs[jb + jj][d0];
#pragma unroll
                    for (int i = 0; i < 10; i++) {
                        float4 v4 = vr[i];
                        o[i*4+0] += e * v4.x; o[i*4+1] += e * v4.y;
                        o[i*4+2] += e * v4.z; o[i*4+3] += e * v4.w;
                    }
                }
            }
        }
        __syncthreads();
    }

    if (rowvalid) {
        float inv = 1.f / l;
        float* op = O + (size_t)batch * o_bs
                      + (size_t)(q0 + r) * ldo + head * DH + d0;
#pragma unroll
        for (int i = 0; i < 40; i++) op[i] = tf32r(o[i] * inv);
    }
}

// ---------------------------------------------------------------------------
// GEGLU (output RNA-rounded — feeds ffw2 GEMM A)
// ---------------------------------------------------------------------------
__global__ void geglu_kernel(const float* __restrict__ in, float* __restrict__ out)
{
    size_t idx = (size_t)blockIdx.x * blockDim.x + threadIdx.x;
    if (idx >= (size_t)NROWS * FF_I) return;
    size_t rr = idx / FF_I;
    int    i  = (int)(idx - rr * FF_I);
    const float* row = in + rr * FF_N;
    float p = row[i];
    float g = row[FF_I + i];
    float gel = 0.5f * g * (1.f + erff(g * 0.70710678118654752f));
    out[idx] = tf32r(p * gel);
}

// ---------------------------------------------------------------------------
// Temporal reshape transposes
// ---------------------------------------------------------------------------
__global__ void transpose_fwd(const float* __restrict__ in, float* __restrict__ out)
{
    size_t idx = (size_t)blockIdx.x * blockDim.x + threadIdx.x;
    if (idx >= (size_t)NROWS * DIMC) return;
    int c   = (int)(idx % DIMC);
    int row = (int)(idx / DIMC);
    int f   = row & 15;
    int tok = (row >> 4) & 255;
    int b   = row >> 12;
    out[idx] = in[((size_t)((b*16 + f)*256 + tok)) * DIMC + c];
}

__global__ void transpose_bwd(const float* __restrict__ in, float* __restrict__ out)
{
    size_t idx = (size_t)blockIdx.x * blockDim.x + threadIdx.x;
    if (idx >= (size_t)NROWS * DIMC) return;
    int c   = (int)(idx % DIMC);
    int row = (int)(idx / DIMC);
    int tok = row & 255;
    int f   = (row >> 8) & 15;
    int b   = row >> 12;
    out[idx] = in[((size_t)((b*256 + tok)*16 + f)) * DIMC + c];
}

// ---------------------------------------------------------------------------
// Host launcher
// ---------------------------------------------------------------------------
static void launch_gemm(const float* A, const float* B, float* C,
                        const float* bias, const float* res,
                        int M, int N, int K)
{
    static bool attr_set = false;
    if (!attr_set) {
        cudaFuncSetAttribute(gemm_tf32v5,
            cudaFuncAttributeMaxDynamicSharedMemorySize, GEMM_SMEM);
        attr_set = true;
    }
    int nm = (M + 127) / 128, nn = N / 128;
    gemm_tf32v5<<<nm * nn, 256, GEMM_SMEM>>>(A, B, C, bias, res, M, N, K);
}

static void launch_round(const float* in, float* out, int n)
{
    round_copy<<<(n/4 + 255) / 256, 256>>>(in, out, n);
}

extern "C" void kernel_launch(void* const* d_in, const int* in_sizes, int n_in,
                              void* d_out, int out_size)
{
    const float* hid  = (const float*)d_in[0];
    const float* enc  = (const float*)d_in[1];
    const float* n1w  = (const float*)d_in[2];
    const float* n1b  = (const float*)d_in[3];
    const float* a1wq = (const float*)d_in[4];
    const float* a1wk = (const float*)d_in[5];
    const float* a1wv = (const float*)d_in[6];
    const float* a1wo = (const float*)d_in[7];
    const float* a1bo = (const float*)d_in[8];
    const float* n2w  = (const float*)d_in[9];
    const float* n2b  = (const float*)d_in[10];
    const float* a2wq = (const float*)d_in[11];
    const float* a2wk = (const float*)d_in[12];
    const float* a2wv = (const float*)d_in[13];
    const float* a2wo = (const float*)d_in[14];
    const float* a2bo = (const float*)d_in[15];
    const float* n3w  = (const float*)d_in[16];
    const float* n3b  = (const float*)d_in[17];
    const float* ffw1 = (const float*)d_in[18];
    const float* ffb1 = (const float*)d_in[19];
    const float* ffw2 = (const float*)d_in[20];
    const float* ffb2 = (const float*)d_in[21];
    const float* ntw  = (const float*)d_in[22];
    const float* ntb  = (const float*)d_in[23];
    const float* atwq = (const float*)d_in[24];
    const float* atwk = (const float*)d_in[25];
    const float* atwv = (const float*)d_in[26];
    const float* atwo = (const float*)d_in[27];
    const float* atbo = (const float*)d_in[28];

    float* out = (float*)d_out;

    float *nh, *q, *ao, *ht, *ff1, *gg, *encr, *wt;
    cudaGetSymbolAddress((void**)&nh,  g_nh);
    cudaGetSymbolAddress((void**)&q,   g_q);
    cudaGetSymbolAddress((void**)&ao,  g_ao);
    cudaGetSymbolAddress((void**)&ht,  g_ht);
    cudaGetSymbolAddress((void**)&ff1, g_ff1);
    cudaGetSymbolAddress((void**)&gg,  g_gg);
    cudaGetSymbolAddress((void**)&encr,g_encr);
    cudaGetSymbolAddress((void**)&wt,  g_wt);

    const float scale = 0.07905694150420949f;   // 160^-0.5

    // ---- one-time packing/rounding of B operands ----
    {
        int n1 = DIMC * DIMC;     // 1,638,400
        pack3<<<(n1/4 + 255) / 256, 256>>>(a1wq, a1wk, a1wv, wt + OFF_W1QKV, DIMC, DIMC);
        pack3<<<(n1/4 + 255) / 256, 256>>>(atwq, atwk, atwv, wt + OFF_WTQKV, DIMC, DIMC);
        int n2 = CROSS * DIMC;    // 983,040
        pack2<<<(n2/4 + 255) / 256, 256>>>(a2wk, a2wv, wt + OFF_W2KV, CROSS, DIMC);
        launch_round(a1wo, wt + OFF_A1WO, n1);
        launch_round(a2wq, wt + OFF_A2WQ, n1);
        launch_round(a2wo, wt + OFF_A2WO, n1);
        launch_round(ffw1, wt + OFF_FFW1, DIMC*FF_N);
        launch_round(ffw2, wt + OFF_FFW2, FF_I*DIMC);
        launch_round(atwo, wt + OFF_ATWO, n1);
        launch_round(enc,  encr,          ENCROWS*CROSS);
    }

    const int QKV = 3 * DIMC;     // 3840
    const int KV2 = 2 * DIMC;     // 2560

    // ---- attn1: sparse-causal self-attention ----
    ln_kernel<<<NROWS, 128>>>(hid, n1w, n1b, nh);
    launch_gemm(nh, wt + OFF_W1QKV, ff1, nullptr, nullptr, NROWS, QKV, DIMC);
    attn_kernel<<<dim3(4, HEADS, BF), 256>>>(
        ff1, ff1 + DIMC, ff1 + 2*DIMC, ao,
        TOK, 2*TOK, (long)TOK*QKV, 0, (long)TOK*DIMC,
        QKV, QKV, DIMC, 1, scale);
    launch_gemm(ao, wt + OFF_A1WO, out, a1bo, hid, NROWS, DIMC, DIMC);

    // ---- attn2: cross-attention ----
    ln_kernel<<<NROWS, 128>>>(out, n2w, n2b, nh);
    launch_gemm(nh,   wt + OFF_A2WQ, q,  nullptr, nullptr, NROWS,   DIMC, DIMC);
    launch_gemm(encr, wt + OFF_W2KV, gg, nullptr, nullptr, ENCROWS, KV2,  CROSS);
    attn_kernel<<<dim3(4, HEADS, BF), 256>>>(
        q, gg, gg + DIMC, ao,
        TOK, ESEQ, (long)TOK*DIMC, (long)ESEQ*KV2, (long)TOK*DIMC,
        DIMC, KV2, DIMC, 0, scale);
    launch_gemm(ao, wt + OFF_A2WO, out, a2bo, out, NROWS, DIMC, DIMC);

    // ---- geglu FFN ----
    ln_kernel<<<NROWS, 128>>>(out, n3w, n3b, nh);
    launch_gemm(nh, wt + OFF_FFW1, ff1, ffb1, nullptr, NROWS, FF_N, DIMC);
    {
        size_t tot = (size_t)NROWS * FF_I;
        geglu_kernel<<<(unsigned)((tot + 255) / 256), 256>>>(ff1, gg);
    }
    launch_gemm(gg, wt + OFF_FFW2, out, ffb2, out, NROWS, DIMC, FF_I);

    // ---- temporal self-attention ----
    {
        size_t tot = (size_t)NROWS * DIMC;
        transpose_fwd<<<(unsigned)((tot + 255) / 256), 256>>>(out, ht);
    }
    ln_kernel<<<NROWS, 128>>>(ht, ntw, ntb, nh);
    launch_gemm(nh, wt + OFF_WTQKV, ff1, nullptr, nullptr, NROWS, QKV, DIMC);
    attn_kernel<<<dim3(1, HEADS, 2*TOK), 256>>>(
        ff1, ff1 + DIMC, ff1 + 2*DIMC, ao,
        FRAMES, FRAMES, (long)FRAMES*QKV, (long)FRAMES*QKV, (long)FRAMES*DIMC,
        QKV, QKV, DIMC, 0, scale);
    launch_gemm(ao, wt + OFF_ATWO, ht, atbo, ht, NROWS, DIMC, DIMC);
    {
        size_t tot = (size_t)NROWS * DIMC;
        transpose_bwd<<<(unsigned)((tot + 255) / 256), 256>>>(ht, out);
    }
}

// round 13
// speedup vs baseline: 1.7787x; 1.3138x over previous
#include <cuda_runtime.h>
#include <cuda_fp16.h>
#include <cstdint>
#include <math.h>

// ---------------------------------------------------------------------------
// Problem constants
// ---------------------------------------------------------------------------
#define BF      32
#define TOK     256
#define DIMC    1280
#define HEADS   8
#define DH      160
#define CROSS   768
#define ESEQ    77
#define FRAMES  16
#define NROWS   (BF*TOK)          // 8192
#define ENCROWS (BF*ESEQ)         // 2464
#define FF_N    (2*4*DIMC)        // 10240
#define FF_I    (4*DIMC)          // 5120

// ---------------------------------------------------------------------------
// Scratch (device globals; no allocation allowed)
// ---------------------------------------------------------------------------
__device__ __align__(256) __half g_nh_h [NROWS*DIMC];
__device__ __align__(256) __half g_ao_h [NROWS*DIMC];
__device__ __align__(256) __half g_gg_h [(size_t)NROWS*FF_I];
__device__ __align__(256) __half g_enc_h[ENCROWS*CROSS];
__device__ float g_q  [NROWS*DIMC];
__device__ float g_ht [NROWS*DIMC];
__device__ float g_ff1[(size_t)NROWS*FF_N];   // QKV / ffn1 outputs (fp32)
__device__ float g_kv [ENCROWS*2*DIMC];       // enc K|V (fp32)
__device__ __align__(256) uint32_t g_wt[19005440];  // half2 k-pair-interleaved weights

// packed-weight offsets (uint32 = half2 units), layout [K/2][N]
#define OFF_W1QKV 0u          // [640, 3840]
#define OFF_A1WO  2457600u    // [640, 1280]
#define OFF_A2WQ  3276800u
#define OFF_W2KV  4096000u    // [384, 2560]
#define OFF_A2WO  5079040u
#define OFF_FFW1  5898240u    // [640, 10240]
#define OFF_FFW2  12451840u   // [2560, 1280]
#define OFF_WTQKV 15728640u   // [640, 3840]
#define OFF_ATWO  18186240u

// ---------------------------------------------------------------------------
// Helpers
// ---------------------------------------------------------------------------
__device__ __forceinline__ uint32_t smem_u32(const void* p) {
    uint32_t a;
    asm("{ .reg .u64 t; cvta.to.shared.u64 t, %1; cvt.u32.u64 %0, t; }" : "=r"(a) : "l"(p));
    return a;
}

#define CPASYNC16(dst, src, sz) \
    asm volatile("cp.async.cg.shared.global [%0], [%1], 16, %2;" \
        :: "r"((uint32_t)(dst)), "l"(src), "r"((uint32_t)(sz)) : "memory")
#define CP_COMMIT() asm volatile("cp.async.commit_group;" ::: "memory")
#define CP_WAIT(n)  asm volatile("cp.async.wait_group %0;" :: "n"(n) : "memory")

// ---------------------------------------------------------------------------
// fp16 GEMM v6b: C[M,N] = A[M,K] @ B[K,N] (+bias[N]) (+res[M,N]), fp32 accum
// CTA tile 128x128x32, 8 warps (4m x 2n), warp tile 32x64, m16n8k16 f16 mma.
// A: __half row-major. B: half2 k-pair-interleaved [K/2][N] (uint32).
// 4-stage cp.async pipeline; 2 CTAs/SM; ldmatrix.x4 A frags; rotated B rows.
// Requirements: K % 32 == 0, N % 128 == 0; M ragged OK.
// ---------------------------------------------------------------------------
#define STAGES        4
#define A_STG_BYTES   10240      // 128 rows * 80B (32 halves padded to 40)
#define B_STG_BYTES   8192       // 16 pair-rows * 512B
#define GEMM_SMEM     (STAGES*(A_STG_BYTES+B_STG_BYTES))  // 73728

__global__ void __launch_bounds__(256, 2)
gemm_f16(const __half* __restrict__ A, const uint32_t* __restrict__ B2,
         float* __restrict__ C, const float* __restrict__ bias,
         const float* __restrict__ res, int M, int N, int K)
{
    extern __shared__ __align__(16) char smem[];
    uint32_t aBase = smem_u32(smem);
    uint32_t bBase = aBase + STAGES * A_STG_BYTES;

    int tid  = threadIdx.x;
    int warp = tid >> 5, lane = tid & 31;
    int wm = warp & 3, wn = warp >> 2;
    int g  = lane >> 2, t4 = lane & 3;

    // tile raster (GM groups along M for L2 reuse of B strips)
    int num_m = (M + 127) >> 7, num_n = N >> 7;
    const int GM = 8;
    int npg = GM * num_n;
    int group = blockIdx.x / npg;
    int first = group * GM;
    int gsz = min(num_m - first, GM);
    int rem = blockIdx.x - group * npg;
    int m0 = (first + rem % gsz) << 7;
    int n0 = (rem / gsz) << 7;

    // ---- gmem load mapping ----
    // A: thread -> row tid&127, col-group tid>>7 (16 halves = 32B, 2x16B)
    int arow = tid & 127, acg = tid >> 7;
    bool aval = (m0 + arow) < M;
    const __half* aptr = A + (size_t)(m0 + arow) * K + acg * 16;
    uint32_t aDst = aBase + arow * 80 + acg * 32;
    // B: thread -> pair-row tid>>4, chunks {tid&15, (tid&15)+16} (16B = 4 half2)
    int bp = tid >> 4, bc = tid & 15;
    int Rb = (bp & 1) + 4 * ((bp >> 1) & 1);
    const uint32_t* bptr = B2 + (size_t)bp * N + n0 + bc * 4;
    uint32_t bD0 = bBase + bp * 512 + ((bc + Rb) & 31) * 16;
    uint32_t bD1 = bBase + bp * 512 + ((bc + 16 + Rb) & 31) * 16;

    // A ldmatrix per-lane byte offset (row pad 40 halves = 80B)
    uint32_t aFrag = ((wm * 32 + (lane & 15)) * 40 + (lane >> 4) * 8) * 2;
    // B fragment rotation/chunks (BUGFIX: include warp n-offset 16*wn)
    int Rf  = (t4 & 1) + 4 * ((t4 >> 1) & 1);
    int pc0 = ((16 * wn + 2 * g + Rf) & 31) * 16;
    int pc1 = ((16 * wn + 2 * g + 1 + Rf) & 31) * 16;

    float acc[2][8][4];
#pragma unroll
    for (int mi = 0; mi < 2; mi++)
#pragma unroll
        for (int ni = 0; ni < 8; ni++)
#pragma unroll
            for (int i = 0; i < 4; i++) acc[mi][ni][i] = 0.f;

    int KT = K >> 5;

#define LOAD_STAGE(kt, s)                                                     \
    do {                                                                      \
        const __half* _a = aptr + (size_t)(kt) * 32;                          \
        uint32_t _ad = aDst + (s) * A_STG_BYTES;                              \
        unsigned _sz = aval ? 16u : 0u;                                       \
        CPASYNC16(_ad,      _a,     _sz);                                     \
        CPASYNC16(_ad + 16, _a + 8, _sz);                                     \
        const uint32_t* _b = bptr + (size_t)(kt) * 16 * N;                    \
        CPASYNC16(bD0 + (s) * B_STG_BYTES, _b,      16u);                     \
        CPASYNC16(bD1 + (s) * B_STG_BYTES, _b + 64, 16u);                     \
    } while (0)

#pragma unroll
    for (int s = 0; s < STAGES - 1; s++) {
        if (s < KT) LOAD_STAGE(s, s);
        CP_COMMIT();
    }

    for (int kt = 0; kt < KT; kt++) {
        CP_WAIT(STAGES - 2);
        __syncthreads();

        int nk = kt + STAGES - 1;
        if (nk < KT) LOAD_STAGE(nk, nk % STAGES);
        CP_COMMIT();

        uint32_t astage = aBase + (kt % STAGES) * A_STG_BYTES + aFrag;
        uint32_t bstage = bBase + (kt % STAGES) * B_STG_BYTES;

#pragma unroll
        for (int ks = 0; ks < 2; ks++) {
            uint32_t af[2][4];
#pragma unroll
            for (int mi = 0; mi < 2; mi++) {
                uint32_t addr = astage + mi * (16 * 80) + ks * 32;
                asm volatile(
                    "ldmatrix.sync.aligned.m8n8.x4.shared.b16 {%0,%1,%2,%3}, [%4];"
                    : "=r"(af[mi][0]), "=r"(af[mi][1]),
                      "=r"(af[mi][2]), "=r"(af[mi][3])
                    : "r"(addr));
            }
            uint32_t r0 = bstage + (8 * ks + t4) * 512;
            uint32_t r1 = r0 + 2048;
            uint4 B00, B01, B10, B11;
            asm volatile("ld.shared.v4.b32 {%0,%1,%2,%3}, [%4];"
                : "=r"(B00.x), "=r"(B00.y), "=r"(B00.z), "=r"(B00.w) : "r"(r0 + pc0));
            asm volatile("ld.shared.v4.b32 {%0,%1,%2,%3}, [%4];"
                : "=r"(B01.x), "=r"(B01.y), "=r"(B01.z), "=r"(B01.w) : "r"(r0 + pc1));
            asm volatile("ld.shared.v4.b32 {%0,%1,%2,%3}, [%4];"
                : "=r"(B10.x), "=r"(B10.y), "=r"(B10.z), "=r"(B10.w) : "r"(r1 + pc0));
            asm volatile("ld.shared.v4.b32 {%0,%1,%2,%3}, [%4];"
                : "=r"(B11.x), "=r"(B11.y), "=r"(B11.z), "=r"(B11.w) : "r"(r1 + pc1));
            uint32_t b0a[8] = {B00.x, B00.y, B00.z, B00.w, B01.x, B01.y, B01.z, B01.w};
            uint32_t b1a[8] = {B10.x, B10.y, B10.z, B10.w, B11.x, B11.y, B11.z, B11.w};
#pragma unroll
            for (int ni = 0; ni < 8; ni++) {
#pragma unroll
                for (int mi = 0; mi < 2; mi++)
                    asm volatile(
                        "mma.sync.aligned.m16n8k16.row.col.f32.f16.f16.f32 "
                        "{%0,%1,%2,%3}, {%4,%5,%6,%7}, {%8,%9}, {%0,%1,%2,%3};"
                        : "+f"(acc[mi][ni][0]), "+f"(acc[mi][ni][1]),
                          "+f"(acc[mi][ni][2]), "+f"(acc[mi][ni][3])
                        : "r"(af[mi][0]), "r"(af[mi][1]),
                          "r"(af[mi][2]), "r"(af[mi][3]),
                          "r"(b0a[ni]), "r"(b1a[ni]));
            }
        }
    }
#undef LOAD_STAGE

    // epilogue: thread's cols are the contiguous strip colb..colb+15
    int colb = n0 + wn * 64 + 16 * t4;
    float4 bv[4];
#pragma unroll
    for (int q2 = 0; q2 < 4; q2++)
        bv[q2] = bias ? *(const float4*)(bias + colb + 4 * q2)
                      : make_float4(0.f, 0.f, 0.f, 0.f);

#pragma unroll
    for (int mi = 0; mi < 2; mi++) {
        int row0 = m0 + wm * 32 + mi * 16 + g;
#pragma unroll
        for (int h = 0; h < 2; h++) {
            int row = row0 + h * 8;
            if (row < M) {
                size_t base = (size_t)row * N + colb;
#pragma unroll
                for (int q2 = 0; q2 < 4; q2++) {
                    float4 o;
                    float* s0 = &o.x;
#pragma unroll
                    for (int e = 0; e < 4; e++) {
                        int s = 4 * q2 + e;
                        float v = (s < 8) ? acc[mi][s][h ? 2 : 0]
                                          : acc[mi][s - 8][h ? 3 : 1];
                        s0[e] = v;
                    }
                    float4 rv = res ? *(const float4*)(res + base + 4 * q2)
                                    : make_float4(0.f, 0.f, 0.f, 0.f);
                    const float* bb = &bv[q2].x;
                    o.x += bb[0] + rv.x; o.y += bb[1] + rv.y;
                    o.z += bb[2] + rv.z; o.w += bb[3] + rv.w;
                    *(float4*)(C + base + 4 * q2) = o;
                }
            }
        }
    }
}

// ---------------------------------------------------------------------------
// Weight packing: [K][N] fp32 -> [K/2][N] half2 (k-pair interleaved)
// ---------------------------------------------------------------------------
__global__ void packh(const float* __restrict__ src, uint32_t* __restrict__ dst,
                      int K, int N, int dstride, int coff)
{
    int total = (K >> 1) * (N >> 2);
    int idx = blockIdx.x * 256 + threadIdx.x;
    if (idx >= total) return;
    int npc = N >> 2;
    int kp = idx / npc, n4 = (idx - kp * npc) * 4;
    const float* r0 = src + (size_t)(2 * kp) * N + n4;
    const float* r1 = r0 + N;
    float4 lo = *(const float4*)r0, hi = *(const float4*)r1;
    __half2 h0 = __floats2half2_rn(lo.x, hi.x);
    __half2 h1 = __floats2half2_rn(lo.y, hi.y);
    __half2 h2 = __floats2half2_rn(lo.z, hi.z);
    __half2 h3 = __floats2half2_rn(lo.w, hi.w);
    uint4 o;
    o.x = *reinterpret_cast<uint32_t*>(&h0);
    o.y = *reinterpret_cast<uint32_t*>(&h1);
    o.z = *reinterpret_cast<uint32_t*>(&h2);
    o.w = *reinterpret_cast<uint32_t*>(&h3);
    *(uint4*)(dst + (size_t)kp * dstride + coff + n4) = o;
}

// fp32 -> fp16 copy (enc)
__global__ void f2h(const float* __restrict__ in, __half* __restrict__ out, int n)
{
    int i = (blockIdx.x * 256 + threadIdx.x) * 8;
    if (i >= n) return;
    float4 a = *(const float4*)(in + i);
    float4 b = *(const float4*)(in + i + 4);
    __half2 h0 = __floats2half2_rn(a.x, a.y);
    __half2 h1 = __floats2half2_rn(a.z, a.w);
    __half2 h2 = __floats2half2_rn(b.x, b.y);
    __half2 h3 = __floats2half2_rn(b.z, b.w);
    uint4 o;
    o.x = *reinterpret_cast<uint32_t*>(&h0);
    o.y = *reinterpret_cast<uint32_t*>(&h1);
    o.z = *reinterpret_cast<uint32_t*>(&h2);
    o.w = *reinterpret_cast<uint32_t*>(&h3);
    *(uint4*)(out + i) = o;
}

// ---------------------------------------------------------------------------
// LayerNorm (fp32 in, fp16 out — feeds GEMM A operands only)
// ---------------------------------------------------------------------------
__global__ __launch_bounds__(128)
void ln_kernel(const float* __restrict__ x, const float* __restrict__ w,
               const float* __restrict__ b, __half* __restrict__ y)
{
    int row = blockIdx.x;
    const float* xr = x + (size_t)row * DIMC;
    __half*      yr = y + (size_t)row * DIMC;
    int tid = threadIdx.x;

    float v[10];
    float s = 0.f, ss = 0.f;
#pragma unroll
    for (int i = 0; i < 10; i++) {
        float t = xr[tid + i*128];
        v[i] = t; s += t; ss += t*t;
    }
#pragma unroll
    for (int off = 16; off; off >>= 1) {
        s  += __shfl_xor_sync(0xffffffffu, s,  off);
        ss += __shfl_xor_sync(0xffffffffu, ss, off);
    }
    __shared__ float sh[8];
    int warp = tid >> 5;
    if ((tid & 31) == 0) { sh[warp] = s; sh[4+warp] = ss; }
    __syncthreads();
    s  = sh[0] + sh[1] + sh[2] + sh[3];
    ss = sh[4] + sh[5] + sh[6] + sh[7];
    float mean = s * (1.f/1280.f);
    float var  = ss * (1.f/1280.f) - mean*mean;
    float rstd = rsqrtf(var + 1e-5f);
#pragma unroll
    for (int i = 0; i < 10; i++) {
        int c = tid + i*128;
        yr[c] = __float2half_rn((v[i] - mean) * rstd * w[c] + b[c]);
    }
}

// ---------------------------------------------------------------------------
// Fused attention (fp32 math, fp16 output) with explicit row strides.
// ---------------------------------------------------------------------------
__global__ __launch_bounds__(256)
void attn_kernel(const float* __restrict__ Q, const float* __restrict__ K,
                 const float* __restrict__ V, __half* __restrict__ O,
                 int Sq, int Sk, long q_bs, long kv_bs, long o_bs,
                 int ldq, int ldkv, int ldo, int sparse, float scale)
{
    __shared__ float Ks[32][160];
    __shared__ float Vs[32][160];

    int batch = blockIdx.z, head = blockIdx.y;
    int q0  = blockIdx.x * 64;
    int tid = threadIdx.x;
    int r   = tid >> 2, c4 = tid & 3;
    int d0  = c4 * 40;
    bool rowvalid = (q0 + r) < Sq;

    float qv[40];
    {
        int rr = rowvalid ? r : 0;
        const float* qp = Q + (size_t)batch * q_bs
                            + (size_t)(q0 + rr) * ldq + head * DH + d0;
#pragma unroll
        for (int i = 0; i < 40; i++) qv[i] = rowvalid ? qp[i] : 0.f;
    }

    float o[40];
#pragma unroll
    for (int i = 0; i < 40; i++) o[i] = 0.f;
    float m = -1e30f, l = 0.f;

    int lr = tid >> 3;
    int lc = (tid & 7) * 20;

    int ntiles = (Sk + 31) >> 5;
    for (int kt = 0; kt < ntiles; kt++) {
        int j = kt * 32 + lr;
        {
            const float* kp = nullptr;
            const float* vp = nullptr;
            if (j < Sk) {
                size_t off;
                if (sparse) {
                    int bb = batch >> 4, f = batch & 15;
                    int srcf = (j < 256) ? 0 : ((f > 0) ? (f - 1) : 0);
                    int jr2  = (j < 256) ? j : (j - 256);
                    off = (size_t)((bb*16 + srcf) * 256 + jr2) * ldkv
                        + head * DH + lc;
                } else {
                    off = (size_t)batch * kv_bs + (size_t)j * ldkv
                        + head * DH + lc;
                }
                kp = K + off; vp = V + off;
            }
#pragma unroll
            for (int i = 0; i < 5; i++) {
                float4 kx = kp ? *(const float4*)(kp + i*4)
                               : make_float4(0,0,0,0);
                float4 vx = vp ? *(const float4*)(vp + i*4)
                               : make_float4(0,0,0,0);
                *(float4*)&Ks[lr][lc + i*4] = kx;
                *(float4*)&Vs[lr][lc + i*4] = vx;
            }
        }
        __syncthreads();

#pragma unroll
        for (int jc = 0; jc < 2; jc++) {
            int jb = jc * 16;
            if (kt*32 + jb < Sk) {
                float p[16];
#pragma unroll
                for (int jj = 0; jj < 16; jj++) {
                    const float4* kr = (const float4*)&Ks[jb + jj][d0];
                    float s0 = 0.f, s1 = 0.f, s2 = 0.f, s3 = 0.f;
#pragma unroll
                    for (int i = 0; i < 10; i++) {
                        float4 k4 = kr[i];
                        s0 += qv[i*4+0]*k4.x; s1 += qv[i*4+1]*k4.y;
                        s2 += qv[i*4+2]*k4.z; s3 += qv[i*4+3]*k4.w;
                    }
                    p[jj] = (s0 + s1) + (s2 + s3);
                }
#pragma unroll
                for (int jj = 0; jj < 16; jj++) {
                    p[jj] += __shfl_xor_sync(0xffffffffu, p[jj], 1);
                    p[jj] += __shfl_xor_sync(0xffffffffu, p[jj], 2);
                    int jg = kt*32 + jb + jj;
                    p[jj] = (jg < Sk) ? p[jj] * scale : -1e30f;
                }
                float mt = m;
#pragma unroll
                for (int jj = 0; jj < 16; jj++) mt = fmaxf(mt, p[jj]);
                if (mt > m) {
                    float sc = __expf(m - mt);
                    l *= sc;
#pragma unroll
                    for (int i = 0; i < 40; i++) o[i] *= sc;
                    m = mt;
                }
#pragma unroll
                for (int jj = 0; jj < 16; jj++) {
                    float e = __expf(p[jj] - m);
                    l += e;
                    const float4* vr = (const float4*)&Vs[jb + jj][d0];
#pragma unroll
                    for (int i = 0; i < 10; i++) {
                        float4 v4 = vr[i];
                        o[i*4+0] += e * v4.x; o[i*4+1] += e * v4.y;
                        o[i*4+2] += e * v4.z; o[i*4+3] += e * v4.w;
                    }
                }
            }
        }
        __syncthreads();
    }

    if (rowvalid) {
        float inv = 1.f / l;
        __half* op = O + (size_t)batch * o_bs
                       + (size_t)(q0 + r) * ldo + head * DH + d0;
#pragma unroll
        for (int i = 0; i < 40; i++) op[i] = __float2half_rn(o[i] * inv);
    }
}

// ---------------------------------------------------------------------------
// GEGLU (fp32 in, fp16 out — feeds ffw2 GEMM A)
// ---------------------------------------------------------------------------
__global__ void geglu_kernel(const float* __restrict__ in, __half* __restrict__ out)
{
    size_t idx = (size_t)blockIdx.x * blockDim.x + threadIdx.x;
    if (idx >= (size_t)NROWS * FF_I) return;
    size_t rr = idx / FF_I;
    int    i  = (int)(idx - rr * FF_I);
    const float* row = in + rr * FF_N;
    float p = row[i];
    float g = row[FF_I + i];
    float gel = 0.5f * g * (1.f + erff(g * 0.70710678118654752f));
    out[idx] = __float2half_rn(p * gel);
}

// ---------------------------------------------------------------------------
// Temporal reshape transposes (fp32)
// ---------------------------------------------------------------------------
__global__ void transpose_fwd(const float* __restrict__ in, float* __restrict__ out)
{
    size_t idx = (size_t)blockIdx.x * blockDim.x + threadIdx.x;
    if (idx >= (size_t)NROWS * DIMC) return;
    int c   = (int)(idx % DIMC);
    int row = (int)(idx / DIMC);
    int f   = row & 15;
    int tok = (row >> 4) & 255;
    int b   = row >> 12;
    out[idx] = in[((size_t)((b*16 + f)*256 + tok)) * DIMC + c];
}

__global__ void transpose_bwd(const float* __restrict__ in, float* __restrict__ out)
{
    size_t idx = (size_t)blockIdx.x * blockDim.x + threadIdx.x;
    if (idx >= (size_t)NROWS * DIMC) return;
    int c   = (int)(idx % DIMC);
    int row = (int)(idx / DIMC);
    int tok = row & 255;
    int f   = (row >> 8) & 15;
    int b   = row >> 12;
    out[idx] = in[((size_t)((b*256 + tok)*16 + f)) * DIMC + c];
}

// ---------------------------------------------------------------------------
// Host launcher
// ---------------------------------------------------------------------------
static void launch_gemm(const __half* A, const uint32_t* B2, float* C,
                        const float* bias, const float* res,
                        int M, int N, int K)
{
    static bool attr_set = false;
    if (!attr_set) {
        cudaFuncSetAttribute(gemm_f16,
            cudaFuncAttributeMaxDynamicSharedMemorySize, GEMM_SMEM);
        attr_set = true;
    }
    int nm = (M + 127) / 128, nn = N / 128;
    gemm_f16<<<nm * nn, 256, GEMM_SMEM>>>(A, B2, C, bias, res, M, N, K);
}

static void launch_pack(const float* src, uint32_t* dst, int K, int N,
                        int dstride, int coff)
{
    int total = (K / 2) * (N / 4);
    packh<<<(total + 255) / 256, 256>>>(src, dst, K, N, dstride, coff);
}

extern "C" void kernel_launch(void* const* d_in, const int* in_sizes, int n_in,
                              void* d_out, int out_size)
{
    const float* hid  = (const float*)d_in[0];
    const float* enc  = (const float*)d_in[1];
    const float* n1w  = (const float*)d_in[2];
    const float* n1b  = (const float*)d_in[3];
    const float* a1wq = (const float*)d_in[4];
    const float* a1wk = (const float*)d_in[5];
    const float* a1wv = (const float*)d_in[6];
    const float* a1wo = (const float*)d_in[7];
    const float* a1bo = (const float*)d_in[8];
    const float* n2w  = (const float*)d_in[9];
    const float* n2b  = (const float*)d_in[10];
    const float* a2wq = (const float*)d_in[11];
    const float* a2wk = (const float*)d_in[12];
    const float* a2wv = (const float*)d_in[13];
    const float* a2wo = (const float*)d_in[14];
    const float* a2bo = (const float*)d_in[15];
    const float* n3w  = (const float*)d_in[16];
    const float* n3b  = (const float*)d_in[17];
    const float* ffw1 = (const float*)d_in[18];
    const float* ffb1 = (const float*)d_in[19];
    const float* ffw2 = (const float*)d_in[20];
    const float* ffb2 = (const float*)d_in[21];
    const float* ntw  = (const float*)d_in[22];
    const float* ntb  = (const float*)d_in[23];
    const float* atwq = (const float*)d_in[24];
    const float* atwk = (const float*)d_in[25];
    const float* atwv = (const float*)d_in[26];
    const float* atwo = (const float*)d_in[27];
    const float* atbo = (const float*)d_in[28];

    float* out = (float*)d_out;

    __half *nh, *ao, *gg, *ench;
    float *q, *ht, *ff1, *kv;
    uint32_t* wt;
    cudaGetSymbolAddress((void**)&nh,  g_nh_h);
    cudaGetSymbolAddress((void**)&ao,  g_ao_h);
    cudaGetSymbolAddress((void**)&gg,  g_gg_h);
    cudaGetSymbolAddress((void**)&ench,g_enc_h);
    cudaGetSymbolAddress((void**)&q,   g_q);
    cudaGetSymbolAddress((void**)&ht,  g_ht);
    cudaGetSymbolAddress((void**)&ff1, g_ff1);
    cudaGetSymbolAddress((void**)&kv,  g_kv);
    cudaGetSymbolAddress((void**)&wt,  g_wt);

    const float scale = 0.07905694150420949f;   // 160^-0.5

    // ---- one-time weight packing (fp32 -> interleaved half2) ----
    launch_pack(a1wq, wt + OFF_W1QKV, DIMC, DIMC, 3*DIMC, 0);
    launch_pack(a1wk, wt + OFF_W1QKV, DIMC, DIMC, 3*DIMC, DIMC);
    launch_pack(a1wv, wt + OFF_W1QKV, DIMC, DIMC, 3*DIMC, 2*DIMC);
    launch_pack(a1wo, wt + OFF_A1WO,  DIMC, DIMC, DIMC, 0);
    launch_pack(a2wq, wt + OFF_A2WQ,  DIMC, DIMC, DIMC, 0);
    launch_pack(a2wk, wt + OFF_W2KV,  CROSS, DIMC, 2*DIMC, 0);
    launch_pack(a2wv, wt + OFF_W2KV,  CROSS, DIMC, 2*DIMC, DIMC);
    launch_pack(a2wo, wt + OFF_A2WO,  DIMC, DIMC, DIMC, 0);
    launch_pack(ffw1, wt + OFF_FFW1,  DIMC, FF_N, FF_N, 0);
    launch_pack(ffw2, wt + OFF_FFW2,  FF_I, DIMC, DIMC, 0);
    launch_pack(atwq, wt + OFF_WTQKV, DIMC, DIMC, 3*DIMC, 0);
    launch_pack(atwk, wt + OFF_WTQKV, DIMC, DIMC, 3*DIMC, DIMC);
    launch_pack(atwv, wt + OFF_WTQKV, DIMC, DIMC, 3*DIMC, 2*DIMC);
    launch_pack(atwo, wt + OFF_ATWO,  DIMC, DIMC, DIMC, 0);
    f2h<<<(ENCROWS*CROSS/8 + 255) / 256, 256>>>(enc, ench, ENCROWS*CROSS);

    const int QKV = 3 * DIMC;     // 3840
    const int KV2 = 2 * DIMC;     // 2560

    // ---- attn1: sparse-causal self-attention ----
    ln_kernel<<<NROWS, 128>>>(hid, n1w, n1b, nh);
    launch_gemm(nh, wt + OFF_W1QKV, ff1, nullptr, nullptr, NROWS, QKV, DIMC);
    attn_kernel<<<dim3(4, HEADS, BF), 256>>>(
        ff1, ff1 + DIMC, ff1 + 2*DIMC, ao,
        TOK, 2*TOK, (long)TOK*QKV, 0, (long)TOK*DIMC,
        QKV, QKV, DIMC, 1, scale);
    launch_gemm(ao, wt + OFF_A1WO, out, a1bo, hid, NROWS, DIMC, DIMC);

    // ---- attn2: cross-attention ----
    ln_kernel<<<NROWS, 128>>>(out, n2w, n2b, nh);
    launch_gemm(nh,   wt + OFF_A2WQ, q,  nullptr, nullptr, NROWS,   DIMC, DIMC);
    launch_gemm(ench, wt + OFF_W2KV, kv, nullptr, nullptr, ENCROWS, KV2,  CROSS);
    attn_kernel<<<dim3(4, HEADS, BF), 256>>>(
        q, kv, kv + DIMC, ao,
        TOK, ESEQ, (long)TOK*DIMC, (long)ESEQ*KV2, (long)TOK*DIMC,
        DIMC, KV2, DIMC, 0, scale);
    launch_gemm(ao, wt + OFF_A2WO, out, a2bo, out, NROWS, DIMC, DIMC);

    // ---- geglu FFN ----
    ln_kernel<<<NROWS, 128>>>(out, n3w, n3b, nh);
    launch_gemm(nh, wt + OFF_FFW1, ff1, ffb1, nullptr, NROWS, FF_N, DIMC);
    {
        size_t tot = (size_t)NROWS * FF_I;
        geglu_kernel<<<(unsigned)((tot + 255) / 256), 256>>>(ff1, gg);
    }
    launch_gemm(gg, wt + OFF_FFW2, out, ffb2, out, NROWS, DIMC, FF_I);

    // ---- temporal self-attention ----
    {
        size_t tot = (size_t)NROWS * DIMC;
        transpose_fwd<<<(unsigned)((tot + 255) / 256), 256>>>(out, ht);
    }
    ln_kernel<<<NROWS, 128>>>(ht, ntw, ntb, nh);
    launch_gemm(nh, wt + OFF_WTQKV, ff1, nullptr, nullptr, NROWS, QKV, DIMC);
    attn_kernel<<<dim3(1, HEADS, 2*TOK), 256>>>(
        ff1, ff1 + DIMC, ff1 + 2*DIMC, ao,
        FRAMES, FRAMES, (long)FRAMES*QKV, (long)FRAMES*QKV, (long)FRAMES*DIMC,
        QKV, QKV, DIMC, 0, scale);
    launch_gemm(ao, wt + OFF_ATWO, ht, atbo, ht, NROWS, DIMC, DIMC);
    {
        size_t tot = (size_t)NROWS * DIMC;
        transpose_bwd<<<(unsigned)((tot + 255) / 256), 256>>>(ht, out);
    }
}

// round 14
// speedup vs baseline: 1.9568x; 1.1001x over previous
#include <cuda_runtime.h>
#include <cuda_fp16.h>
#include <cstdint>
#include <math.h>

// ---------------------------------------------------------------------------
// Problem constants
// ---------------------------------------------------------------------------
#define BF      32
#define TOK     256
#define DIMC    1280
#define HEADS   8
#define DH      160
#define CROSS   768
#define ESEQ    77
#define FRAMES  16
#define NROWS   (BF*TOK)          // 8192
#define ENCROWS (BF*ESEQ)         // 2464
#define FF_N    (2*4*DIMC)        // 10240
#define FF_I    (4*DIMC)          // 5120

// ---------------------------------------------------------------------------
// Scratch (device globals; no allocation allowed)
// ---------------------------------------------------------------------------
__device__ __align__(256) __half g_nh_h [NROWS*DIMC];
__device__ __align__(256) __half g_ao_h [NROWS*DIMC];
__device__ __align__(256) __half g_qkv_h[(size_t)NROWS*3*DIMC];
__device__ __align__(256) __half g_gg_h [(size_t)NROWS*FF_I];
__device__ __align__(256) __half g_kv_h [ENCROWS*2*DIMC];
__device__ __align__(256) __half g_enc_h[ENCROWS*CROSS];
__device__ float g_ht [NROWS*DIMC];
__device__ float g_biasi[FF_N];
__device__ __align__(256) uint32_t g_wt[19005440];  // half2 k-pair-interleaved weights

// packed-weight offsets (uint32 = half2 units), layout [K/2][N]
#define OFF_W1QKV 0u          // [640, 3840]
#define OFF_A1WO  2457600u    // [640, 1280]
#define OFF_A2WQ  3276800u
#define OFF_W2KV  4096000u    // [384, 2560]
#define OFF_A2WO  5079040u
#define OFF_FFW1  5898240u    // [640, 10240] (p/g column-interleaved)
#define OFF_FFW2  12451840u   // [2560, 1280]
#define OFF_WTQKV 15728640u   // [640, 3840]
#define OFF_ATWO  18186240u

// ---------------------------------------------------------------------------
// Helpers
// ---------------------------------------------------------------------------
__device__ __forceinline__ uint32_t smem_u32(const void* p) {
    uint32_t a;
    asm("{ .reg .u64 t; cvta.to.shared.u64 t, %1; cvt.u32.u64 %0, t; }" : "=r"(a) : "l"(p));
    return a;
}

#define CPASYNC16(dst, src, sz) \
    asm volatile("cp.async.cg.shared.global [%0], [%1], 16, %2;" \
        :: "r"((uint32_t)(dst)), "l"(src), "r"((uint32_t)(sz)) : "memory")
#define CP_COMMIT() asm volatile("cp.async.commit_group;" ::: "memory")
#define CP_WAIT(n)  asm volatile("cp.async.wait_group %0;" :: "n"(n) : "memory")

// ---------------------------------------------------------------------------
// fp16 GEMM v7: C = A[M,K] @ B[K,N], fp32 accum, 3 epilogue modes:
//   MODE 0: C fp32, + bias + res
//   MODE 1: C fp16, plain
//   MODE 2: C fp16 [M, N/2], geglu over interleaved (p,g) pairs, + bias
// CTA tile 128x128x32, 8 warps (4m x 2n), m16n8k16 f16 mma, 4-stage cp.async,
// 2 CTAs/SM, ldmatrix.x4 A frags, rotated B rows, column-permuted MMA tiles.
// Requirements: K % 32 == 0, N % 128 == 0; M ragged OK.
// ---------------------------------------------------------------------------
#define STAGES        4
#define A_STG_BYTES   10240      // 128 rows * 80B (32 halves padded to 40)
#define B_STG_BYTES   8192       // 16 pair-rows * 512B
#define GEMM_SMEM     (STAGES*(A_STG_BYTES+B_STG_BYTES))  // 73728

template<int MODE>
__global__ void __launch_bounds__(256, 2)
gemm_f16(const __half* __restrict__ A, const uint32_t* __restrict__ B2,
         void* __restrict__ Cv, const float* __restrict__ bias,
         const float* __restrict__ res, int M, int N, int K)
{
    extern __shared__ __align__(16) char smem[];
    uint32_t aBase = smem_u32(smem);
    uint32_t bBase = aBase + STAGES * A_STG_BYTES;

    int tid  = threadIdx.x;
    int warp = tid >> 5, lane = tid & 31;
    int wm = warp & 3, wn = warp >> 2;
    int g  = lane >> 2, t4 = lane & 3;

    // tile raster (GM groups along M for L2 reuse of B strips)
    int num_m = (M + 127) >> 7, num_n = N >> 7;
    const int GM = 8;
    int npg = GM * num_n;
    int group = blockIdx.x / npg;
    int first = group * GM;
    int gsz = min(num_m - first, GM);
    int rem = blockIdx.x - group * npg;
    int m0 = (first + rem % gsz) << 7;
    int n0 = (rem / gsz) << 7;

    // ---- gmem load mapping ----
    int arow = tid & 127, acg = tid >> 7;
    bool aval = (m0 + arow) < M;
    const __half* aptr = A + (size_t)(m0 + arow) * K + acg * 16;
    uint32_t aDst = aBase + arow * 80 + acg * 32;
    int bp = tid >> 4, bc = tid & 15;
    int Rb = (bp & 1) + 4 * ((bp >> 1) & 1);
    const uint32_t* bptr = B2 + (size_t)bp * N + n0 + bc * 4;
    uint32_t bD0 = bBase + bp * 512 + ((bc + Rb) & 31) * 16;
    uint32_t bD1 = bBase + bp * 512 + ((bc + 16 + Rb) & 31) * 16;

    uint32_t aFrag = ((wm * 32 + (lane & 15)) * 40 + (lane >> 4) * 8) * 2;
    int Rf  = (t4 & 1) + 4 * ((t4 >> 1) & 1);
    int pc0 = ((16 * wn + 2 * g + Rf) & 31) * 16;
    int pc1 = ((16 * wn + 2 * g + 1 + Rf) & 31) * 16;

    float acc[2][8][4];
#pragma unroll
    for (int mi = 0; mi < 2; mi++)
#pragma unroll
        for (int ni = 0; ni < 8; ni++)
#pragma unroll
            for (int i = 0; i < 4; i++) acc[mi][ni][i] = 0.f;

    int KT = K >> 5;

#define LOAD_STAGE(kt, s)                                                     \
    do {                                                                      \
        const __half* _a = aptr + (size_t)(kt) * 32;                          \
        uint32_t _ad = aDst + (s) * A_STG_BYTES;                              \
        unsigned _sz = aval ? 16u : 0u;                                       \
        CPASYNC16(_ad,      _a,     _sz);                                     \
        CPASYNC16(_ad + 16, _a + 8, _sz);                                     \
        const uint32_t* _b = bptr + (size_t)(kt) * 16 * N;                    \
        CPASYNC16(bD0 + (s) * B_STG_BYTES, _b,      16u);                     \
        CPASYNC16(bD1 + (s) * B_STG_BYTES, _b + 64, 16u);                     \
    } while (0)

#pragma unroll
    for (int s = 0; s < STAGES - 1; s++) {
        if (s < KT) LOAD_STAGE(s, s);
        CP_COMMIT();
    }

    for (int kt = 0; kt < KT; kt++) {
        CP_WAIT(STAGES - 2);
        __syncthreads();

        int nk = kt + STAGES - 1;
        if (nk < KT) LOAD_STAGE(nk, nk % STAGES);
        CP_COMMIT();

        uint32_t astage = aBase + (kt % STAGES) * A_STG_BYTES + aFrag;
        uint32_t bstage = bBase + (kt % STAGES) * B_STG_BYTES;

#pragma unroll
        for (int ks = 0; ks < 2; ks++) {
            uint32_t af[2][4];
#pragma unroll
            for (int mi = 0; mi < 2; mi++) {
                uint32_t addr = astage + mi * (16 * 80) + ks * 32;
                asm volatile(
                    "ldmatrix.sync.aligned.m8n8.x4.shared.b16 {%0,%1,%2,%3}, [%4];"
                    : "=r"(af[mi][0]), "=r"(af[mi][1]),
                      "=r"(af[mi][2]), "=r"(af[mi][3])
                    : "r"(addr));
            }
            uint32_t r0 = bstage + (8 * ks + t4) * 512;
            uint32_t r1 = r0 + 2048;
            uint4 B00, B01, B10, B11;
            asm volatile("ld.shared.v4.b32 {%0,%1,%2,%3}, [%4];"
                : "=r"(B00.x), "=r"(B00.y), "=r"(B00.z), "=r"(B00.w) : "r"(r0 + pc0));
            asm volatile("ld.shared.v4.b32 {%0,%1,%2,%3}, [%4];"
                : "=r"(B01.x), "=r"(B01.y), "=r"(B01.z), "=r"(B01.w) : "r"(r0 + pc1));
            asm volatile("ld.shared.v4.b32 {%0,%1,%2,%3}, [%4];"
                : "=r"(B10.x), "=r"(B10.y), "=r"(B10.z), "=r"(B10.w) : "r"(r1 + pc0));
            asm volatile("ld.shared.v4.b32 {%0,%1,%2,%3}, [%4];"
                : "=r"(B11.x), "=r"(B11.y), "=r"(B11.z), "=r"(B11.w) : "r"(r1 + pc1));
            uint32_t b0a[8] = {B00.x, B00.y, B00.z, B00.w, B01.x, B01.y, B01.z, B01.w};
            uint32_t b1a[8] = {B10.x, B10.y, B10.z, B10.w, B11.x, B11.y, B11.z, B11.w};
#pragma unroll
            for (int ni = 0; ni < 8; ni++) {
#pragma unroll
                for (int mi = 0; mi < 2; mi++)
                    asm volatile(
                        "mma.sync.aligned.m16n8k16.row.col.f32.f16.f16.f32 "
                        "{%0,%1,%2,%3}, {%4,%5,%6,%7}, {%8,%9}, {%0,%1,%2,%3};"
                        : "+f"(acc[mi][ni][0]), "+f"(acc[mi][ni][1]),
                          "+f"(acc[mi][ni][2]), "+f"(acc[mi][ni][3])
                        : "r"(af[mi][0]), "r"(af[mi][1]),
                          "r"(af[mi][2]), "r"(af[mi][3]),
                          "r"(b0a[ni]), "r"(b1a[ni]));
            }
        }
    }
#undef LOAD_STAGE

    // ---- epilogue: thread's cols are the contiguous strip colb..colb+15 ----
    int colb = n0 + wn * 64 + 16 * t4;
#define ACCV(s, hh) ((s) < 8 ? acc[mi][(s)][(hh) ? 2 : 0] : acc[mi][(s) - 8][(hh) ? 3 : 1])

    if (MODE == 0) {
        float* C = (float*)Cv;
        float4 bv[4];
#pragma unroll
        for (int q2 = 0; q2 < 4; q2++)
            bv[q2] = *(const float4*)(bias + colb + 4 * q2);
#pragma unroll
        for (int mi = 0; mi < 2; mi++) {
            int row0 = m0 + wm * 32 + mi * 16 + g;
#pragma unroll
            for (int h = 0; h < 2; h++) {
                int row = row0 + h * 8;
                if (row < M) {
                    size_t base = (size_t)row * N + colb;
#pragma unroll
                    for (int q2 = 0; q2 < 4; q2++) {
                        float4 o;
                        float* s0 = &o.x;
#pragma unroll
                        for (int e = 0; e < 4; e++)
                            s0[e] = ACCV(4 * q2 + e, h);
                        float4 rv = *(const float4*)(res + base + 4 * q2);
                        const float* bb = &bv[q2].x;
                        o.x += bb[0] + rv.x; o.y += bb[1] + rv.y;
                        o.z += bb[2] + rv.z; o.w += bb[3] + rv.w;
                        *(float4*)(C + base + 4 * q2) = o;
                    }
                }
            }
        }
    } else if (MODE == 1) {
        __half* C = (__half*)Cv;
#pragma unroll
        for (int mi = 0; mi < 2; mi++) {
            int row0 = m0 + wm * 32 + mi * 16 + g;
#pragma unroll
            for (int h = 0; h < 2; h++) {
                int row = row0 + h * 8;
                if (row < M) {
                    __half* dst = C + (size_t)row * N + colb;
#pragma unroll
                    for (int q2 = 0; q2 < 2; q2++) {
                        uint4 u;
                        __half2 h0 = __floats2half2_rn(ACCV(8*q2+0, h), ACCV(8*q2+1, h));
                        __half2 h1 = __floats2half2_rn(ACCV(8*q2+2, h), ACCV(8*q2+3, h));
                        __half2 h2 = __floats2half2_rn(ACCV(8*q2+4, h), ACCV(8*q2+5, h));
                        __half2 h3 = __floats2half2_rn(ACCV(8*q2+6, h), ACCV(8*q2+7, h));
                        u.x = *reinterpret_cast<uint32_t*>(&h0);
                        u.y = *reinterpret_cast<uint32_t*>(&h1);
                        u.z = *reinterpret_cast<uint32_t*>(&h2);
                        u.w = *reinterpret_cast<uint32_t*>(&h3);
                        *(uint4*)(dst + 8 * q2) = u;
                    }
                }
            }
        }
    } else {  // MODE 2: geglu over interleaved (p,g) pairs
        __half* C = (__half*)Cv;
        int No = N >> 1;
        float bvf[16];
#pragma unroll
        for (int q2 = 0; q2 < 4; q2++)
            *(float4*)(bvf + 4 * q2) = *(const float4*)(bias + colb + 4 * q2);
#pragma unroll
        for (int mi = 0; mi < 2; mi++) {
            int row0 = m0 + wm * 32 + mi * 16 + g;
#pragma unroll
            for (int h = 0; h < 2; h++) {
                int row = row0 + h * 8;
                if (row < M) {
                    float ov[8];
#pragma unroll
                    for (int e = 0; e < 8; e++) {
                        float p  = ACCV(2 * e, h)     + bvf[2 * e];
                        float gg = ACCV(2 * e + 1, h) + bvf[2 * e + 1];
                        float gel = 0.5f * gg * (1.f + erff(gg * 0.70710678118654752f));
                        ov[e] = p * gel;
                    }
                    uint4 u;
                    __half2 h0 = __floats2half2_rn(ov[0], ov[1]);
                    __half2 h1 = __floats2half2_rn(ov[2], ov[3]);
                    __half2 h2 = __floats2half2_rn(ov[4], ov[5]);
                    __half2 h3 = __floats2half2_rn(ov[6], ov[7]);
                    u.x = *reinterpret_cast<uint32_t*>(&h0);
                    u.y = *reinterpret_cast<uint32_t*>(&h1);
                    u.z = *reinterpret_cast<uint32_t*>(&h2);
                    u.w = *reinterpret_cast<uint32_t*>(&h3);
                    *(uint4*)(C + (size_t)row * No + (colb >> 1)) = u;
                }
            }
        }
    }
#undef ACCV
}

// ---------------------------------------------------------------------------
// Weight packing: [K][N] fp32 -> [K/2][N] half2 (k-pair interleaved)
// ---------------------------------------------------------------------------
__global__ void packh(const float* __restrict__ src, uint32_t* __restrict__ dst,
                      int K, int N, int dstride, int coff)
{
    int total = (K >> 1) * (N >> 2);
    int idx = blockIdx.x * 256 + threadIdx.x;
    if (idx >= total) return;
    int npc = N >> 2;
    int kp = idx / npc, n4 = (idx - kp * npc) * 4;
    const float* r0 = src + (size_t)(2 * kp) * N + n4;
    const float* r1 = r0 + N;
    float4 lo = *(const float4*)r0, hi = *(const float4*)r1;
    __half2 h0 = __floats2half2_rn(lo.x, hi.x);
    __half2 h1 = __floats2half2_rn(lo.y, hi.y);
    __half2 h2 = __floats2half2_rn(lo.z, hi.z);
    __half2 h3 = __floats2half2_rn(lo.w, hi.w);
    uint4 o;
    o.x = *reinterpret_cast<uint32_t*>(&h0);
    o.y = *reinterpret_cast<uint32_t*>(&h1);
    o.z = *reinterpret_cast<uint32_t*>(&h2);
    o.w = *reinterpret_cast<uint32_t*>(&h3);
    *(uint4*)(dst + (size_t)kp * dstride + coff + n4) = o;
}

// ffw1 packing with p/g column interleave: dst[kp][2j+0]=pair(p_j), [2j+1]=pair(g_j)
__global__ void packh_ilv(const float* __restrict__ src, uint32_t* __restrict__ dst)
{
    const int HALF = FF_I;          // 5120
    int total = (DIMC / 2) * (HALF / 2);
    int idx = blockIdx.x * 256 + threadIdx.x;
    if (idx >= total) return;
    int jpc = HALF / 2;
    int kp = idx / jpc, j0 = (idx - kp * jpc) * 2;
    const float* r0 = src + (size_t)(2 * kp) * FF_N;
    const float* r1 = r0 + FF_N;
    float2 p0 = *(const float2*)(r0 + j0);
    float2 p1 = *(const float2*)(r1 + j0);
    float2 g0 = *(const float2*)(r0 + HALF + j0);
    float2 g1 = *(const float2*)(r1 + HALF + j0);
    __half2 hp0 = __floats2half2_rn(p0.x, p1.x);
    __half2 hg0 = __floats2half2_rn(g0.x, g1.x);
    __half2 hp1 = __floats2half2_rn(p0.y, p1.y);
    __half2 hg1 = __floats2half2_rn(g0.y, g1.y);
    uint4 o;
    o.x = *reinterpret_cast<uint32_t*>(&hp0);
    o.y = *reinterpret_cast<uint32_t*>(&hg0);
    o.z = *reinterpret_cast<uint32_t*>(&hp1);
    o.w = *reinterpret_cast<uint32_t*>(&hg1);
    *(uint4*)(dst + (size_t)kp * FF_N + 2 * j0) = o;
}

// interleave ffn1 bias: biasI[2j]=b[j], biasI[2j+1]=b[5120+j]
__global__ void bias_ilv(const float* __restrict__ b, float* __restrict__ bi)
{
    int j = blockIdx.x * 256 + threadIdx.x;
    if (j < FF_I) {
        bi[2 * j]     = b[j];
        bi[2 * j + 1] = b[FF_I + j];
    }
}

// fp32 -> fp16 copy (enc)
__global__ void f2h(const float* __restrict__ in, __half* __restrict__ out, int n)
{
    int i = (blockIdx.x * 256 + threadIdx.x) * 8;
    if (i >= n) return;
    float4 a = *(const float4*)(in + i);
    float4 b = *(const float4*)(in + i + 4);
    __half2 h0 = __floats2half2_rn(a.x, a.y);
    __half2 h1 = __floats2half2_rn(a.z, a.w);
    __half2 h2 = __floats2half2_rn(b.x, b.y);
    __half2 h3 = __floats2half2_rn(b.z, b.w);
    uint4 o;
    o.x = *reinterpret_cast<uint32_t*>(&h0);
    o.y = *reinterpret_cast<uint32_t*>(&h1);
    o.z = *reinterpret_cast<uint32_t*>(&h2);
    o.w = *reinterpret_cast<uint32_t*>(&h3);
    *(uint4*)(out + i) = o;
}

// ---------------------------------------------------------------------------
// LayerNorm (fp32 in, fp16 out)
// ---------------------------------------------------------------------------
__global__ __launch_bounds__(128)
void ln_kernel(const float* __restrict__ x, const float* __restrict__ w,
               const float* __restrict__ b, __half* __restrict__ y)
{
    int row = blockIdx.x;
    const float* xr = x + (size_t)row * DIMC;
    __half*      yr = y + (size_t)row * DIMC;
    int tid = threadIdx.x;

    float v[10];
    float s = 0.f, ss = 0.f;
#pragma unroll
    for (int i = 0; i < 10; i++) {
        float t = xr[tid + i*128];
        v[i] = t; s += t; ss += t*t;
    }
#pragma unroll
    for (int off = 16; off; off >>= 1) {
        s  += __shfl_xor_sync(0xffffffffu, s,  off);
        ss += __shfl_xor_sync(0xffffffffu, ss, off);
    }
    __shared__ float sh[8];
    int warp = tid >> 5;
    if ((tid & 31) == 0) { sh[warp] = s; sh[4+warp] = ss; }
    __syncthreads();
    s  = sh[0] + sh[1] + sh[2] + sh[3];
    ss = sh[4] + sh[5] + sh[6] + sh[7];
    float mean = s * (1.f/1280.f);
    float var  = ss * (1.f/1280.f) - mean*mean;
    float rstd = rsqrtf(var + 1e-5f);
#pragma unroll
    for (int i = 0; i < 10; i++) {
        int c = tid + i*128;
        yr[c] = __float2half_rn((v[i] - mean) * rstd * w[c] + b[c]);
    }
}

// ---------------------------------------------------------------------------
// Fused attention: fp16 in (Q/K/V), fp32 math, fp16 out. Strides in halves.
// ---------------------------------------------------------------------------
__global__ __launch_bounds__(256)
void attn_kernel(const __half* __restrict__ Q, const __half* __restrict__ K,
                 const __half* __restrict__ V, __half* __restrict__ O,
                 int Sq, int Sk, long q_bs, long kv_bs, long o_bs,
                 int ldq, int ldkv, int ldo, int sparse, float scale)
{
    __shared__ float Ks[32][160];
    __shared__ float Vs[32][160];

    int batch = blockIdx.z, head = blockIdx.y;
    int q0  = blockIdx.x * 64;
    int tid = threadIdx.x;
    int r   = tid >> 2, c4 = tid & 3;
    int d0  = c4 * 40;
    bool rowvalid = (q0 + r) < Sq;

    float qv[40];
    {
        int rr = rowvalid ? r : 0;
        const __half* qp = Q + (size_t)batch * q_bs
                             + (size_t)(q0 + rr) * ldq + head * DH + d0;
#pragma unroll
        for (int i = 0; i < 5; i++) {
            uint4 u = rowvalid ? ((const uint4*)qp)[i]
                               : make_uint4(0, 0, 0, 0);
            const __half2* ph = (const __half2*)&u;
#pragma unroll
            for (int j = 0; j < 4; j++) {
                float2 f = __half22float2(ph[j]);
                qv[i*8 + 2*j]     = f.x;
                qv[i*8 + 2*j + 1] = f.y;
            }
        }
    }

    float o[40];
#pragma unroll
    for (int i = 0; i < 40; i++) o[i] = 0.f;
    float m = -1e30f, l = 0.f;

    int lr = tid >> 3;
    int lc = (tid & 7) * 20;

    int ntiles = (Sk + 31) >> 5;
    for (int kt = 0; kt < ntiles; kt++) {
        int j = kt * 32 + lr;
        {
            const __half* kp = nullptr;
            const __half* vp = nullptr;
            if (j < Sk) {
                size_t off;
                if (sparse) {
                    int bb = batch >> 4, f = batch & 15;
                    int srcf = (j < 256) ? 0 : ((f > 0) ? (f - 1) : 0);
                    int jr2  = (j < 256) ? j : (j - 256);
                    off = (size_t)((bb*16 + srcf) * 256 + jr2) * ldkv
                        + head * DH + lc;
                } else {
                    off = (size_t)batch * kv_bs + (size_t)j * ldkv
                        + head * DH + lc;
                }
                kp = K + off; vp = V + off;
            }
#pragma unroll
            for (int i = 0; i < 5; i++) {
                uint2 kx = kp ? *(const uint2*)(kp + i*4) : make_uint2(0, 0);
                uint2 vx = vp ? *(const uint2*)(vp + i*4) : make_uint2(0, 0);
                const __half2* kh = (const __half2*)&kx;
                const __half2* vh = (const __half2*)&vx;
                float2 k0 = __half22float2(kh[0]), k1 = __half22float2(kh[1]);
                float2 v0 = __half22float2(vh[0]), v1 = __half22float2(vh[1]);
                *(float4*)&Ks[lr][lc + i*4] = make_float4(k0.x, k0.y, k1.x, k1.y);
                *(float4*)&Vs[lr][lc + i*4] = make_float4(v0.x, v0.y, v1.x, v1.y);
            }
        }
        __syncthreads();

#pragma unroll
        for (int jc = 0; jc < 2; jc++) {
            int jb = jc * 16;
            if (kt*32 + jb < Sk) {
                float p[16];
#pragma unroll
                for (int jj = 0; jj < 16; jj++) {
                    const float4* kr = (const float4*)&Ks[jb + jj][d0];
                    float s0 = 0.f, s1 = 0.f, s2 = 0.f, s3 = 0.f;
#pragma unroll
                    for (int i = 0; i < 10; i++) {
                        float4 k4 = kr[i];
                        s0 += qv[i*4+0]*k4.x; s1 += qv[i*4+1]*k4.y;
                        s2 += qv[i*4+2]*k4.z; s3 += qv[i*4+3]*k4.w;
                    }
                    p[jj] = (s0 + s1) + (s2 + s3);
                }
#pragma unroll
                for (int jj = 0; jj < 16; jj++) {
                    p[jj] += __shfl_xor_sync(0xffffffffu, p[jj], 1);
                    p[jj] += __shfl_xor_sync(0xffffffffu, p[jj], 2);
                    int jg = kt*32 + jb + jj;
                    p[jj] = (jg < Sk) ? p[jj] * scale : -1e30f;
                }
                float mt = m;
#pragma unroll
                for (int jj = 0; jj < 16; jj++) mt = fmaxf(mt, p[jj]);
                if (mt > m) {
                    float sc = __expf(m - mt);
                    l *= sc;
#pragma unroll
                    for (int i = 0; i < 40; i++) o[i] *= sc;
                    m = mt;
                }
#pragma unroll
                for (int jj = 0; jj < 16; jj++) {
                    float e = __expf(p[jj] - m);
                    l += e;
                    const float4* vr = (const float4*)&Vs[jb + jj][d0];
#pragma unroll
                    for (int i = 0; i < 10; i++) {
                        float4 v4 = vr[i];
                        o[i*4+0] += e * v4.x; o[i*4+1] += e * v4.y;
                        o[i*4+2] += e * v4.z; o[i*4+3] += e * v4.w;
                    }
                }
            }
        }
        __syncthreads();
    }

    if (rowvalid) {
        float inv = 1.f / l;
        __half* op = O + (size_t)batch * o_bs
                       + (size_t)(q0 + r) * ldo + head * DH + d0;
#pragma unroll
        for (int i = 0; i < 5; i++) {
            uint4 u;
            __half2 h0 = __floats2half2_rn(o[i*8+0]*inv, o[i*8+1]*inv);
            __half2 h1 = __floats2half2_rn(o[i*8+2]*inv, o[i*8+3]*inv);
            __half2 h2 = __floats2half2_rn(o[i*8+4]*inv, o[i*8+5]*inv);
            __half2 h3 = __floats2half2_rn(o[i*8+6]*inv, o[i*8+7]*inv);
            u.x = *reinterpret_cast<uint32_t*>(&h0);
            u.y = *reinterpret_cast<uint32_t*>(&h1);
            u.z = *reinterpret_cast<uint32_t*>(&h2);
            u.w = *reinterpret_cast<uint32_t*>(&h3);
            ((uint4*)op)[i] = u;
        }
    }
}

// ---------------------------------------------------------------------------
// Temporal reshape transposes (fp32)
// ---------------------------------------------------------------------------
__global__ void transpose_fwd(const float* __restrict__ in, float* __restrict__ out)
{
    size_t idx = (size_t)blockIdx.x * blockDim.x + threadIdx.x;
    if (idx >= (size_t)NROWS * DIMC) return;
    int c   = (int)(idx % DIMC);
    int row = (int)(idx / DIMC);
    int f   = row & 15;
    int tok = (row >> 4) & 255;
    int b   = row >> 12;
    out[idx] = in[((size_t)((b*16 + f)*256 + tok)) * DIMC + c];
}

__global__ void transpose_bwd(const float* __restrict__ in, float* __restrict__ out)
{
    size_t idx = (size_t)blockIdx.x * blockDim.x + threadIdx.x;
    if (idx >= (size_t)NROWS * DIMC) return;
    int c   = (int)(idx % DIMC);
    int row = (int)(idx / DIMC);
    int tok = row & 255;
    int f   = (row >> 8) & 15;
    int b   = row >> 12;
    out[idx] = in[((size_t)((b*256 + tok)*16 + f)) * DIMC + c];
}

// ---------------------------------------------------------------------------
// Host launcher
// ---------------------------------------------------------------------------
template<int MODE>
static void launch_gemm(const __half* A, const uint32_t* B2, void* C,
                        const float* bias, const float* res,
                        int M, int N, int K)
{
    static bool attr_set = false;
    if (!attr_set) {
        cudaFuncSetAttribute(gemm_f16<MODE>,
            cudaFuncAttributeMaxDynamicSharedMemorySize, GEMM_SMEM);
        attr_set = true;
    }
    int nm = (M + 127) / 128, nn = N / 128;
    gemm_f16<MODE><<<nm * nn, 256, GEMM_SMEM>>>(A, B2, C, bias, res, M, N, K);
}

static void launch_pack(const float* src, uint32_t* dst, int K, int N,
                        int dstride, int coff)
{
    int total = (K / 2) * (N / 4);
    packh<<<(total + 255) / 256, 256>>>(src, dst, K, N, dstride, coff);
}

extern "C" void kernel_launch(void* const* d_in, const int* in_sizes, int n_in,
                              void* d_out, int out_size)
{
    const float* hid  = (const float*)d_in[0];
    const float* enc  = (const float*)d_in[1];
    const float* n1w  = (const float*)d_in[2];
    const float* n1b  = (const float*)d_in[3];
    const float* a1wq = (const float*)d_in[4];
    const float* a1wk = (const float*)d_in[5];
    const float* a1wv = (const float*)d_in[6];
    const float* a1wo = (const float*)d_in[7];
    const float* a1bo = (const float*)d_in[8];
    const float* n2w  = (const float*)d_in[9];
    const float* n2b  = (const float*)d_in[10];
    const float* a2wq = (const float*)d_in[11];
    const float* a2wk = (const float*)d_in[12];
    const float* a2wv = (const float*)d_in[13];
    const float* a2wo = (const float*)d_in[14];
    const float* a2bo = (const float*)d_in[15];
    const float* n3w  = (const float*)d_in[16];
    const float* n3b  = (const float*)d_in[17];
    const float* ffw1 = (const float*)d_in[18];
    const float* ffb1 = (const float*)d_in[19];
    const float* ffw2 = (const float*)d_in[20];
    const float* ffb2 = (const float*)d_in[21];
    const float* ntw  = (const float*)d_in[22];
    const float* ntb  = (const float*)d_in[23];
    const float* atwq = (const float*)d_in[24];
    const float* atwk = (const float*)d_in[25];
    const float* atwv = (const float*)d_in[26];
    const float* atwo = (const float*)d_in[27];
    const float* atbo = (const float*)d_in[28];

    float* out = (float*)d_out;

    __half *nh, *ao, *qkv, *gg, *kvh, *ench;
    float *ht, *biasi;
    uint32_t* wt;
    cudaGetSymbolAddress((void**)&nh,   g_nh_h);
    cudaGetSymbolAddress((void**)&ao,   g_ao_h);
    cudaGetSymbolAddress((void**)&qkv,  g_qkv_h);
    cudaGetSymbolAddress((void**)&gg,   g_gg_h);
    cudaGetSymbolAddress((void**)&kvh,  g_kv_h);
    cudaGetSymbolAddress((void**)&ench, g_enc_h);
    cudaGetSymbolAddress((void**)&ht,   g_ht);
    cudaGetSymbolAddress((void**)&biasi,g_biasi);
    cudaGetSymbolAddress((void**)&wt,   g_wt);

    const float scale = 0.07905694150420949f;   // 160^-0.5

    // ---- one-time weight packing ----
    launch_pack(a1wq, wt + OFF_W1QKV, DIMC, DIMC, 3*DIMC, 0);
    launch_pack(a1wk, wt + OFF_W1QKV, DIMC, DIMC, 3*DIMC, DIMC);
    launch_pack(a1wv, wt + OFF_W1QKV, DIMC, DIMC, 3*DIMC, 2*DIMC);
    launch_pack(a1wo, wt + OFF_A1WO,  DIMC, DIMC, DIMC, 0);
    launch_pack(a2wq, wt + OFF_A2WQ,  DIMC, DIMC, DIMC, 0);
    launch_pack(a2wk, wt + OFF_W2KV,  CROSS, DIMC, 2*DIMC, 0);
    launch_pack(a2wv, wt + OFF_W2KV,  CROSS, DIMC, 2*DIMC, DIMC);
    launch_pack(a2wo, wt + OFF_A2WO,  DIMC, DIMC, DIMC, 0);
    {
        int total = (DIMC/2) * (FF_I/2);
        packh_ilv<<<(total + 255) / 256, 256>>>(ffw1, wt + OFF_FFW1);
        bias_ilv<<<(FF_I + 255) / 256, 256>>>(ffb1, biasi);
    }
    launch_pack(ffw2, wt + OFF_FFW2,  FF_I, DIMC, DIMC, 0);
    launch_pack(atwq, wt + OFF_WTQKV, DIMC, DIMC, 3*DIMC, 0);
    launch_pack(atwk, wt + OFF_WTQKV, DIMC, DIMC, 3*DIMC, DIMC);
    launch_pack(atwv, wt + OFF_WTQKV, DIMC, DIMC, 3*DIMC, 2*DIMC);
    launch_pack(atwo, wt + OFF_ATWO,  DIMC, DIMC, DIMC, 0);
    f2h<<<(ENCROWS*CROSS/8 + 255) / 256, 256>>>(enc, ench, ENCROWS*CROSS);

    const int QKV = 3 * DIMC;     // 3840
    const int KV2 = 2 * DIMC;     // 2560

    // ---- attn1: sparse-causal self-attention ----
    ln_kernel<<<NROWS, 128>>>(hid, n1w, n1b, nh);
    launch_gemm<1>(nh, wt + OFF_W1QKV, qkv, nullptr, nullptr, NROWS, QKV, DIMC);
    attn_kernel<<<dim3(4, HEADS, BF), 256>>>(
        qkv, qkv + DIMC, qkv + 2*DIMC, ao,
        TOK, 2*TOK, (long)TOK*QKV, 0, (long)TOK*DIMC,
        QKV, QKV, DIMC, 1, scale);
    launch_gemm<0>(ao, wt + OFF_A1WO, out, a1bo, hid, NROWS, DIMC, DIMC);

    // ---- attn2: cross-attention ----
    ln_kernel<<<NROWS, 128>>>(out, n2w, n2b, nh);
    launch_gemm<1>(nh,   wt + OFF_A2WQ, qkv, nullptr, nullptr, NROWS,   DIMC, DIMC);
    launch_gemm<1>(ench, wt + OFF_W2KV, kvh, nullptr, nullptr, ENCROWS, KV2,  CROSS);
    attn_kernel<<<dim3(4, HEADS, BF), 256>>>(
        qkv, kvh, kvh + DIMC, ao,
        TOK, ESEQ, (long)TOK*DIMC, (long)ESEQ*KV2, (long)TOK*DIMC,
        DIMC, KV2, DIMC, 0, scale);
    launch_gemm<0>(ao, wt + OFF_A2WO, out, a2bo, out, NROWS, DIMC, DIMC);

    // ---- geglu FFN (geglu fused into ffn1 epilogue) ----
    ln_kernel<<<NROWS, 128>>>(out, n3w, n3b, nh);
    launch_gemm<2>(nh, wt + OFF_FFW1, gg, biasi, nullptr, NROWS, FF_N, DIMC);
    launch_gemm<0>(gg, wt + OFF_FFW2, out, ffb2, out, NROWS, DIMC, FF_I);

    // ---- temporal self-attention ----
    {
        size_t tot = (size_t)NROWS * DIMC;
        transpose_fwd<<<(unsigned)((tot + 255) / 256), 256>>>(out, ht);
    }
    ln_kernel<<<NROWS, 128>>>(ht, ntw, ntb, nh);
    launch_gemm<1>(nh, wt + OFF_WTQKV, qkv, nullptr, nullptr, NROWS, QKV, DIMC);
    attn_kernel<<<dim3(1, HEADS, 2*TOK), 256>>>(
        qkv, qkv + DIMC, qkv + 2*DIMC, ao,
        FRAMES, FRAMES, (long)FRAMES*QKV, (long)FRAMES*QKV, (long)FRAMES*DIMC,
        QKV, QKV, DIMC, 0, scale);
    launch_gemm<0>(ao, wt + OFF_ATWO, ht, atbo, ht, NROWS, DIMC, DIMC);
    {
        size_t tot = (size_t)NROWS * DIMC;
        transpose_bwd<<<(unsigned)((tot + 255) / 256), 256>>>(ht, out);
    }
}

// round 15
// speedup vs baseline: 2.9736x; 1.5196x over previous
#include <cuda_runtime.h>
#include <cuda_fp16.h>
#include <cstdint>
#include <math.h>

// ---------------------------------------------------------------------------
// Problem constants
// ---------------------------------------------------------------------------
#define BF      32
#define TOK     256
#define DIMC    1280
#define HEADS   8
#define DH      160
#define CROSS   768
#define ESEQ    77
#define FRAMES  16
#define NROWS   (BF*TOK)          // 8192
#define ENCROWS (BF*ESEQ)         // 2464
#define FF_N    (2*4*DIMC)        // 10240
#define FF_I    (4*DIMC)          // 5120

// ---------------------------------------------------------------------------
// Scratch (device globals; no allocation allowed)
// ---------------------------------------------------------------------------
__device__ __align__(256) __half g_nh_h [NROWS*DIMC];
__device__ __align__(256) __half g_ao_h [NROWS*DIMC];
__device__ __align__(256) __half g_qkv_h[(size_t)NROWS*3*DIMC];
__device__ __align__(256) __half g_gg_h [(size_t)NROWS*FF_I];
__device__ __align__(256) __half g_kv_h [ENCROWS*2*DIMC];
__device__ __align__(256) __half g_enc_h[ENCROWS*CROSS];
__device__ float g_ht [NROWS*DIMC];
__device__ float g_biasi[FF_N];
__device__ __align__(256) uint32_t g_wt[19005440];  // half2 k-pair-interleaved weights

// packed-weight offsets (uint32 = half2 units), layout [K/2][N]
#define OFF_W1QKV 0u          // [640, 3840]
#define OFF_A1WO  2457600u    // [640, 1280]
#define OFF_A2WQ  3276800u
#define OFF_W2KV  4096000u    // [384, 2560]
#define OFF_A2WO  5079040u
#define OFF_FFW1  5898240u    // [640, 10240] (p/g column-interleaved)
#define OFF_FFW2  12451840u   // [2560, 1280]
#define OFF_WTQKV 15728640u   // [640, 3840]
#define OFF_ATWO  18186240u

// ---------------------------------------------------------------------------
// Helpers
// ---------------------------------------------------------------------------
__device__ __forceinline__ uint32_t smem_u32(const void* p) {
    uint32_t a;
    asm("{ .reg .u64 t; cvta.to.shared.u64 t, %1; cvt.u32.u64 %0, t; }" : "=r"(a) : "l"(p));
    return a;
}

#define CPASYNC16(dst, src, sz) \
    asm volatile("cp.async.cg.shared.global [%0], [%1], 16, %2;" \
        :: "r"((uint32_t)(dst)), "l"(src), "r"((uint32_t)(sz)) : "memory")
#define CP_COMMIT() asm volatile("cp.async.commit_group;" ::: "memory")
#define CP_WAIT(n)  asm volatile("cp.async.wait_group %0;" :: "n"(n) : "memory")

#define MMA16816(c, a, b0, b1) \
    asm volatile( \
        "mma.sync.aligned.m16n8k16.row.col.f32.f16.f16.f32 " \
        "{%0,%1,%2,%3}, {%4,%5,%6,%7}, {%8,%9}, {%0,%1,%2,%3};" \
        : "+f"((c)[0]), "+f"((c)[1]), "+f"((c)[2]), "+f"((c)[3]) \
        : "r"((a)[0]), "r"((a)[1]), "r"((a)[2]), "r"((a)[3]), \
          "r"(b0), "r"(b1))

// ---------------------------------------------------------------------------
// fp16 GEMM v7 (unchanged from R14): 3 epilogue modes
// ---------------------------------------------------------------------------
#define STAGES        4
#define A_STG_BYTES   10240
#define B_STG_BYTES   8192
#define GEMM_SMEM     (STAGES*(A_STG_BYTES+B_STG_BYTES))  // 73728

template<int MODE>
__global__ void __launch_bounds__(256, 2)
gemm_f16(const __half* __restrict__ A, const uint32_t* __restrict__ B2,
         void* __restrict__ Cv, const float* __restrict__ bias,
         const float* __restrict__ res, int M, int N, int K)
{
    extern __shared__ __align__(16) char smem[];
    uint32_t aBase = smem_u32(smem);
    uint32_t bBase = aBase + STAGES * A_STG_BYTES;

    int tid  = threadIdx.x;
    int warp = tid >> 5, lane = tid & 31;
    int wm = warp & 3, wn = warp >> 2;
    int g  = lane >> 2, t4 = lane & 3;

    int num_m = (M + 127) >> 7, num_n = N >> 7;
    const int GM = 8;
    int npg = GM * num_n;
    int group = blockIdx.x / npg;
    int first = group * GM;
    int gsz = min(num_m - first, GM);
    int rem = blockIdx.x - group * npg;
    int m0 = (first + rem % gsz) << 7;
    int n0 = (rem / gsz) << 7;

    int arow = tid & 127, acg = tid >> 7;
    bool aval = (m0 + arow) < M;
    const __half* aptr = A + (size_t)(m0 + arow) * K + acg * 16;
    uint32_t aDst = aBase + arow * 80 + acg * 32;
    int bp = tid >> 4, bc = tid & 15;
    int Rb = (bp & 1) + 4 * ((bp >> 1) & 1);
    const uint32_t* bptr = B2 + (size_t)bp * N + n0 + bc * 4;
    uint32_t bD0 = bBase + bp * 512 + ((bc + Rb) & 31) * 16;
    uint32_t bD1 = bBase + bp * 512 + ((bc + 16 + Rb) & 31) * 16;

    uint32_t aFrag = ((wm * 32 + (lane & 15)) * 40 + (lane >> 4) * 8) * 2;
    int Rf  = (t4 & 1) + 4 * ((t4 >> 1) & 1);
    int pc0 = ((16 * wn + 2 * g + Rf) & 31) * 16;
    int pc1 = ((16 * wn + 2 * g + 1 + Rf) & 31) * 16;

    float acc[2][8][4];
#pragma unroll
    for (int mi = 0; mi < 2; mi++)
#pragma unroll
        for (int ni = 0; ni < 8; ni++)
#pragma unroll
            for (int i = 0; i < 4; i++) acc[mi][ni][i] = 0.f;

    int KT = K >> 5;

#define LOAD_STAGE(kt, s)                                                     \
    do {                                                                      \
        const __half* _a = aptr + (size_t)(kt) * 32;                          \
        uint32_t _ad = aDst + (s) * A_STG_BYTES;                              \
        unsigned _sz = aval ? 16u : 0u;                                       \
        CPASYNC16(_ad,      _a,     _sz);                                     \
        CPASYNC16(_ad + 16, _a + 8, _sz);                                     \
        const uint32_t* _b = bptr + (size_t)(kt) * 16 * N;                    \
        CPASYNC16(bD0 + (s) * B_STG_BYTES, _b,      16u);                     \
        CPASYNC16(bD1 + (s) * B_STG_BYTES, _b + 64, 16u);                     \
    } while (0)

#pragma unroll
    for (int s = 0; s < STAGES - 1; s++) {
        if (s < KT) LOAD_STAGE(s, s);
        CP_COMMIT();
    }

    for (int kt = 0; kt < KT; kt++) {
        CP_WAIT(STAGES - 2);
        __syncthreads();

        int nk = kt + STAGES - 1;
        if (nk < KT) LOAD_STAGE(nk, nk % STAGES);
        CP_COMMIT();

        uint32_t astage = aBase + (kt % STAGES) * A_STG_BYTES + aFrag;
        uint32_t bstage = bBase + (kt % STAGES) * B_STG_BYTES;

#pragma unroll
        for (int ks = 0; ks < 2; ks++) {
            uint32_t af[2][4];
#pragma unroll
            for (int mi = 0; mi < 2; mi++) {
                uint32_t addr = astage + mi * (16 * 80) + ks * 32;
                asm volatile(
                    "ldmatrix.sync.aligned.m8n8.x4.shared.b16 {%0,%1,%2,%3}, [%4];"
                    : "=r"(af[mi][0]), "=r"(af[mi][1]),
                      "=r"(af[mi][2]), "=r"(af[mi][3])
                    : "r"(addr));
            }
            uint32_t r0 = bstage + (8 * ks + t4) * 512;
            uint32_t r1 = r0 + 2048;
            uint4 B00, B01, B10, B11;
            asm volatile("ld.shared.v4.b32 {%0,%1,%2,%3}, [%4];"
                : "=r"(B00.x), "=r"(B00.y), "=r"(B00.z), "=r"(B00.w) : "r"(r0 + pc0));
            asm volatile("ld.shared.v4.b32 {%0,%1,%2,%3}, [%4];"
                : "=r"(B01.x), "=r"(B01.y), "=r"(B01.z), "=r"(B01.w) : "r"(r0 + pc1));
            asm volatile("ld.shared.v4.b32 {%0,%1,%2,%3}, [%4];"
                : "=r"(B10.x), "=r"(B10.y), "=r"(B10.z), "=r"(B10.w) : "r"(r1 + pc0));
            asm volatile("ld.shared.v4.b32 {%0,%1,%2,%3}, [%4];"
                : "=r"(B11.x), "=r"(B11.y), "=r"(B11.z), "=r"(B11.w) : "r"(r1 + pc1));
            uint32_t b0a[8] = {B00.x, B00.y, B00.z, B00.w, B01.x, B01.y, B01.z, B01.w};
            uint32_t b1a[8] = {B10.x, B10.y, B10.z, B10.w, B11.x, B11.y, B11.z, B11.w};
#pragma unroll
            for (int ni = 0; ni < 8; ni++) {
#pragma unroll
                for (int mi = 0; mi < 2; mi++)
                    MMA16816(acc[mi][ni], af[mi], b0a[ni], b1a[ni]);
            }
        }
    }
#undef LOAD_STAGE

    int colb = n0 + wn * 64 + 16 * t4;
#define ACCV(s, hh) ((s) < 8 ? acc[mi][(s)][(hh) ? 2 : 0] : acc[mi][(s) - 8][(hh) ? 3 : 1])

    if (MODE == 0) {
        float* C = (float*)Cv;
        float4 bv[4];
#pragma unroll
        for (int q2 = 0; q2 < 4; q2++)
            bv[q2] = *(const float4*)(bias + colb + 4 * q2);
#pragma unroll
        for (int mi = 0; mi < 2; mi++) {
            int row0 = m0 + wm * 32 + mi * 16 + g;
#pragma unroll
            for (int h = 0; h < 2; h++) {
                int row = row0 + h * 8;
                if (row < M) {
                    size_t base = (size_t)row * N + colb;
#pragma unroll
                    for (int q2 = 0; q2 < 4; q2++) {
                        float4 o;
                        float* s0 = &o.x;
#pragma unroll
                        for (int e = 0; e < 4; e++)
                            s0[e] = ACCV(4 * q2 + e, h);
                        float4 rv = *(const float4*)(res + base + 4 * q2);
                        const float* bb = &bv[q2].x;
                        o.x += bb[0] + rv.x; o.y += bb[1] + rv.y;
                        o.z += bb[2] + rv.z; o.w += bb[3] + rv.w;
                        *(float4*)(C + base + 4 * q2) = o;
                    }
                }
            }
        }
    } else if (MODE == 1) {
        __half* C = (__half*)Cv;
#pragma unroll
        for (int mi = 0; mi < 2; mi++) {
            int row0 = m0 + wm * 32 + mi * 16 + g;
#pragma unroll
            for (int h = 0; h < 2; h++) {
                int row = row0 + h * 8;
                if (row < M) {
                    __half* dst = C + (size_t)row * N + colb;
#pragma unroll
                    for (int q2 = 0; q2 < 2; q2++) {
                        uint4 u;
                        __half2 h0 = __floats2half2_rn(ACCV(8*q2+0, h), ACCV(8*q2+1, h));
                        __half2 h1 = __floats2half2_rn(ACCV(8*q2+2, h), ACCV(8*q2+3, h));
                        __half2 h2 = __floats2half2_rn(ACCV(8*q2+4, h), ACCV(8*q2+5, h));
                        __half2 h3 = __floats2half2_rn(ACCV(8*q2+6, h), ACCV(8*q2+7, h));
                        u.x = *reinterpret_cast<uint32_t*>(&h0);
                        u.y = *reinterpret_cast<uint32_t*>(&h1);
                        u.z = *reinterpret_cast<uint32_t*>(&h2);
                        u.w = *reinterpret_cast<uint32_t*>(&h3);
                        *(uint4*)(dst + 8 * q2) = u;
                    }
                }
            }
        }
    } else {
        __half* C = (__half*)Cv;
        int No = N >> 1;
        float bvf[16];
#pragma unroll
        for (int q2 = 0; q2 < 4; q2++)
            *(float4*)(bvf + 4 * q2) = *(const float4*)(bias + colb + 4 * q2);
#pragma unroll
        for (int mi = 0; mi < 2; mi++) {
            int row0 = m0 + wm * 32 + mi * 16 + g;
#pragma unroll
            for (int h = 0; h < 2; h++) {
                int row = row0 + h * 8;
                if (row < M) {
                    float ov[8];
#pragma unroll
                    for (int e = 0; e < 8; e++) {
                        float p  = ACCV(2 * e, h)     + bvf[2 * e];
                        float gg = ACCV(2 * e + 1, h) + bvf[2 * e + 1];
                        float gel = 0.5f * gg * (1.f + erff(gg * 0.70710678118654752f));
                        ov[e] = p * gel;
                    }
                    uint4 u;
                    __half2 h0 = __floats2half2_rn(ov[0], ov[1]);
                    __half2 h1 = __floats2half2_rn(ov[2], ov[3]);
                    __half2 h2 = __floats2half2_rn(ov[4], ov[5]);
                    __half2 h3 = __floats2half2_rn(ov[6], ov[7]);
                    u.x = *reinterpret_cast<uint32_t*>(&h0);
                    u.y = *reinterpret_cast<uint32_t*>(&h1);
                    u.z = *reinterpret_cast<uint32_t*>(&h2);
                    u.w = *reinterpret_cast<uint32_t*>(&h3);
                    *(uint4*)(C + (size_t)row * No + (colb >> 1)) = u;
                }
            }
        }
    }
#undef ACCV
}

// ---------------------------------------------------------------------------
// Weight packing (unchanged)
// ---------------------------------------------------------------------------
__global__ void packh(const float* __restrict__ src, uint32_t* __restrict__ dst,
                      int K, int N, int dstride, int coff)
{
    int total = (K >> 1) * (N >> 2);
    int idx = blockIdx.x * 256 + threadIdx.x;
    if (idx >= total) return;
    int npc = N >> 2;
    int kp = idx / npc, n4 = (idx - kp * npc) * 4;
    const float* r0 = src + (size_t)(2 * kp) * N + n4;
    const float* r1 = r0 + N;
    float4 lo = *(const float4*)r0, hi = *(const float4*)r1;
    __half2 h0 = __floats2half2_rn(lo.x, hi.x);
    __half2 h1 = __floats2half2_rn(lo.y, hi.y);
    __half2 h2 = __floats2half2_rn(lo.z, hi.z);
    __half2 h3 = __floats2half2_rn(lo.w, hi.w);
    uint4 o;
    o.x = *reinterpret_cast<uint32_t*>(&h0);
    o.y = *reinterpret_cast<uint32_t*>(&h1);
    o.z = *reinterpret_cast<uint32_t*>(&h2);
    o.w = *reinterpret_cast<uint32_t*>(&h3);
    *(uint4*)(dst + (size_t)kp * dstride + coff + n4) = o;
}

__global__ void packh_ilv(const float* __restrict__ src, uint32_t* __restrict__ dst)
{
    const int HALF = FF_I;
    int total = (DIMC / 2) * (HALF / 2);
    int idx = blockIdx.x * 256 + threadIdx.x;
    if (idx >= total) return;
    int jpc = HALF / 2;
    int kp = idx / jpc, j0 = (idx - kp * jpc) * 2;
    const float* r0 = src + (size_t)(2 * kp) * FF_N;
    const float* r1 = r0 + FF_N;
    float2 p0 = *(const float2*)(r0 + j0);
    float2 p1 = *(const float2*)(r1 + j0);
    float2 g0 = *(const float2*)(r0 + HALF + j0);
    float2 g1 = *(const float2*)(r1 + HALF + j0);
    __half2 hp0 = __floats2half2_rn(p0.x, p1.x);
    __half2 hg0 = __floats2half2_rn(g0.x, g1.x);
    __half2 hp1 = __floats2half2_rn(p0.y, p1.y);
    __half2 hg1 = __floats2half2_rn(g0.y, g1.y);
    uint4 o;
    o.x = *reinterpret_cast<uint32_t*>(&hp0);
    o.y = *reinterpret_cast<uint32_t*>(&hg0);
    o.z = *reinterpret_cast<uint32_t*>(&hp1);
    o.w = *reinterpret_cast<uint32_t*>(&hg1);
    *(uint4*)(dst + (size_t)kp * FF_N + 2 * j0) = o;
}

__global__ void bias_ilv(const float* __restrict__ b, float* __restrict__ bi)
{
    int j = blockIdx.x * 256 + threadIdx.x;
    if (j < FF_I) {
        bi[2 * j]     = b[j];
        bi[2 * j + 1] = b[FF_I + j];
    }
}

__global__ void f2h(const float* __restrict__ in, __half* __restrict__ out, int n)
{
    int i = (blockIdx.x * 256 + threadIdx.x) * 8;
    if (i >= n) return;
    float4 a = *(const float4*)(in + i);
    float4 b = *(const float4*)(in + i + 4);
    __half2 h0 = __floats2half2_rn(a.x, a.y);
    __half2 h1 = __floats2half2_rn(a.z, a.w);
    __half2 h2 = __floats2half2_rn(b.x, b.y);
    __half2 h3 = __floats2half2_rn(b.z, b.w);
    uint4 o;
    o.x = *reinterpret_cast<uint32_t*>(&h0);
    o.y = *reinterpret_cast<uint32_t*>(&h1);
    o.z = *reinterpret_cast<uint32_t*>(&h2);
    o.w = *reinterpret_cast<uint32_t*>(&h3);
    *(uint4*)(out + i) = o;
}

// ---------------------------------------------------------------------------
// LayerNorm (fp32 in, fp16 out)
// ---------------------------------------------------------------------------
__global__ __launch_bounds__(128)
void ln_kernel(const float* __restrict__ x, const float* __restrict__ w,
               const float* __restrict__ b, __half* __restrict__ y)
{
    int row = blockIdx.x;
    const float* xr = x + (size_t)row * DIMC;
    __half*      yr = y + (size_t)row * DIMC;
    int tid = threadIdx.x;

    float v[10];
    float s = 0.f, ss = 0.f;
#pragma unroll
    for (int i = 0; i < 10; i++) {
        float t = xr[tid + i*128];
        v[i] = t; s += t; ss += t*t;
    }
#pragma unroll
    for (int off = 16; off; off >>= 1) {
        s  += __shfl_xor_sync(0xffffffffu, s,  off);
        ss += __shfl_xor_sync(0xffffffffu, ss, off);
    }
    __shared__ float sh[8];
    int warp = tid >> 5;
    if ((tid & 31) == 0) { sh[warp] = s; sh[4+warp] = ss; }
    __syncthreads();
    s  = sh[0] + sh[1] + sh[2] + sh[3];
    ss = sh[4] + sh[5] + sh[6] + sh[7];
    float mean = s * (1.f/1280.f);
    float var  = ss * (1.f/1280.f) - mean*mean;
    float rstd = rsqrtf(var + 1e-5f);
#pragma unroll
    for (int i = 0; i < 10; i++) {
        int c = tid + i*128;
        yr[c] = __float2half_rn((v[i] - mean) * rstd * w[c] + b[c]);
    }
}

// ---------------------------------------------------------------------------
// Tensor-core flash attention. 128 threads, 4 warps x 16 q-rows = 64 q/block.
// fp16 Q/K/V in gmem; S and O accumulate fp32 via m16n8k16 HMMA.
// ---------------------------------------------------------------------------
#define QPAD 168   // row stride in halves (conflict-free for ldmatrix)

__global__ void __launch_bounds__(128, 3)
attn_tc(const __half* __restrict__ Q, const __half* __restrict__ K,
        const __half* __restrict__ V, __half* __restrict__ O,
        int Sq, int Sk, long q_bs, long kv_bs, long o_bs,
        int ldq, int ldkv, int ldo, int sparse, float scale)
{
    __shared__ __half Qs[64][QPAD];
    __shared__ __half Ks[32][QPAD];
    __shared__ __half Vs[32][QPAD];

    int batch = blockIdx.z, head = blockIdx.y;
    int q0  = blockIdx.x * 64;
    int tid = threadIdx.x;
    int wp  = tid >> 5, lane = tid & 31;
    int g   = lane >> 2, t4 = lane & 3;

    uint32_t qsB = smem_u32(&Qs[0][0]);
    uint32_t ksB = smem_u32(&Ks[0][0]);
    uint32_t vsB = smem_u32(&Vs[0][0]);

    // ---- stage Q tile [64, 160] (2 threads/row x 10 uint4) ----
    {
        int row = tid >> 1, half16 = (tid & 1) * 10;  // uint4 index 0..19
        bool valid = (q0 + row) < Sq;
        const uint4* src = (const uint4*)(Q + (size_t)batch * q_bs
                          + (size_t)(q0 + (valid ? row : 0)) * ldq + head * DH);
        uint4* dst = (uint4*)&Qs[row][0];
#pragma unroll
        for (int i = 0; i < 10; i++) {
            uint4 u = valid ? src[half16 + i] : make_uint4(0,0,0,0);
            dst[half16 + i] = u;
        }
    }
    __syncthreads();

    // ---- preload Q A-fragments (10 k-tiles x 4 regs) ----
    uint32_t qf[10][4];
    {
        uint32_t base = qsB + ((16*wp + (lane & 15)) * QPAD + (lane >> 4) * 8) * 2;
#pragma unroll
        for (int d = 0; d < 10; d++) {
            asm volatile(
                "ldmatrix.sync.aligned.m8n8.x4.shared.b16 {%0,%1,%2,%3}, [%4];"
                : "=r"(qf[d][0]), "=r"(qf[d][1]), "=r"(qf[d][2]), "=r"(qf[d][3])
                : "r"(base + d * 32));
        }
    }
    __syncthreads();   // Qs no longer needed as smem after frag load

    float o[20][4];
#pragma unroll
    for (int w = 0; w < 20; w++)
#pragma unroll
        for (int c = 0; c < 4; c++) o[w][c] = 0.f;
    float m0 = -1e30f, m1 = -1e30f, l0 = 0.f, l1 = 0.f;

    // ldmatrix lane-address components
    int selK = lane >> 3;                // 0..3
    int krow = 8 * (selK >> 1) + (lane & 7);
    int koff = 16 * (selK & 1);
    int vkey = 8 * (selK & 1) + (lane & 7);
    int vwin = (selK >> 1);

    int ntiles = (Sk + 31) >> 5;
    for (int kt = 0; kt < ntiles; kt++) {
        // ---- stage K/V tile [32, 160] (4 threads/row x 5 uint4 each) ----
        {
            int row = tid >> 2, c4i = (tid & 3) * 5;
            int j = kt * 32 + row;
            const uint4* kp = nullptr; const uint4* vp = nullptr;
            if (j < Sk) {
                size_t off;
                if (sparse) {
                    int bb = batch >> 4, f = batch & 15;
                    int srcf = (j < 256) ? 0 : ((f > 0) ? (f - 1) : 0);
                    int jr2  = (j < 256) ? j : (j - 256);
                    off = (size_t)((bb*16 + srcf) * 256 + jr2) * ldkv + head * DH;
                } else {
                    off = (size_t)batch * kv_bs + (size_t)j * ldkv + head * DH;
                }
                kp = (const uint4*)(K + off); vp = (const uint4*)(V + off);
            }
            uint4* kd = (uint4*)&Ks[row][0];
            uint4* vd = (uint4*)&Vs[row][0];
#pragma unroll
            for (int i = 0; i < 5; i++) {
                uint4 ku = kp ? kp[c4i + i] : make_uint4(0,0,0,0);
                uint4 vu = vp ? vp[c4i + i] : make_uint4(0,0,0,0);
                kd[c4i + i] = ku;
                vd[c4i + i] = vu;
            }
        }
        __syncthreads();

        // ---- S = Q K^T : [16, 32] per warp, fp32 ----
        float s[4][4];
#pragma unroll
        for (int j = 0; j < 4; j++)
#pragma unroll
            for (int c = 0; c < 4; c++) s[j][c] = 0.f;
#pragma unroll
        for (int d = 0; d < 10; d++) {
            uint32_t kb[4], kb2[4];
            uint32_t a0 = ksB + (krow * QPAD) * 2 + koff + 32 * d;
            asm volatile(
                "ldmatrix.sync.aligned.m8n8.x4.shared.b16 {%0,%1,%2,%3}, [%4];"
                : "=r"(kb[0]), "=r"(kb[1]), "=r"(kb[2]), "=r"(kb[3]) : "r"(a0));
            uint32_t a1 = a0 + 16 * QPAD * 2;
            asm volatile(
                "ldmatrix.sync.aligned.m8n8.x4.shared.b16 {%0,%1,%2,%3}, [%4];"
                : "=r"(kb2[0]), "=r"(kb2[1]), "=r"(kb2[2]), "=r"(kb2[3]) : "r"(a1));
            MMA16816(s[0], qf[d], kb[0],  kb[1]);
            MMA16816(s[1], qf[d], kb[2],  kb[3]);
            MMA16816(s[2], qf[d], kb2[0], kb2[1]);
            MMA16816(s[3], qf[d], kb2[2], kb2[3]);
        }

        // ---- mask + scale + online softmax ----
        int kbase = kt * 32;
        float tm0 = -1e30f, tm1 = -1e30f;
#pragma unroll
        for (int j = 0; j < 4; j++) {
            int k0 = kbase + 8*j + 2*t4;
            bool v0 = k0 < Sk, v1 = (k0 + 1) < Sk;
            s[j][0] = v0 ? s[j][0] * scale : -1e30f;
            s[j][1] = v1 ? s[j][1] * scale : -1e30f;
            s[j][2] = v0 ? s[j][2] * scale : -1e30f;
            s[j][3] = v1 ? s[j][3] * scale : -1e30f;
            tm0 = fmaxf(tm0, fmaxf(s[j][0], s[j][1]));
            tm1 = fmaxf(tm1, fmaxf(s[j][2], s[j][3]));
        }
        tm0 = fmaxf(tm0, __shfl_xor_sync(0xffffffffu, tm0, 1));
        tm0 = fmaxf(tm0, __shfl_xor_sync(0xffffffffu, tm0, 2));
        tm1 = fmaxf(tm1, __shfl_xor_sync(0xffffffffu, tm1, 1));
        tm1 = fmaxf(tm1, __shfl_xor_sync(0xffffffffu, tm1, 2));

        if (tm0 > m0 || tm1 > m1) {
            float nm0 = fmaxf(m0, tm0), nm1 = fmaxf(m1, tm1);
            float a0 = __expf(m0 - nm0), a1 = __expf(m1 - nm1);
            m0 = nm0; m1 = nm1;
            l0 *= a0; l1 *= a1;
#pragma unroll
            for (int w = 0; w < 20; w++) {
                o[w][0] *= a0; o[w][1] *= a0;
                o[w][2] *= a1; o[w][3] *= a1;
            }
        }

        uint32_t plo[4], phi[4];
#pragma unroll
        for (int j = 0; j < 4; j++) {
            float e0 = __expf(s[j][0] - m0), e1 = __expf(s[j][1] - m0);
            float e2 = __expf(s[j][2] - m1), e3 = __expf(s[j][3] - m1);
            l0 += e0 + e1; l1 += e2 + e3;
            __half2 hl = __floats2half2_rn(e0, e1);
            __half2 hh = __floats2half2_rn(e2, e3);
            plo[j] = *reinterpret_cast<uint32_t*>(&hl);
            phi[j] = *reinterpret_cast<uint32_t*>(&hh);
        }

        // ---- O += P V ----
#pragma unroll
        for (int kk = 0; kk < 2; kk++) {
            uint32_t pa[4] = {plo[2*kk], phi[2*kk], plo[2*kk+1], phi[2*kk+1]};
#pragma unroll
            for (int w2 = 0; w2 < 10; w2++) {
                uint32_t vb[4];
                uint32_t a = vsB + ((16*kk + vkey) * QPAD + (2*w2 + vwin) * 8) * 2;
                asm volatile(
                    "ldmatrix.sync.aligned.m8n8.x4.trans.shared.b16 {%0,%1,%2,%3}, [%4];"
                    : "=r"(vb[0]), "=r"(vb[1]), "=r"(vb[2]), "=r"(vb[3]) : "r"(a));
                MMA16816(o[2*w2],     pa, vb[0], vb[1]);
                MMA16816(o[2*w2 + 1], pa, vb[2], vb[3]);
            }
        }
        __syncthreads();
    }

    // ---- finalize: reduce l across t4 group, write O ----
    l0 += __shfl_xor_sync(0xffffffffu, l0, 1);
    l0 += __shfl_xor_sync(0xffffffffu, l0, 2);
    l1 += __shfl_xor_sync(0xffffffffu, l1, 1);
    l1 += __shfl_xor_sync(0xffffffffu, l1, 2);
    float inv0 = 1.f / l0, inv1 = 1.f / l1;

    int row0 = q0 + 16*wp + g;
    int row1 = row0 + 8;
    __half* ob = O + (size_t)batch * o_bs + head * DH + 8 * 0 + 2 * t4;
#pragma unroll
    for (int w = 0; w < 20; w++) {
        if (row0 < Sq) {
            __half2 hv = __floats2half2_rn(o[w][0] * inv0, o[w][1] * inv0);
            *(__half2*)(ob + (size_t)row0 * ldo + 8 * w) = hv;
        }
        if (row1 < Sq) {
            __half2 hv = __floats2half2_rn(o[w][2] * inv1, o[w][3] * inv1);
            *(__half2*)(ob + (size_t)row1 * ldo + 8 * w) = hv;
        }
    }
}

// ---------------------------------------------------------------------------
// Temporal reshape transposes (fp32)
// ---------------------------------------------------------------------------
__global__ void transpose_fwd(const float* __restrict__ in, float* __restrict__ out)
{
    size_t idx = (size_t)blockIdx.x * blockDim.x + threadIdx.x;
    if (idx >= (size_t)NROWS * DIMC) return;
    int c   = (int)(idx % DIMC);
    int row = (int)(idx / DIMC);
    int f   = row & 15;
    int tok = (row >> 4) & 255;
    int b   = row >> 12;
    out[idx] = in[((size_t)((b*16 + f)*256 + tok)) * DIMC + c];
}

__global__ void transpose_bwd(const float* __restrict__ in, float* __restrict__ out)
{
    size_t idx = (size_t)blockIdx.x * blockDim.x + threadIdx.x;
    if (idx >= (size_t)NROWS * DIMC) return;
    int c   = (int)(idx % DIMC);
    int row = (int)(idx / DIMC);
    int tok = row & 255;
    int f   = (row >> 8) & 15;
    int b   = row >> 12;
    out[idx] = in[((size_t)((b*256 + tok)*16 + f)) * DIMC + c];
}

// ---------------------------------------------------------------------------
// Host launcher
// ---------------------------------------------------------------------------
template<int MODE>
static void launch_gemm(const __half* A, const uint32_t* B2, void* C,
                        const float* bias, const float* res,
                        int M, int N, int K)
{
    static bool attr_set = false;
    if (!attr_set) {
        cudaFuncSetAttribute(gemm_f16<MODE>,
            cudaFuncAttributeMaxDynamicSharedMemorySize, GEMM_SMEM);
        attr_set = true;
    }
    int nm = (M + 127) / 128, nn = N / 128;
    gemm_f16<MODE><<<nm * nn, 256, GEMM_SMEM>>>(A, B2, C, bias, res, M, N, K);
}

static void launch_pack(const float* src, uint32_t* dst, int K, int N,
                        int dstride, int coff)
{
    int total = (K / 2) * (N / 4);
    packh<<<(total + 255) / 256, 256>>>(src, dst, K, N, dstride, coff);
}

extern "C" void kernel_launch(void* const* d_in, const int* in_sizes, int n_in,
                              void* d_out, int out_size)
{
    const float* hid  = (const float*)d_in[0];
    const float* enc  = (const float*)d_in[1];
    const float* n1w  = (const float*)d_in[2];
    const float* n1b  = (const float*)d_in[3];
    const float* a1wq = (const float*)d_in[4];
    const float* a1wk = (const float*)d_in[5];
    const float* a1wv = (const float*)d_in[6];
    const float* a1wo = (const float*)d_in[7];
    const float* a1bo = (const float*)d_in[8];
    const float* n2w  = (const float*)d_in[9];
    const float* n2b  = (const float*)d_in[10];
    const float* a2wq = (const float*)d_in[11];
    const float* a2wk = (const float*)d_in[12];
    const float* a2wv = (const float*)d_in[13];
    const float* a2wo = (const float*)d_in[14];
    const float* a2bo = (const float*)d_in[15];
    const float* n3w  = (const float*)d_in[16];
    const float* n3b  = (const float*)d_in[17];
    const float* ffw1 = (const float*)d_in[18];
    const float* ffb1 = (const float*)d_in[19];
    const float* ffw2 = (const float*)d_in[20];
    const float* ffb2 = (const float*)d_in[21];
    const float* ntw  = (const float*)d_in[22];
    const float* ntb  = (const float*)d_in[23];
    const float* atwq = (const float*)d_in[24];
    const float* atwk = (const float*)d_in[25];
    const float* atwv = (const float*)d_in[26];
    const float* atwo = (const float*)d_in[27];
    const float* atbo = (const float*)d_in[28];

    float* out = (float*)d_out;

    __half *nh, *ao, *qkv, *gg, *kvh, *ench;
    float *ht, *biasi;
    uint32_t* wt;
    cudaGetSymbolAddress((void**)&nh,   g_nh_h);
    cudaGetSymbolAddress((void**)&ao,   g_ao_h);
    cudaGetSymbolAddress((void**)&qkv,  g_qkv_h);
    cudaGetSymbolAddress((void**)&gg,   g_gg_h);
    cudaGetSymbolAddress((void**)&kvh,  g_kv_h);
    cudaGetSymbolAddress((void**)&ench, g_enc_h);
    cudaGetSymbolAddress((void**)&ht,   g_ht);
    cudaGetSymbolAddress((void**)&biasi,g_biasi);
    cudaGetSymbolAddress((void**)&wt,   g_wt);

    const float scale = 0.07905694150420949f;   // 160^-0.5

    // ---- one-time weight packing ----
    launch_pack(a1wq, wt + OFF_W1QKV, DIMC, DIMC, 3*DIMC, 0);
    launch_pack(a1wk, wt + OFF_W1QKV, DIMC, DIMC, 3*DIMC, DIMC);
    launch_pack(a1wv, wt + OFF_W1QKV, DIMC, DIMC, 3*DIMC, 2*DIMC);
    launch_pack(a1wo, wt + OFF_A1WO,  DIMC, DIMC, DIMC, 0);
    launch_pack(a2wq, wt + OFF_A2WQ,  DIMC, DIMC, DIMC, 0);
    launch_pack(a2wk, wt + OFF_W2KV,  CROSS, DIMC, 2*DIMC, 0);
    launch_pack(a2wv, wt + OFF_W2KV,  CROSS, DIMC, 2*DIMC, DIMC);
    launch_pack(a2wo, wt + OFF_A2WO,  DIMC, DIMC, DIMC, 0);
    {
        int total = (DIMC/2) * (FF_I/2);
        packh_ilv<<<(total + 255) / 256, 256>>>(ffw1, wt + OFF_FFW1);
        bias_ilv<<<(FF_I + 255) / 256, 256>>>(ffb1, biasi);
    }
    launch_pack(ffw2, wt + OFF_FFW2,  FF_I, DIMC, DIMC, 0);
    launch_pack(atwq, wt + OFF_WTQKV, DIMC, DIMC, 3*DIMC, 0);
    launch_pack(atwk, wt + OFF_WTQKV, DIMC, DIMC, 3*DIMC, DIMC);
    launch_pack(atwv, wt + OFF_WTQKV, DIMC, DIMC, 3*DIMC, 2*DIMC);
    launch_pack(atwo, wt + OFF_ATWO,  DIMC, DIMC, DIMC, 0);
    f2h<<<(ENCROWS*CROSS/8 + 255) / 256, 256>>>(enc, ench, ENCROWS*CROSS);

    const int QKV = 3 * DIMC;     // 3840
    const int KV2 = 2 * DIMC;     // 2560

    // ---- attn1: sparse-causal self-attention ----
    ln_kernel<<<NROWS, 128>>>(hid, n1w, n1b, nh);
    launch_gemm<1>(nh, wt + OFF_W1QKV, qkv, nullptr, nullptr, NROWS, QKV, DIMC);
    attn_tc<<<dim3(4, HEADS, BF), 128>>>(
        qkv, qkv + DIMC, qkv + 2*DIMC, ao,
        TOK, 2*TOK, (long)TOK*QKV, 0, (long)TOK*DIMC,
        QKV, QKV, DIMC, 1, scale);
    launch_gemm<0>(ao, wt + OFF_A1WO, out, a1bo, hid, NROWS, DIMC, DIMC);

    // ---- attn2: cross-attention ----
    ln_kernel<<<NROWS, 128>>>(out, n2w, n2b, nh);
    launch_gemm<1>(nh,   wt + OFF_A2WQ, qkv, nullptr, nullptr, NROWS,   DIMC, DIMC);
    launch_gemm<1>(ench, wt + OFF_W2KV, kvh, nullptr, nullptr, ENCROWS, KV2,  CROSS);
    attn_tc<<<dim3(4, HEADS, BF), 128>>>(
        qkv, kvh, kvh + DIMC, ao,
        TOK, ESEQ, (long)TOK*DIMC, (long)ESEQ*KV2, (long)TOK*DIMC,
        DIMC, KV2, DIMC, 0, scale);
    launch_gemm<0>(ao, wt + OFF_A2WO, out, a2bo, out, NROWS, DIMC, DIMC);

    // ---- geglu FFN (geglu fused into ffn1 epilogue) ----
    ln_kernel<<<NROWS, 128>>>(out, n3w, n3b, nh);
    launch_gemm<2>(nh, wt + OFF_FFW1, gg, biasi, nullptr, NROWS, FF_N, DIMC);
    launch_gemm<0>(gg, wt + OFF_FFW2, out, ffb2, out, NROWS, DIMC, FF_I);

    // ---- temporal self-attention ----
    {
        size_t tot = (size_t)NROWS * DIMC;
        transpose_fwd<<<(unsigned)((tot + 255) / 256), 256>>>(out, ht);
    }
    ln_kernel<<<NROWS, 128>>>(ht, ntw, ntb, nh);
    launch_gemm<1>(nh, wt + OFF_WTQKV, qkv, nullptr, nullptr, NROWS, QKV, DIMC);
    attn_tc<<<dim3(1, HEADS, 2*TOK), 128>>>(
        qkv, qkv + DIMC, qkv + 2*DIMC, ao,
        FRAMES, FRAMES, (long)FRAMES*QKV, (long)FRAMES*QKV, (long)FRAMES*DIMC,
        QKV, QKV, DIMC, 0, scale);
    launch_gemm<0>(ao, wt + OFF_ATWO, ht, atbo, ht, NROWS, DIMC, DIMC);
    {
        size_t tot = (size_t)NROWS * DIMC;
        transpose_bwd<<<(unsigned)((tot + 255) / 256), 256>>>(ht, out);
    }
}

// round 16
// speedup vs baseline: 3.0229x; 1.0166x over previous
#include <cuda_runtime.h>
#include <cuda_fp16.h>
#include <cstdint>
#include <math.h>

// ---------------------------------------------------------------------------
// Problem constants
// ---------------------------------------------------------------------------
#define BF      32
#define TOK     256
#define DIMC    1280
#define HEADS   8
#define DH      160
#define CROSS   768
#define ESEQ    77
#define FRAMES  16
#define NROWS   (BF*TOK)          // 8192
#define ENCROWS (BF*ESEQ)         // 2464
#define FF_N    (2*4*DIMC)        // 10240
#define FF_I    (4*DIMC)          // 5120

// ---------------------------------------------------------------------------
// Scratch (device globals; no allocation allowed)
// ---------------------------------------------------------------------------
__device__ __align__(256) __half g_nh_h [NROWS*DIMC];
__device__ __align__(256) __half g_ao_h [NROWS*DIMC];
__device__ __align__(256) __half g_qkv_h[(size_t)NROWS*3*DIMC];
__device__ __align__(256) __half g_gg_h [(size_t)NROWS*FF_I];
__device__ __align__(256) __half g_kv_h [ENCROWS*2*DIMC];
__device__ __align__(256) __half g_enc_h[ENCROWS*CROSS];
__device__ float g_biasi[FF_N];
__device__ __align__(256) uint32_t g_wt[19005440];  // half2 k-pair-interleaved weights

// packed-weight offsets (uint32 = half2 units), layout [K/2][N]
#define OFF_W1QKV 0u
#define OFF_A1WO  2457600u
#define OFF_A2WQ  3276800u
#define OFF_W2KV  4096000u
#define OFF_A2WO  5079040u
#define OFF_FFW1  5898240u
#define OFF_FFW2  12451840u
#define OFF_WTQKV 15728640u
#define OFF_ATWO  18186240u

// ---------------------------------------------------------------------------
// Helpers
// ---------------------------------------------------------------------------
__device__ __forceinline__ uint32_t smem_u32(const void* p) {
    uint32_t a;
    asm("{ .reg .u64 t; cvta.to.shared.u64 t, %1; cvt.u32.u64 %0, t; }" : "=r"(a) : "l"(p));
    return a;
}

#define CPASYNC16(dst, src, sz) \
    asm volatile("cp.async.cg.shared.global [%0], [%1], 16, %2;" \
        :: "r"((uint32_t)(dst)), "l"(src), "r"((uint32_t)(sz)) : "memory")
#define CP_COMMIT() asm volatile("cp.async.commit_group;" ::: "memory")
#define CP_WAIT(n)  asm volatile("cp.async.wait_group %0;" :: "n"(n) : "memory")

#define MMA16816(c, a, b0, b1) \
    asm volatile( \
        "mma.sync.aligned.m16n8k16.row.col.f32.f16.f16.f32 " \
        "{%0,%1,%2,%3}, {%4,%5,%6,%7}, {%8,%9}, {%0,%1,%2,%3};" \
        : "+f"((c)[0]), "+f"((c)[1]), "+f"((c)[2]), "+f"((c)[3]) \
        : "r"((a)[0]), "r"((a)[1]), "r"((a)[2]), "r"((a)[3]), \
          "r"(b0), "r"(b1))

// temporal row map: t -> spatial s
__device__ __forceinline__ int t2s(int t) {
    int f = t & 15, tok = (t >> 4) & 255, b = t >> 12;
    return b * 4096 + f * 256 + tok;
}

// ---------------------------------------------------------------------------
// fp16 GEMM: C = A[M,K] @ B[K,N], fp32 accum.
// MODE 0: C fp32, +bias+res (PERM=1: write/res at t2s(row))
// MODE 1: C fp16, plain
// MODE 2: C fp16 [M, N/2], geglu over interleaved (p,g) pairs, + bias
// ---------------------------------------------------------------------------
#define STAGES        4
#define A_STG_BYTES   10240
#define B_STG_BYTES   8192
#define GEMM_SMEM     (STAGES*(A_STG_BYTES+B_STG_BYTES))  // 73728

template<int MODE, int PERM>
__global__ void __launch_bounds__(256, 2)
gemm_f16(const __half* __restrict__ A, const uint32_t* __restrict__ B2,
         void* __restrict__ Cv, const float* __restrict__ bias,
         const float* __restrict__ res, int M, int N, int K)
{
    extern __shared__ __align__(16) char smem[];
    uint32_t aBase = smem_u32(smem);
    uint32_t bBase = aBase + STAGES * A_STG_BYTES;

    int tid  = threadIdx.x;
    int warp = tid >> 5, lane = tid & 31;
    int wm = warp & 3, wn = warp >> 2;
    int g  = lane >> 2, t4 = lane & 3;

    int num_m = (M + 127) >> 7, num_n = N >> 7;
    const int GM = 8;
    int npg = GM * num_n;
    int group = blockIdx.x / npg;
    int first = group * GM;
    int gsz = min(num_m - first, GM);
    int rem = blockIdx.x - group * npg;
    int m0 = (first + rem % gsz) << 7;
    int n0 = (rem / gsz) << 7;

    int arow = tid & 127, acg = tid >> 7;
    bool aval = (m0 + arow) < M;
    const __half* aptr = A + (size_t)(m0 + arow) * K + acg * 16;
    uint32_t aDst = aBase + arow * 80 + acg * 32;
    int bp = tid >> 4, bc = tid & 15;
    int Rb = (bp & 1) + 4 * ((bp >> 1) & 1);
    const uint32_t* bptr = B2 + (size_t)bp * N + n0 + bc * 4;
    uint32_t bD0 = bBase + bp * 512 + ((bc + Rb) & 31) * 16;
    uint32_t bD1 = bBase + bp * 512 + ((bc + 16 + Rb) & 31) * 16;

    uint32_t aFrag = ((wm * 32 + (lane & 15)) * 40 + (lane >> 4) * 8) * 2;
    int Rf  = (t4 & 1) + 4 * ((t4 >> 1) & 1);
    int pc0 = ((16 * wn + 2 * g + Rf) & 31) * 16;
    int pc1 = ((16 * wn + 2 * g + 1 + Rf) & 31) * 16;

    float acc[2][8][4];
#pragma unroll
    for (int mi = 0; mi < 2; mi++)
#pragma unroll
        for (int ni = 0; ni < 8; ni++)
#pragma unroll
            for (int i = 0; i < 4; i++) acc[mi][ni][i] = 0.f;

    int KT = K >> 5;

#define LOAD_STAGE(kt, s)                                                     \
    do {                                                                      \
        const __half* _a = aptr + (size_t)(kt) * 32;                          \
        uint32_t _ad = aDst + (s) * A_STG_BYTES;                              \
        unsigned _sz = aval ? 16u : 0u;                                       \
        CPASYNC16(_ad,      _a,     _sz);                                     \
        CPASYNC16(_ad + 16, _a + 8, _sz);                                     \
        const uint32_t* _b = bptr + (size_t)(kt) * 16 * N;                    \
        CPASYNC16(bD0 + (s) * B_STG_BYTES, _b,      16u);                     \
        CPASYNC16(bD1 + (s) * B_STG_BYTES, _b + 64, 16u);                     \
    } while (0)

#pragma unroll
    for (int s = 0; s < STAGES - 1; s++) {
        if (s < KT) LOAD_STAGE(s, s);
        CP_COMMIT();
    }

    for (int kt = 0; kt < KT; kt++) {
        CP_WAIT(STAGES - 2);
        __syncthreads();

        int nk = kt + STAGES - 1;
        if (nk < KT) LOAD_STAGE(nk, nk % STAGES);
        CP_COMMIT();

        uint32_t astage = aBase + (kt % STAGES) * A_STG_BYTES + aFrag;
        uint32_t bstage = bBase + (kt % STAGES) * B_STG_BYTES;

#pragma unroll
        for (int ks = 0; ks < 2; ks++) {
            uint32_t af[2][4];
#pragma unroll
            for (int mi = 0; mi < 2; mi++) {
                uint32_t addr = astage + mi * (16 * 80) + ks * 32;
                asm volatile(
                    "ldmatrix.sync.aligned.m8n8.x4.shared.b16 {%0,%1,%2,%3}, [%4];"
                    : "=r"(af[mi][0]), "=r"(af[mi][1]),
                      "=r"(af[mi][2]), "=r"(af[mi][3])
                    : "r"(addr));
            }
            uint32_t r0 = bstage + (8 * ks + t4) * 512;
            uint32_t r1 = r0 + 2048;
            uint4 B00, B01, B10, B11;
            asm volatile("ld.shared.v4.b32 {%0,%1,%2,%3}, [%4];"
                : "=r"(B00.x), "=r"(B00.y), "=r"(B00.z), "=r"(B00.w) : "r"(r0 + pc0));
            asm volatile("ld.shared.v4.b32 {%0,%1,%2,%3}, [%4];"
                : "=r"(B01.x), "=r"(B01.y), "=r"(B01.z), "=r"(B01.w) : "r"(r0 + pc1));
            asm volatile("ld.shared.v4.b32 {%0,%1,%2,%3}, [%4];"
                : "=r"(B10.x), "=r"(B10.y), "=r"(B10.z), "=r"(B10.w) : "r"(r1 + pc0));
            asm volatile("ld.shared.v4.b32 {%0,%1,%2,%3}, [%4];"
                : "=r"(B11.x), "=r"(B11.y), "=r"(B11.z), "=r"(B11.w) : "r"(r1 + pc1));
            uint32_t b0a[8] = {B00.x, B00.y, B00.z, B00.w, B01.x, B01.y, B01.z, B01.w};
            uint32_t b1a[8] = {B10.x, B10.y, B10.z, B10.w, B11.x, B11.y, B11.z, B11.w};
#pragma unroll
            for (int ni = 0; ni < 8; ni++) {
#pragma unroll
                for (int mi = 0; mi < 2; mi++)
                    MMA16816(acc[mi][ni], af[mi], b0a[ni], b1a[ni]);
            }
        }
    }
#undef LOAD_STAGE

    int colb = n0 + wn * 64 + 16 * t4;
#define ACCV(s, hh) ((s) < 8 ? acc[mi][(s)][(hh) ? 2 : 0] : acc[mi][(s) - 8][(hh) ? 3 : 1])

    if (MODE == 0) {
        float* C = (float*)Cv;
        float4 bv[4];
#pragma unroll
        for (int q2 = 0; q2 < 4; q2++)
            bv[q2] = *(const float4*)(bias + colb + 4 * q2);
#pragma unroll
        for (int mi = 0; mi < 2; mi++) {
            int row0 = m0 + wm * 32 + mi * 16 + g;
#pragma unroll
            for (int h = 0; h < 2; h++) {
                int row = row0 + h * 8;
                if (row < M) {
                    int grow = PERM ? t2s(row) : row;
                    size_t base = (size_t)grow * N + colb;
#pragma unroll
                    for (int q2 = 0; q2 < 4; q2++) {
                        float4 o;
                        float* s0 = &o.x;
#pragma unroll
                        for (int e = 0; e < 4; e++)
                            s0[e] = ACCV(4 * q2 + e, h);
                        float4 rv = *(const float4*)(res + base + 4 * q2);
                        const float* bb = &bv[q2].x;
                        o.x += bb[0] + rv.x; o.y += bb[1] + rv.y;
                        o.z += bb[2] + rv.z; o.w += bb[3] + rv.w;
                        *(float4*)(C + base + 4 * q2) = o;
                    }
                }
            }
        }
    } else if (MODE == 1) {
        __half* C = (__half*)Cv;
#pragma unroll
        for (int mi = 0; mi < 2; mi++) {
            int row0 = m0 + wm * 32 + mi * 16 + g;
#pragma unroll
            for (int h = 0; h < 2; h++) {
                int row = row0 + h * 8;
                if (row < M) {
                    __half* dst = C + (size_t)row * N + colb;
#pragma unroll
                    for (int q2 = 0; q2 < 2; q2++) {
                        uint4 u;
                        __half2 h0 = __floats2half2_rn(ACCV(8*q2+0, h), ACCV(8*q2+1, h));
                        __half2 h1 = __floats2half2_rn(ACCV(8*q2+2, h), ACCV(8*q2+3, h));
                        __half2 h2 = __floats2half2_rn(ACCV(8*q2+4, h), ACCV(8*q2+5, h));
                        __half2 h3 = __floats2half2_rn(ACCV(8*q2+6, h), ACCV(8*q2+7, h));
                        u.x = *reinterpret_cast<uint32_t*>(&h0);
                        u.y = *reinterpret_cast<uint32_t*>(&h1);
                        u.z = *reinterpret_cast<uint32_t*>(&h2);
                        u.w = *reinterpret_cast<uint32_t*>(&h3);
                        *(uint4*)(dst + 8 * q2) = u;
                    }
                }
            }
        }
    } else {
        __half* C = (__half*)Cv;
        int No = N >> 1;
        float bvf[16];
#pragma unroll
        for (int q2 = 0; q2 < 4; q2++)
            *(float4*)(bvf + 4 * q2) = *(const float4*)(bias + colb + 4 * q2);
#pragma unroll
        for (int mi = 0; mi < 2; mi++) {
            int row0 = m0 + wm * 32 + mi * 16 + g;
#pragma unroll
            for (int h = 0; h < 2; h++) {
                int row = row0 + h * 8;
                if (row < M) {
                    float ov[8];
#pragma unroll
                    for (int e = 0; e < 8; e++) {
                        float p  = ACCV(2 * e, h)     + bvf[2 * e];
                        float gg = ACCV(2 * e + 1, h) + bvf[2 * e + 1];
                        float gel = 0.5f * gg * (1.f + erff(gg * 0.70710678118654752f));
                        ov[e] = p * gel;
                    }
                    uint4 u;
                    __half2 h0 = __floats2half2_rn(ov[0], ov[1]);
                    __half2 h1 = __floats2half2_rn(ov[2], ov[3]);
                    __half2 h2 = __floats2half2_rn(ov[4], ov[5]);
                    __half2 h3 = __floats2half2_rn(ov[6], ov[7]);
                    u.x = *reinterpret_cast<uint32_t*>(&h0);
                    u.y = *reinterpret_cast<uint32_t*>(&h1);
                    u.z = *reinterpret_cast<uint32_t*>(&h2);
                    u.w = *reinterpret_cast<uint32_t*>(&h3);
                    *(uint4*)(C + (size_t)row * No + (colb >> 1)) = u;
                }
            }
        }
    }
#undef ACCV
}

// ---------------------------------------------------------------------------
// Fused prologue packing: 13 plain packs + enc f2h in ONE kernel.
// ---------------------------------------------------------------------------
struct PackParams { const float* s[13]; const float* enc; };

// job table: {base, K, N, dstride, coff, dstoff}
__constant__ int PJ_base[15]    = {0, 204800, 409600, 614400, 819200, 1024000,
                                   1146880, 1269760, 1474560, 2293760, 2498560,
                                   2703360, 2908160, 3112960, 3349504};
__constant__ int PJ_K[14]       = {1280,1280,1280,1280,1280, 768, 768,1280,5120,
                                   1280,1280,1280,1280, 0};
__constant__ int PJ_N[14]       = {1280,1280,1280,1280,1280,1280,1280,1280,1280,
                                   1280,1280,1280,1280, 0};
__constant__ int PJ_dstride[14] = {3840,3840,3840,1280,1280,2560,2560,1280,1280,
                                   3840,3840,3840,1280, 0};
__constant__ int PJ_coff[14]    = {0,1280,2560,0,0,0,1280,0,0,0,1280,2560,0, 0};
__constant__ unsigned PJ_doff[14] = {OFF_W1QKV,OFF_W1QKV,OFF_W1QKV,OFF_A1WO,
                                     OFF_A2WQ,OFF_W2KV,OFF_W2KV,OFF_A2WO,
                                     OFF_FFW2,OFF_WTQKV,OFF_WTQKV,OFF_WTQKV,
                                     OFF_ATWO, 0};

__global__ void pack_all(PackParams pp, uint32_t* __restrict__ wt,
                         __half* __restrict__ ench)
{
    int idx = blockIdx.x * 256 + threadIdx.x;
    if (idx >= 3349504) return;
    int job = 0;
#pragma unroll
    for (int j = 1; j < 15; j++) job += (idx >= PJ_base[j]);
    int local = idx - PJ_base[job];

    if (job == 13) {   // enc f2h
        int i = local * 8;
        float4 a = *(const float4*)(pp.enc + i);
        float4 b = *(const float4*)(pp.enc + i + 4);
        __half2 h0 = __floats2half2_rn(a.x, a.y);
        __half2 h1 = __floats2half2_rn(a.z, a.w);
        __half2 h2 = __floats2half2_rn(b.x, b.y);
        __half2 h3 = __floats2half2_rn(b.z, b.w);
        uint4 o;
        o.x = *reinterpret_cast<uint32_t*>(&h0);
        o.y = *reinterpret_cast<uint32_t*>(&h1);
        o.z = *reinterpret_cast<uint32_t*>(&h2);
        o.w = *reinterpret_cast<uint32_t*>(&h3);
        *(uint4*)(ench + i) = o;
        return;
    }

    const float* src = pp.s[job];
    int K = PJ_K[job], N = PJ_N[job];
    int npc = N >> 2;
    int kp = local / npc, n4 = (local - kp * npc) * 4;
    const float* r0 = src + (size_t)(2 * kp) * N + n4;
    const float* r1 = r0 + N;
    float4 lo = *(const float4*)r0, hi = *(const float4*)r1;
    __half2 h0 = __floats2half2_rn(lo.x, hi.x);
    __half2 h1 = __floats2half2_rn(lo.y, hi.y);
    __half2 h2 = __floats2half2_rn(lo.z, hi.z);
    __half2 h3 = __floats2half2_rn(lo.w, hi.w);
    uint4 o;
    o.x = *reinterpret_cast<uint32_t*>(&h0);
    o.y = *reinterpret_cast<uint32_t*>(&h1);
    o.z = *reinterpret_cast<uint32_t*>(&h2);
    o.w = *reinterpret_cast<uint32_t*>(&h3);
    *(uint4*)(wt + PJ_doff[job] + (size_t)kp * PJ_dstride[job] + PJ_coff[job] + n4) = o;
    (void)K;
}

// ffw1 interleaved pack + ffn1 bias interleave (one kernel)
__global__ void pack_ffn1(const float* __restrict__ src, uint32_t* __restrict__ dst,
                          const float* __restrict__ b, float* __restrict__ bi)
{
    const int HALF = FF_I;
    const int ILV_BLOCKS = 6400;   // (640*2560)/256
    if (blockIdx.x >= ILV_BLOCKS) {
        int j = (blockIdx.x - ILV_BLOCKS) * 256 + threadIdx.x;
        if (j < FF_I) { bi[2*j] = b[j]; bi[2*j + 1] = b[FF_I + j]; }
        return;
    }
    int idx = blockIdx.x * 256 + threadIdx.x;
    int jpc = HALF / 2;
    int kp = idx / jpc, j0 = (idx - kp * jpc) * 2;
    const float* r0 = src + (size_t)(2 * kp) * FF_N;
    const float* r1 = r0 + FF_N;
    float2 p0 = *(const float2*)(r0 + j0);
    float2 p1 = *(const float2*)(r1 + j0);
    float2 g0 = *(const float2*)(r0 + HALF + j0);
    float2 g1 = *(const float2*)(r1 + HALF + j0);
    __half2 hp0 = __floats2half2_rn(p0.x, p1.x);
    __half2 hg0 = __floats2half2_rn(g0.x, g1.x);
    __half2 hp1 = __floats2half2_rn(p0.y, p1.y);
    __half2 hg1 = __floats2half2_rn(g0.y, g1.y);
    uint4 o;
    o.x = *reinterpret_cast<uint32_t*>(&hp0);
    o.y = *reinterpret_cast<uint32_t*>(&hg0);
    o.z = *reinterpret_cast<uint32_t*>(&hp1);
    o.w = *reinterpret_cast<uint32_t*>(&hg1);
    *(uint4*)(dst + (size_t)kp * FF_N + 2 * j0) = o;
}

// ---------------------------------------------------------------------------
// LayerNorm (fp32 in, fp16 out). perm=1: read spatial row t2s(t).
// ---------------------------------------------------------------------------
__global__ __launch_bounds__(128)
void ln_kernel(const float* __restrict__ x, const float* __restrict__ w,
               const float* __restrict__ b, __half* __restrict__ y, int perm)
{
    int row = blockIdx.x;
    int srow = perm ? t2s(row) : row;
    const float* xr = x + (size_t)srow * DIMC;
    __half*      yr = y + (size_t)row * DIMC;
    int tid = threadIdx.x;

    float v[10];
    float s = 0.f, ss = 0.f;
#pragma unroll
    for (int i = 0; i < 10; i++) {
        float t = xr[tid + i*128];
        v[i] = t; s += t; ss += t*t;
    }
#pragma unroll
    for (int off = 16; off; off >>= 1) {
        s  += __shfl_xor_sync(0xffffffffu, s,  off);
        ss += __shfl_xor_sync(0xffffffffu, ss, off);
    }
    __shared__ float sh[8];
    int warp = tid >> 5;
    if ((tid & 31) == 0) { sh[warp] = s; sh[4+warp] = ss; }
    __syncthreads();
    s  = sh[0] + sh[1] + sh[2] + sh[3];
    ss = sh[4] + sh[5] + sh[6] + sh[7];
    float mean = s * (1.f/1280.f);
    float var  = ss * (1.f/1280.f) - mean*mean;
    float rstd = rsqrtf(var + 1e-5f);
#pragma unroll
    for (int i = 0; i < 10; i++) {
        int c = tid + i*128;
        yr[c] = __float2half_rn((v[i] - mean) * rstd * w[c] + b[c]);
    }
}

// ---------------------------------------------------------------------------
// Tensor-core flash attention (unchanged from R15)
// ---------------------------------------------------------------------------
#define QPAD 168

__global__ void __launch_bounds__(128, 3)
attn_tc(const __half* __restrict__ Q, const __half* __restrict__ K,
        const __half* __restrict__ V, __half* __restrict__ O,
        int Sq, int Sk, long q_bs, long kv_bs, long o_bs,
        int ldq, int ldkv, int ldo, int sparse, float scale)
{
    __shared__ __half Qs[64][QPAD];
    __shared__ __half Ks[32][QPAD];
    __shared__ __half Vs[32][QPAD];

    int batch = blockIdx.z, head = blockIdx.y;
    int q0  = blockIdx.x * 64;
    int tid = threadIdx.x;
    int wp  = tid >> 5, lane = tid & 31;
    int g   = lane >> 2, t4 = lane & 3;

    uint32_t qsB = smem_u32(&Qs[0][0]);
    uint32_t ksB = smem_u32(&Ks[0][0]);
    uint32_t vsB = smem_u32(&Vs[0][0]);

    {
        int row = tid >> 1, half16 = (tid & 1) * 10;
        bool valid = (q0 + row) < Sq;
        const uint4* src = (const uint4*)(Q + (size_t)batch * q_bs
                          + (size_t)(q0 + (valid ? row : 0)) * ldq + head * DH);
        uint4* dst = (uint4*)&Qs[row][0];
#pragma unroll
        for (int i = 0; i < 10; i++) {
            uint4 u = valid ? src[half16 + i] : make_uint4(0,0,0,0);
            dst[half16 + i] = u;
        }
    }
    __syncthreads();

    uint32_t qf[10][4];
    {
        uint32_t base = qsB + ((16*wp + (lane & 15)) * QPAD + (lane >> 4) * 8) * 2;
#pragma unroll
        for (int d = 0; d < 10; d++) {
            asm volatile(
                "ldmatrix.sync.aligned.m8n8.x4.shared.b16 {%0,%1,%2,%3}, [%4];"
                : "=r"(qf[d][0]), "=r"(qf[d][1]), "=r"(qf[d][2]), "=r"(qf[d][3])
                : "r"(base + d * 32));
        }
    }
    __syncthreads();

    float o[20][4];
#pragma unroll
    for (int w = 0; w < 20; w++)
#pragma unroll
        for (int c = 0; c < 4; c++) o[w][c] = 0.f;
    float m0 = -1e30f, m1 = -1e30f, l0 = 0.f, l1 = 0.f;

    int selK = lane >> 3;
    int krow = 8 * (selK >> 1) + (lane & 7);
    int koff = 16 * (selK & 1);
    int vkey = 8 * (selK & 1) + (lane & 7);
    int vwin = (selK >> 1);

    int ntiles = (Sk + 31) >> 5;
    for (int kt = 0; kt < ntiles; kt++) {
        {
            int row = tid >> 2, c4i = (tid & 3) * 5;
            int j = kt * 32 + row;
            const uint4* kp = nullptr; const uint4* vp = nullptr;
            if (j < Sk) {
                size_t off;
                if (sparse) {
                    int bb = batch >> 4, f = batch & 15;
                    int srcf = (j < 256) ? 0 : ((f > 0) ? (f - 1) : 0);
                    int jr2  = (j < 256) ? j : (j - 256);
                    off = (size_t)((bb*16 + srcf) * 256 + jr2) * ldkv + head * DH;
                } else {
                    off = (size_t)batch * kv_bs + (size_t)j * ldkv + head * DH;
                }
                kp = (const uint4*)(K + off); vp = (const uint4*)(V + off);
            }
            uint4* kd = (uint4*)&Ks[row][0];
            uint4* vd = (uint4*)&Vs[row][0];
#pragma unroll
            for (int i = 0; i < 5; i++) {
                uint4 ku = kp ? kp[c4i + i] : make_uint4(0,0,0,0);
                uint4 vu = vp ? vp[c4i + i] : make_uint4(0,0,0,0);
                kd[c4i + i] = ku;
                vd[c4i + i] = vu;
            }
        }
        __syncthreads();

        float s[4][4];
#pragma unroll
        for (int j = 0; j < 4; j++)
#pragma unroll
            for (int c = 0; c < 4; c++) s[j][c] = 0.f;
#pragma unroll
        for (int d = 0; d < 10; d++) {
            uint32_t kb[4], kb2[4];
            uint32_t a0 = ksB + (krow * QPAD) * 2 + koff + 32 * d;
            asm volatile(
                "ldmatrix.sync.aligned.m8n8.x4.shared.b16 {%0,%1,%2,%3}, [%4];"
                : "=r"(kb[0]), "=r"(kb[1]), "=r"(kb[2]), "=r"(kb[3]) : "r"(a0));
            uint32_t a1 = a0 + 16 * QPAD * 2;
            asm volatile(
                "ldmatrix.sync.aligned.m8n8.x4.shared.b16 {%0,%1,%2,%3}, [%4];"
                : "=r"(kb2[0]), "=r"(kb2[1]), "=r"(kb2[2]), "=r"(kb2[3]) : "r"(a1));
            MMA16816(s[0], qf[d], kb[0],  kb[1]);
            MMA16816(s[1], qf[d], kb[2],  kb[3]);
            MMA16816(s[2], qf[d], kb2[0], kb2[1]);
            MMA16816(s[3], qf[d], kb2[2], kb2[3]);
        }

        int kbase = kt * 32;
        float tm0 = -1e30f, tm1 = -1e30f;
#pragma unroll
        for (int j = 0; j < 4; j++) {
            int k0 = kbase + 8*j + 2*t4;
            bool v0 = k0 < Sk, v1 = (k0 + 1) < Sk;
            s[j][0] = v0 ? s[j][0] * scale : -1e30f;
            s[j][1] = v1 ? s[j][1] * scale : -1e30f;
            s[j][2] = v0 ? s[j][2] * scale : -1e30f;
            s[j][3] = v1 ? s[j][3] * scale : -1e30f;
            tm0 = fmaxf(tm0, fmaxf(s[j][0], s[j][1]));
            tm1 = fmaxf(tm1, fmaxf(s[j][2], s[j][3]));
        }
        tm0 = fmaxf(tm0, __shfl_xor_sync(0xffffffffu, tm0, 1));
        tm0 = fmaxf(tm0, __shfl_xor_sync(0xffffffffu, tm0, 2));
        tm1 = fmaxf(tm1, __shfl_xor_sync(0xffffffffu, tm1, 1));
        tm1 = fmaxf(tm1, __shfl_xor_sync(0xffffffffu, tm1, 2));

        if (tm0 > m0 || tm1 > m1) {
            float nm0 = fmaxf(m0, tm0), nm1 = fmaxf(m1, tm1);
            float a0 = __expf(m0 - nm0), a1 = __expf(m1 - nm1);
            m0 = nm0; m1 = nm1;
            l0 *= a0; l1 *= a1;
#pragma unroll
            for (int w = 0; w < 20; w++) {
                o[w][0] *= a0; o[w][1] *= a0;
                o[w][2] *= a1; o[w][3] *= a1;
            }
        }

        uint32_t plo[4], phi[4];
#pragma unroll
        for (int j = 0; j < 4; j++) {
            float e0 = __expf(s[j][0] - m0), e1 = __expf(s[j][1] - m0);
            float e2 = __expf(s[j][2] - m1), e3 = __expf(s[j][3] - m1);
            l0 += e0 + e1; l1 += e2 + e3;
            __half2 hl = __floats2half2_rn(e0, e1);
            __half2 hh = __floats2half2_rn(e2, e3);
            plo[j] = *reinterpret_cast<uint32_t*>(&hl);
            phi[j] = *reinterpret_cast<uint32_t*>(&hh);
        }

#pragma unroll
        for (int kk = 0; kk < 2; kk++) {
            uint32_t pa[4] = {plo[2*kk], phi[2*kk], plo[2*kk+1], phi[2*kk+1]};
#pragma unroll
            for (int w2 = 0; w2 < 10; w2++) {
                uint32_t vb[4];
                uint32_t a = vsB + ((16*kk + vkey) * QPAD + (2*w2 + vwin) * 8) * 2;
                asm volatile(
                    "ldmatrix.sync.aligned.m8n8.x4.trans.shared.b16 {%0,%1,%2,%3}, [%4];"
                    : "=r"(vb[0]), "=r"(vb[1]), "=r"(vb[2]), "=r"(vb[3]) : "r"(a));
                MMA16816(o[2*w2],     pa, vb[0], vb[1]);
                MMA16816(o[2*w2 + 1], pa, vb[2], vb[3]);
            }
        }
        __syncthreads();
    }

    l0 += __shfl_xor_sync(0xffffffffu, l0, 1);
    l0 += __shfl_xor_sync(0xffffffffu, l0, 2);
    l1 += __shfl_xor_sync(0xffffffffu, l1, 1);
    l1 += __shfl_xor_sync(0xffffffffu, l1, 2);
    float inv0 = 1.f / l0, inv1 = 1.f / l1;

    int row0 = q0 + 16*wp + g;
    int row1 = row0 + 8;
    __half* ob = O + (size_t)batch * o_bs + head * DH + 2 * t4;
#pragma unroll
    for (int w = 0; w < 20; w++) {
        if (row0 < Sq) {
            __half2 hv = __floats2half2_rn(o[w][0] * inv0, o[w][1] * inv0);
            *(__half2*)(ob + (size_t)row0 * ldo + 8 * w) = hv;
        }
        if (row1 < Sq) {
            __half2 hv = __floats2half2_rn(o[w][2] * inv1, o[w][3] * inv1);
            *(__half2*)(ob + (size_t)row1 * ldo + 8 * w) = hv;
        }
    }
}

// ---------------------------------------------------------------------------
// Host launcher
// ---------------------------------------------------------------------------
template<int MODE, int PERM>
static void launch_gemm(const __half* A, const uint32_t* B2, void* C,
                        const float* bias, const float* res,
                        int M, int N, int K)
{
    static bool attr_set = false;
    if (!attr_set) {
        cudaFuncSetAttribute(gemm_f16<MODE, PERM>,
            cudaFuncAttributeMaxDynamicSharedMemorySize, GEMM_SMEM);
        attr_set = true;
    }
    int nm = (M + 127) / 128, nn = N / 128;
    gemm_f16<MODE, PERM><<<nm * nn, 256, GEMM_SMEM>>>(A, B2, C, bias, res, M, N, K);
}

extern "C" void kernel_launch(void* const* d_in, const int* in_sizes, int n_in,
                              void* d_out, int out_size)
{
    const float* hid  = (const float*)d_in[0];
    const float* enc  = (const float*)d_in[1];
    const float* n1w  = (const float*)d_in[2];
    const float* n1b  = (const float*)d_in[3];
    const float* a1wq = (const float*)d_in[4];
    const float* a1wk = (const float*)d_in[5];
    const float* a1wv = (const float*)d_in[6];
    const float* a1wo = (const float*)d_in[7];
    const float* a1bo = (const float*)d_in[8];
    const float* n2w  = (const float*)d_in[9];
    const float* n2b  = (const float*)d_in[10];
    const float* a2wq = (const float*)d_in[11];
    const float* a2wk = (const float*)d_in[12];
    const float* a2wv = (const float*)d_in[13];
    const float* a2wo = (const float*)d_in[14];
    const float* a2bo = (const float*)d_in[15];
    const float* n3w  = (const float*)d_in[16];
    const float* n3b  = (const float*)d_in[17];
    const float* ffw1 = (const float*)d_in[18];
    const float* ffb1 = (const float*)d_in[19];
    const float* ffw2 = (const float*)d_in[20];
    const float* ffb2 = (const float*)d_in[21];
    const float* ntw  = (const float*)d_in[22];
    const float* ntb  = (const float*)d_in[23];
    const float* atwq = (const float*)d_in[24];
    const float* atwk = (const float*)d_in[25];
    const float* atwv = (const float*)d_in[26];
    const float* atwo = (const float*)d_in[27];
    const float* atbo = (const float*)d_in[28];

    float* out = (float*)d_out;

    __half *nh, *ao, *qkv, *gg, *kvh, *ench;
    float *biasi;
    uint32_t* wt;
    cudaGetSymbolAddress((void**)&nh,   g_nh_h);
    cudaGetSymbolAddress((void**)&ao,   g_ao_h);
    cudaGetSymbolAddress((void**)&qkv,  g_qkv_h);
    cudaGetSymbolAddress((void**)&gg,   g_gg_h);
    cudaGetSymbolAddress((void**)&kvh,  g_kv_h);
    cudaGetSymbolAddress((void**)&ench, g_enc_h);
    cudaGetSymbolAddress((void**)&biasi,g_biasi);
    cudaGetSymbolAddress((void**)&wt,   g_wt);

    const float scale = 0.07905694150420949f;   // 160^-0.5

    // ---- prologue: 2 launches ----
    {
        PackParams pp;
        pp.s[0] = a1wq; pp.s[1] = a1wk; pp.s[2] = a1wv; pp.s[3] = a1wo;
        pp.s[4] = a2wq; pp.s[5] = a2wk; pp.s[6] = a2wv; pp.s[7] = a2wo;
        pp.s[8] = ffw2; pp.s[9] = atwq; pp.s[10] = atwk; pp.s[11] = atwv;
        pp.s[12] = atwo; pp.enc = enc;
        pack_all<<<(3349504 + 255) / 256, 256>>>(pp, wt, ench);
        pack_ffn1<<<6400 + 20, 256>>>(ffw1, wt + OFF_FFW1, ffb1, biasi);
    }

    const int QKV = 3 * DIMC;     // 3840
    const int KV2 = 2 * DIMC;     // 2560

    // ---- attn1: sparse-causal self-attention ----
    ln_kernel<<<NROWS, 128>>>(hid, n1w, n1b, nh, 0);
    launch_gemm<1,0>(nh, wt + OFF_W1QKV, qkv, nullptr, nullptr, NROWS, QKV, DIMC);
    attn_tc<<<dim3(4, HEADS, BF), 128>>>(
        qkv, qkv + DIMC, qkv + 2*DIMC, ao,
        TOK, 2*TOK, (long)TOK*QKV, 0, (long)TOK*DIMC,
        QKV, QKV, DIMC, 1, scale);
    launch_gemm<0,0>(ao, wt + OFF_A1WO, out, a1bo, hid, NROWS, DIMC, DIMC);

    // ---- attn2: cross-attention ----
    ln_kernel<<<NROWS, 128>>>(out, n2w, n2b, nh, 0);
    launch_gemm<1,0>(nh,   wt + OFF_A2WQ, qkv, nullptr, nullptr, NROWS,   DIMC, DIMC);
    launch_gemm<1,0>(ench, wt + OFF_W2KV, kvh, nullptr, nullptr, ENCROWS, KV2,  CROSS);
    attn_tc<<<dim3(4, HEADS, BF), 128>>>(
        qkv, kvh, kvh + DIMC, ao,
        TOK, ESEQ, (long)TOK*DIMC, (long)ESEQ*KV2, (long)TOK*DIMC,
        DIMC, KV2, DIMC, 0, scale);
    launch_gemm<0,0>(ao, wt + OFF_A2WO, out, a2bo, out, NROWS, DIMC, DIMC);

    // ---- geglu FFN (geglu fused into ffn1 epilogue) ----
    ln_kernel<<<NROWS, 128>>>(out, n3w, n3b, nh, 0);
    launch_gemm<2,0>(nh, wt + OFF_FFW1, gg, biasi, nullptr, NROWS, FF_N, DIMC);
    launch_gemm<0,0>(gg, wt + OFF_FFW2, out, ffb2, out, NROWS, DIMC, FF_I);

    // ---- temporal self-attention (transposes fused via row permutation) ----
    ln_kernel<<<NROWS, 128>>>(out, ntw, ntb, nh, 1);
    launch_gemm<1,0>(nh, wt + OFF_WTQKV, qkv, nullptr, nullptr, NROWS, QKV, DIMC);
    attn_tc<<<dim3(1, HEADS, 2*TOK), 128>>>(
        qkv, qkv + DIMC, qkv + 2*DIMC, ao,
        FRAMES, FRAMES, (long)FRAMES*QKV, (long)FRAMES*QKV, (long)FRAMES*DIMC,
        QKV, QKV, DIMC, 0, scale);
    launch_gemm<0,1>(ao, wt + OFF_ATWO, out, atbo, out, NROWS, DIMC, DIMC);
}